// round 12
// baseline (speedup 1.0000x reference)
#include <cuda_runtime.h>
#include <math.h>
#include <stdint.h>

#define NN 100000
#define EE 1600000
#define DIN 24
#define HH 128
#define DOUT 12
#define HEADS 4
#define NB 391   // ceil(NN/256)

// ----------------------------------------------------------------------------
// Scratch (device globals; no dynamic allocation allowed)
// ----------------------------------------------------------------------------
__device__ float g_h1[NN * HH];      // h3 = x2@W3
__device__ float g_agg[NN * HH];     // raw pre-BN activations per layer
__device__ float g_x1[NN * HH];      // x1 (side-written by Wg GEMM)
__device__ float g_xin[NN * HH];     // x_in_proj
__device__ float g_hg[NN * HH];      // hg
__device__ float g_xa[NN * DIN];     // 24-dim aggregated x
__device__ float g_h4[NN * DOUT];
__device__ float g_gc[NN * DOUT];    // gate contribution per node
__device__ float g_as[NN * HEADS];
__device__ float g_ad[NN * HEADS];
__device__ float g_deg[NN];
__device__ float g_dinv[NN];
__device__ int   g_cnt[NN];
__device__ int   g_cur[NN];
__device__ int   g_rowptr[NN + 1];
__device__ int2  g_epack[EE];
__device__ int   g_part[512];
__device__ float g_bnpart[3][64][256];  // per-layer bucketed BN partials
__device__ float g_wtg[HH * HH];     // Wg^T  [128,128] K-major
__device__ float g_wt3[HH * HH];     // W3^T
__device__ float g_wtcomb[80 * HH];  // [Gw1^T ; W4^T ; pad]

__device__ __forceinline__ float lrelu(float v) { return v > 0.f ? v : 0.2f * v; }
__device__ __forceinline__ uint32_t to_tf32(float f) {
    uint32_t t;
    asm("cvt.rna.tf32.f32 %0, %1;" : "=r"(t) : "f"(f));
    return t;
}

// ----------------------------------------------------------------------------
// Graph preprocessing
// ----------------------------------------------------------------------------
__global__ void __launch_bounds__(256) init_kernel() {
    int i = blockIdx.x * blockDim.x + threadIdx.x;
    if (i < NN) { g_deg[i] = 1.0f; g_cnt[i] = 0; g_cur[i] = 0; }
    if (i < 3 * 64 * 256) ((float*)g_bnpart)[i] = 0.f;
}

__global__ void __launch_bounds__(256) count_kernel(const int* __restrict__ dst,
                                                    const float* __restrict__ w) {
    int e = blockIdx.x * blockDim.x + threadIdx.x;
    if (e < EE) {
        int d = dst[e];
        atomicAdd(&g_deg[d], w[e]);
        atomicAdd(&g_cnt[d], 1);
    }
}

__global__ void __launch_bounds__(256) part_kernel() {
    __shared__ int sw[8];
    int i = blockIdx.x * 256 + threadIdx.x;
    if (i < NN) g_dinv[i] = rsqrtf(g_deg[i]);
    int v = (i < NN) ? g_cnt[i] : 0;
#pragma unroll
    for (int off = 16; off; off >>= 1) v += __shfl_down_sync(0xffffffffu, v, off);
    if ((threadIdx.x & 31) == 0) sw[threadIdx.x >> 5] = v;
    __syncthreads();
    if (threadIdx.x == 0) {
        int s = 0;
#pragma unroll
        for (int k = 0; k < 8; k++) s += sw[k];
        g_part[blockIdx.x] = s;
    }
}

__global__ void __launch_bounds__(256) writerow_kernel() {
    __shared__ int sp[256];
    __shared__ int swr[8];
    __shared__ int soff;
    const int t = threadIdx.x;
    const int i = blockIdx.x * 256 + t;
    int pre = 0;
    for (int b = t; b < blockIdx.x; b += 256) pre += g_part[b];
#pragma unroll
    for (int off = 16; off; off >>= 1) pre += __shfl_down_sync(0xffffffffu, pre, off);
    if ((t & 31) == 0) swr[t >> 5] = pre;
    __syncthreads();
    if (t == 0) {
        int s = 0;
#pragma unroll
        for (int k = 0; k < 8; k++) s += swr[k];
        soff = s;
    }
    int v = (i < NN) ? g_cnt[i] : 0;
    sp[t] = v;
    __syncthreads();
    for (int off = 1; off < 256; off <<= 1) {
        int a = (t >= off) ? sp[t - off] : 0;
        __syncthreads();
        sp[t] += a;
        __syncthreads();
    }
    if (i < NN) g_rowptr[i] = sp[t] - v + soff;
    if (i == 0) g_rowptr[NN] = EE;
}

__global__ void __launch_bounds__(256) fill_kernel(const int* __restrict__ src,
                                                   const int* __restrict__ dst,
                                                   const float* __restrict__ w) {
    int e = blockIdx.x * blockDim.x + threadIdx.x;
    if (e < EE) {
        int d = dst[e];
        int s = src[e];
        int pos = g_rowptr[d] + atomicAdd(&g_cur[d], 1);
        float coef = w[e] * __ldg(&g_dinv[s]) * __ldg(&g_dinv[d]);
        g_epack[pos] = make_int2(s, __float_as_int(coef));
    }
}

__global__ void __launch_bounds__(256) prep_weights_kernel(const float* __restrict__ Wg,
                                                           const float* __restrict__ W3,
                                                           const float* __restrict__ Gw1,
                                                           const float* __restrict__ W4) {
    int idx = blockIdx.x * 256 + threadIdx.x;
    if (idx < 16384) {
        int k = idx >> 7, c = idx & 127;
        g_wtg[c * 128 + k] = __ldg(&Wg[idx]);
    } else if (idx < 32768) {
        int j = idx - 16384;
        int k = j >> 7, c = j & 127;
        g_wt3[c * 128 + k] = __ldg(&W3[j]);
    } else if (idx < 43008) {
        int j = idx - 32768;
        int r = j >> 7, k = j & 127;
        float v = 0.f;
        if (r < 64) v = __ldg(&Gw1[k * 64 + r]);
        else if (r < 76) v = __ldg(&W4[k * DOUT + (r - 64)]);
        g_wtcomb[j] = v;
    }
}

// ----------------------------------------------------------------------------
// 24-channel GCN aggregation, fully predicated 8-wide
// ----------------------------------------------------------------------------
__global__ void __launch_bounds__(128) agg24_kernel(const float* __restrict__ x,
                                                    float* __restrict__ xa) {
    const int warp = threadIdx.x >> 5;
    const int lane = threadIdx.x & 31;
    const int n = blockIdx.x * 4 + warp;
    const float dn = g_dinv[n];
    const int s0 = g_rowptr[n], s1 = g_rowptr[n + 1];
    float acc = (lane < DIN) ? x[n * DIN + lane] * dn * dn : 0.f;
    for (int j = s0; j < s1; j += 8) {
        int2 e[8];
#pragma unroll
        for (int q = 0; q < 8; q++) {
            int idx = j + q;
            e[q] = (idx < s1) ? __ldg(&g_epack[idx]) : make_int2(n, 0);
        }
        float v[8];
#pragma unroll
        for (int q = 0; q < 8; q++)
            v[q] = (lane < DIN) ? __ldg(&x[e[q].x * DIN + lane]) : 0.f;
#pragma unroll
        for (int q = 0; q < 8; q++) acc += __int_as_float(e[q].y) * v[q];
    }
    if (lane < DIN) xa[n * DIN + lane] = acc;
}

// ----------------------------------------------------------------------------
// TF32 mma.sync GEMM. In-kernel BN finalize from bucketed partials.
// ----------------------------------------------------------------------------
template<int NC, bool ADD, bool WRITEX, bool ATT, bool COMBO>
__global__ void __launch_bounds__(256) mma_gemm(const float* __restrict__ Araw,
                                                const float* __restrict__ addp,
                                                float* __restrict__ xout,
                                                const float* __restrict__ Bt,
                                                const float* __restrict__ bias,
                                                float* __restrict__ out,
                                                float* __restrict__ out2,
                                                const float* __restrict__ att_s,
                                                const float* __restrict__ att_d,
                                                const float* __restrict__ bnp,
                                                const float* __restrict__ bng,
                                                const float* __restrict__ bnbe,
                                                const float* __restrict__ Gw2,
                                                const float* __restrict__ Gb2,
                                                const float* __restrict__ Ws,
                                                const float* __restrict__ bs,
                                                const float* __restrict__ xfull) {
    extern __shared__ float smf[];
    float* sSC = smf;
    float* sSH = smf + 128;
    uint32_t* sW = (uint32_t*)(smf + 256);   // [NC][132]
    float* sG = smf + 256 + NC * 132;        // [64*12] (COMBO only)
    const int tid = threadIdx.x, wid = tid >> 5, lane = tid & 31;
    const int n0 = blockIdx.x * 128;

    if (tid < 128) {
        float s = 0.f, s2 = 0.f;
#pragma unroll 8
        for (int b = 0; b < 64; b++) {
            s += __ldg(&bnp[b * 256 + tid]);
            s2 += __ldg(&bnp[b * 256 + tid + 128]);
        }
        float mean = s * (1.0f / NN);
        float var = fmaxf(s2 * (1.0f / NN) - mean * mean, 0.f);
        float sc = rsqrtf(var + 1e-5f) * __ldg(&bng[tid]);
        sSC[tid] = sc;
        sSH[tid] = __ldg(&bnbe[tid]) - mean * sc;
    }
    for (int i = tid; i < NC * 128; i += 256) {
        int c = i >> 7, k = i & 127;
        sW[c * 132 + k] = to_tf32(__ldg(&Bt[i]));
    }
    if (COMBO) {
        for (int i = tid; i < 64 * DOUT; i += 256) sG[i] = __ldg(&Gw2[i]);
    }
    __syncthreads();

    constexpr int NCH = NC / 8;
    float acc[NCH][4];
#pragma unroll
    for (int i = 0; i < NCH; i++) {
        acc[i][0] = 0.f; acc[i][1] = 0.f; acc[i][2] = 0.f; acc[i][3] = 0.f;
    }

    const int r0 = n0 + wid * 16 + (lane >> 2);
    const int r1 = r0 + 8;
    const bool v0 = r0 < NN, v1 = r1 < NN;
    const int kq = lane & 3;
    const int nq = lane >> 2;

#pragma unroll 4
    for (int k8 = 0; k8 < 128; k8 += 8) {
        int ka = k8 + kq, kb = k8 + kq + 4;
        float f0 = 0.f, f1 = 0.f, f2 = 0.f, f3 = 0.f;
        if (v0) {
            f0 = fmaxf(__ldg(&Araw[(size_t)r0 * 128 + ka]) * sSC[ka] + sSH[ka], 0.f);
            f2 = fmaxf(__ldg(&Araw[(size_t)r0 * 128 + kb]) * sSC[kb] + sSH[kb], 0.f);
            if (ADD) {
                f0 += __ldg(&addp[(size_t)r0 * 128 + ka]);
                f2 += __ldg(&addp[(size_t)r0 * 128 + kb]);
            }
            if (WRITEX) {
                xout[(size_t)r0 * 128 + ka] = f0;
                xout[(size_t)r0 * 128 + kb] = f2;
            }
        }
        if (v1) {
            f1 = fmaxf(__ldg(&Araw[(size_t)r1 * 128 + ka]) * sSC[ka] + sSH[ka], 0.f);
            f3 = fmaxf(__ldg(&Araw[(size_t)r1 * 128 + kb]) * sSC[kb] + sSH[kb], 0.f);
            if (ADD) {
                f1 += __ldg(&addp[(size_t)r1 * 128 + ka]);
                f3 += __ldg(&addp[(size_t)r1 * 128 + kb]);
            }
            if (WRITEX) {
                xout[(size_t)r1 * 128 + ka] = f1;
                xout[(size_t)r1 * 128 + kb] = f3;
            }
        }
        uint32_t a0 = to_tf32(f0), a1 = to_tf32(f1), a2 = to_tf32(f2), a3 = to_tf32(f3);
#pragma unroll
        for (int nc = 0; nc < NCH; nc++) {
            uint32_t b0 = sW[(nc * 8 + nq) * 132 + ka];
            uint32_t b1 = sW[(nc * 8 + nq) * 132 + kb];
            asm volatile(
                "mma.sync.aligned.m16n8k8.row.col.f32.tf32.tf32.f32 "
                "{%0,%1,%2,%3}, {%4,%5,%6,%7}, {%8,%9}, {%0,%1,%2,%3};"
                : "+f"(acc[nc][0]), "+f"(acc[nc][1]), "+f"(acc[nc][2]), "+f"(acc[nc][3])
                : "r"(a0), "r"(a1), "r"(a2), "r"(a3), "r"(b0), "r"(b1));
        }
    }

    const int colb = 2 * kq;
    if (COMBO) {
        float z0[DOUT], z1[DOUT];
#pragma unroll
        for (int c = 0; c < DOUT; c++) { z0[c] = 0.f; z1[c] = 0.f; }
#pragma unroll
        for (int nc = 0; nc < NCH; nc++) {
            int col = nc * 8 + colb;
            if (col < 64) {
                float bx = __ldg(&bias[col]), by = __ldg(&bias[col + 1]);
                float t0a = fmaxf(acc[nc][0] + bx, 0.f), t0b = fmaxf(acc[nc][1] + by, 0.f);
                float t1a = fmaxf(acc[nc][2] + bx, 0.f), t1b = fmaxf(acc[nc][3] + by, 0.f);
#pragma unroll
                for (int c = 0; c < DOUT; c++) {
                    float w0 = sG[col * DOUT + c], w1 = sG[(col + 1) * DOUT + c];
                    z0[c] += t0a * w0 + t0b * w1;
                    z1[c] += t1a * w0 + t1b * w1;
                }
            } else if (col < 76) {
                int c2 = col - 64;
                if (v0) *(float2*)&out2[(size_t)r0 * DOUT + c2] =
                            make_float2(acc[nc][0], acc[nc][1]);
                if (v1) *(float2*)&out2[(size_t)r1 * DOUT + c2] =
                            make_float2(acc[nc][2], acc[nc][3]);
            }
        }
#pragma unroll
        for (int c = 0; c < DOUT; c++) {
            z0[c] += __shfl_xor_sync(0xffffffffu, z0[c], 1);
            z0[c] += __shfl_xor_sync(0xffffffffu, z0[c], 2);
            z1[c] += __shfl_xor_sync(0xffffffffu, z1[c], 1);
            z1[c] += __shfl_xor_sync(0xffffffffu, z1[c], 2);
        }
        if (kq == 0) {
            if (v0) {
                float status = __ldg(&xfull[(size_t)r0 * DIN + 12]);
                float flag = status < 0.5f ? 2.5f : 0.f;
#pragma unroll
                for (int c = 0; c < DOUT; c++) {
                    float gate = 1.f / (1.f + expf(-(z0[c] + __ldg(&Gb2[c]))));
                    float sig = (1.f - status) * __ldg(&Ws[c]) + __ldg(&bs[c]);
                    out[(size_t)r0 * DOUT + c] = flag * gate * sig;
                }
            }
            if (v1) {
                float status = __ldg(&xfull[(size_t)r1 * DIN + 12]);
                float flag = status < 0.5f ? 2.5f : 0.f;
#pragma unroll
                for (int c = 0; c < DOUT; c++) {
                    float gate = 1.f / (1.f + expf(-(z1[c] + __ldg(&Gb2[c]))));
                    float sig = (1.f - status) * __ldg(&Ws[c]) + __ldg(&bs[c]);
                    out[(size_t)r1 * DOUT + c] = flag * gate * sig;
                }
            }
        }
    } else {
#pragma unroll
        for (int nc = 0; nc < NCH; nc++) {
            int col = nc * 8 + colb;
            if (v0) *(float2*)&out[(size_t)r0 * NC + col] =
                        make_float2(acc[nc][0], acc[nc][1]);
            if (v1) *(float2*)&out[(size_t)r1 * NC + col] =
                        make_float2(acc[nc][2], acc[nc][3]);
        }
    }

    if (ATT) {
        float as0[4] = {}, ad0[4] = {}, as1[4] = {}, ad1[4] = {};
#pragma unroll
        for (int nc = 0; nc < NCH; nc++) {
            int col = nc * 8 + colb;
            float sx = __ldg(&att_s[col]), sy = __ldg(&att_s[col + 1]);
            float dx = __ldg(&att_d[col]), dy = __ldg(&att_d[col + 1]);
            int h = nc >> 2;
            as0[h] += acc[nc][0] * sx + acc[nc][1] * sy;
            ad0[h] += acc[nc][0] * dx + acc[nc][1] * dy;
            as1[h] += acc[nc][2] * sx + acc[nc][3] * sy;
            ad1[h] += acc[nc][2] * dx + acc[nc][3] * dy;
        }
#pragma unroll
        for (int h = 0; h < 4; h++) {
#pragma unroll
            for (int off = 1; off <= 2; off <<= 1) {
                as0[h] += __shfl_xor_sync(0xffffffffu, as0[h], off);
                ad0[h] += __shfl_xor_sync(0xffffffffu, ad0[h], off);
                as1[h] += __shfl_xor_sync(0xffffffffu, as1[h], off);
                ad1[h] += __shfl_xor_sync(0xffffffffu, ad1[h], off);
            }
        }
        if (kq == 0) {
#pragma unroll
            for (int h = 0; h < 4; h++) {
                if (v0) { g_as[r0 * 4 + h] = as0[h]; g_ad[r0 * 4 + h] = ad0[h]; }
                if (v1) { g_as[r1 * 4 + h] = as1[h]; g_ad[r1 * 4 + h] = ad1[h]; }
            }
        }
    }
}

// ----------------------------------------------------------------------------
// Fused input GEMM: agg1 = xa@W1 + b1, xin = x@Wi + bi, + fused BN1 partials
// ----------------------------------------------------------------------------
__global__ void __launch_bounds__(128) gemm_in_kernel(
        const float* __restrict__ XA, const float* __restrict__ X,
        const float* __restrict__ W1, const float* __restrict__ b1,
        const float* __restrict__ Wi, const float* __restrict__ bi,
        float* __restrict__ h1, float* __restrict__ xin) {
    __shared__ float sS[4][128], sQ[4][128];
    const int tid = threadIdx.x;
    const int cg = tid & 31;
    const int rg = tid >> 5;
    const int n0 = blockIdx.x * 16 + rg * 4;
    float a1[4][4] = {}; float ai[4][4] = {};
    const float4* W1v = (const float4*)W1;
    const float4* Wiv = (const float4*)Wi;
#pragma unroll
    for (int k = 0; k < DIN; k++) {
        float4 w1 = __ldg(&W1v[k * 32 + cg]);
        float4 wi = __ldg(&Wiv[k * 32 + cg]);
#pragma unroll
        for (int r = 0; r < 4; r++) {
            float xav = __ldg(&XA[(n0 + r) * DIN + k]);
            float xv  = __ldg(&X[(n0 + r) * DIN + k]);
            a1[r][0] += xav * w1.x; a1[r][1] += xav * w1.y; a1[r][2] += xav * w1.z; a1[r][3] += xav * w1.w;
            ai[r][0] += xv * wi.x;  ai[r][1] += xv * wi.y;  ai[r][2] += xv * wi.z;  ai[r][3] += xv * wi.w;
        }
    }
    const int c0 = cg * 4;
    float4 b1v = __ldg(&((const float4*)b1)[cg]);
    float4 biv = __ldg(&((const float4*)bi)[cg]);
    float s4[4] = {}, q4[4] = {};
#pragma unroll
    for (int r = 0; r < 4; r++) {
        float4 v1, vi;
        v1.x = a1[r][0] + b1v.x; v1.y = a1[r][1] + b1v.y;
        v1.z = a1[r][2] + b1v.z; v1.w = a1[r][3] + b1v.w;
        vi.x = ai[r][0] + biv.x; vi.y = ai[r][1] + biv.y;
        vi.z = ai[r][2] + biv.z; vi.w = ai[r][3] + biv.w;
        s4[0] += v1.x; q4[0] += v1.x * v1.x;
        s4[1] += v1.y; q4[1] += v1.y * v1.y;
        s4[2] += v1.z; q4[2] += v1.z * v1.z;
        s4[3] += v1.w; q4[3] += v1.w * v1.w;
        *(float4*)&h1[(n0 + r) * HH + c0] = v1;
        *(float4*)&xin[(n0 + r) * HH + c0] = vi;
    }
#pragma unroll
    for (int i = 0; i < 4; i++) { sS[rg][c0 + i] = s4[i]; sQ[rg][c0 + i] = q4[i]; }
    __syncthreads();
    const int b = blockIdx.x & 63;
    float ts = sS[0][tid] + sS[1][tid] + sS[2][tid] + sS[3][tid];
    float tq = sQ[0][tid] + sQ[1][tid] + sQ[2][tid] + sQ[3][tid];
    atomicAdd(&g_bnpart[0][b][tid], ts);
    atomicAdd(&g_bnpart[0][b][tid + 128], tq);
}

// ----------------------------------------------------------------------------
// GCN aggregation (128 ch, warp/node, predicated 8-wide) + BN3 partials
// ----------------------------------------------------------------------------
__global__ void __launch_bounds__(128) gcn_agg128(const float* __restrict__ in,
                                                  const float* __restrict__ bias,
                                                  float* __restrict__ out) {
    __shared__ float sS[4][128], sQ[4][128];
    const int warp = threadIdx.x >> 5;
    const int lane = threadIdx.x & 31;
    const int n = blockIdx.x * 4 + warp;
    const float dn = g_dinv[n];
    const int s0 = g_rowptr[n], s1 = g_rowptr[n + 1];
    const float4* in4 = (const float4*)in;
    float4 acc = __ldg(&in4[n * 32 + lane]);
    float dn2 = dn * dn;
    acc.x *= dn2; acc.y *= dn2; acc.z *= dn2; acc.w *= dn2;
    for (int j = s0; j < s1; j += 8) {
        int2 e[8];
#pragma unroll
        for (int q = 0; q < 8; q++) {
            int idx = j + q;
            e[q] = (idx < s1) ? __ldg(&g_epack[idx]) : make_int2(n, 0);
        }
        float4 v[8];
#pragma unroll
        for (int q = 0; q < 8; q++) v[q] = __ldg(&in4[e[q].x * 32 + lane]);
#pragma unroll
        for (int q = 0; q < 8; q++) {
            float c = __int_as_float(e[q].y);
            acc.x += c * v[q].x; acc.y += c * v[q].y;
            acc.z += c * v[q].z; acc.w += c * v[q].w;
        }
    }
    float4 bv = __ldg(&((const float4*)bias)[lane]);
    acc.x += bv.x; acc.y += bv.y; acc.z += bv.z; acc.w += bv.w;
    ((float4*)out)[n * 32 + lane] = acc;
    sS[warp][lane * 4 + 0] = acc.x; sQ[warp][lane * 4 + 0] = acc.x * acc.x;
    sS[warp][lane * 4 + 1] = acc.y; sQ[warp][lane * 4 + 1] = acc.y * acc.y;
    sS[warp][lane * 4 + 2] = acc.z; sQ[warp][lane * 4 + 2] = acc.z * acc.z;
    sS[warp][lane * 4 + 3] = acc.w; sQ[warp][lane * 4 + 3] = acc.w * acc.w;
    __syncthreads();
    const int tid = threadIdx.x;
    const int b = blockIdx.x & 63;
    float ts = sS[0][tid] + sS[1][tid] + sS[2][tid] + sS[3][tid];
    float tq = sQ[0][tid] + sQ[1][tid] + sQ[2][tid] + sQ[3][tid];
    atomicAdd(&g_bnpart[2][b][tid], ts);
    atomicAdd(&g_bnpart[2][b][tid + 128], tq);
}

// ----------------------------------------------------------------------------
// GAT aggregation: single pass, predicated 8-wide + BN2 partials
// ----------------------------------------------------------------------------
__global__ void __launch_bounds__(256) gat_agg_kernel(const float* __restrict__ hg,
                                                      const float* __restrict__ bg,
                                                      float* __restrict__ out) {
    __shared__ float sS[8][128], sQ[8][128];
    const int w = threadIdx.x >> 5;
    const int lane = threadIdx.x & 31;
    const int n = blockIdx.x * 8 + w;
    const int s0 = g_rowptr[n], s1 = g_rowptr[n + 1];
    const int h = lane >> 3;
    const int eq = lane & 7;
    const float4* ad4 = (const float4*)g_ad;
    const float4* as4 = (const float4*)g_as;

    float4 adv = __ldg(&ad4[n]);
    float4 asv = __ldg(&as4[n]);
    float adh = h < 2 ? (h == 0 ? adv.x : adv.y) : (h == 2 ? adv.z : adv.w);
    float ash = h < 2 ? (h == 0 ? asv.x : asv.y) : (h == 2 ? asv.z : asv.w);
    float xs = expf(lrelu(ash + adh));

    const float4* hg4 = (const float4*)hg;
    float4 acc = make_float4(0.f, 0.f, 0.f, 0.f);
    float tsum = 0.f;

    for (int j = s0; j < s1; j += 8) {
        int2 e[8];
#pragma unroll
        for (int q = 0; q < 8; q++) {
            int idx = j + q;
            e[q] = (idx < s1) ? __ldg(&g_epack[idx]) : make_int2(n, 0);
        }
        float myx = (j + eq < s1)
                        ? expf(lrelu(__ldg(&g_as[e[eq].x * 4 + h]) + adh)) : 0.f;
        tsum += myx;
        float4 v[8];
#pragma unroll
        for (int q = 0; q < 8; q++) v[q] = __ldg(&hg4[e[q].x * 32 + lane]);
#pragma unroll
        for (int q = 0; q < 8; q++) {
            float a = __shfl_sync(0xffffffffu, myx, h * 8 + q);
            acc.x += a * v[q].x; acc.y += a * v[q].y;
            acc.z += a * v[q].z; acc.w += a * v[q].w;
        }
    }
#pragma unroll
    for (int off = 1; off <= 4; off <<= 1)
        tsum += __shfl_xor_sync(0xffffffffu, tsum, off);
    float inv = 1.f / (tsum + xs);

    float4 self = __ldg(&hg4[n * 32 + lane]);
    float4 bv = __ldg(&((const float4*)bg)[lane]);
    float4 o;
    o.x = (acc.x + xs * self.x) * inv + bv.x;
    o.y = (acc.y + xs * self.y) * inv + bv.y;
    o.z = (acc.z + xs * self.z) * inv + bv.z;
    o.w = (acc.w + xs * self.w) * inv + bv.w;
    ((float4*)out)[n * 32 + lane] = o;
    sS[w][lane * 4 + 0] = o.x; sQ[w][lane * 4 + 0] = o.x * o.x;
    sS[w][lane * 4 + 1] = o.y; sQ[w][lane * 4 + 1] = o.y * o.y;
    sS[w][lane * 4 + 2] = o.z; sQ[w][lane * 4 + 2] = o.z * o.z;
    sS[w][lane * 4 + 3] = o.w; sQ[w][lane * 4 + 3] = o.w * o.w;
    __syncthreads();
    const int tid = threadIdx.x;
    if (tid < 128) {
        const int b = blockIdx.x & 63;
        float ts = 0.f, tq = 0.f;
#pragma unroll
        for (int ww = 0; ww < 8; ww++) { ts += sS[ww][tid]; tq += sQ[ww][tid]; }
        atomicAdd(&g_bnpart[1][b][tid], ts);
        atomicAdd(&g_bnpart[1][b][tid + 128], tq);
    }
}

// ----------------------------------------------------------------------------
// Output: GCN aggregation of h4 (12 ch, predicated 8-wide) + gate add
// ----------------------------------------------------------------------------
__global__ void __launch_bounds__(128) out_kernel(
        const float* __restrict__ h4, const float* __restrict__ b4,
        const float* __restrict__ gc, float* __restrict__ out) {
    const int warp = threadIdx.x >> 5;
    const int lane = threadIdx.x & 31;
    const int n = blockIdx.x * 4 + warp;
    const float dn = g_dinv[n];
    const int s0 = g_rowptr[n], s1 = g_rowptr[n + 1];
    float acc = (lane < DOUT) ? h4[n * DOUT + lane] * dn * dn : 0.f;
    for (int j = s0; j < s1; j += 8) {
        int2 e[8];
#pragma unroll
        for (int q = 0; q < 8; q++) {
            int idx = j + q;
            e[q] = (idx < s1) ? __ldg(&g_epack[idx]) : make_int2(n, 0);
        }
        float v[8];
#pragma unroll
        for (int q = 0; q < 8; q++)
            v[q] = (lane < DOUT) ? __ldg(&h4[e[q].x * DOUT + lane]) : 0.f;
#pragma unroll
        for (int q = 0; q < 8; q++) acc += __int_as_float(e[q].y) * v[q];
    }
    if (lane < DOUT)
        out[n * DOUT + lane] = acc + __ldg(&b4[lane]) + __ldg(&gc[n * DOUT + lane]);
}

// ----------------------------------------------------------------------------
// Launch
// ----------------------------------------------------------------------------
extern "C" void kernel_launch(void* const* d_in, const int* in_sizes, int n_in,
                              void* d_out, int out_size) {
    const float* x   = (const float*)d_in[0];
    const int*   ei  = (const int*)d_in[1];
    const float* ew  = (const float*)d_in[2];
    const float* W1  = (const float*)d_in[3];
    const float* b1  = (const float*)d_in[4];
    const float* g1  = (const float*)d_in[5];
    const float* be1 = (const float*)d_in[6];
    const float* Wg  = (const float*)d_in[7];
    const float* atts= (const float*)d_in[8];
    const float* attd= (const float*)d_in[9];
    const float* bg  = (const float*)d_in[10];
    const float* g2  = (const float*)d_in[11];
    const float* be2 = (const float*)d_in[12];
    const float* W3  = (const float*)d_in[13];
    const float* b3  = (const float*)d_in[14];
    const float* g3  = (const float*)d_in[15];
    const float* be3 = (const float*)d_in[16];
    const float* W4  = (const float*)d_in[17];
    const float* b4  = (const float*)d_in[18];
    const float* Wi  = (const float*)d_in[19];
    const float* bi  = (const float*)d_in[20];
    const float* Gw1 = (const float*)d_in[21];
    const float* Gb1 = (const float*)d_in[22];
    const float* Gw2 = (const float*)d_in[23];
    const float* Gb2 = (const float*)d_in[24];
    const float* Ws  = (const float*)d_in[25];
    const float* bs  = (const float*)d_in[26];
    float* out = (float*)d_out;
    const int* src = ei;
    const int* dst = ei + EE;

    float *p_h1, *p_agg, *p_x1, *p_xin, *p_hg, *p_xa, *p_h4, *p_gc;
    float *p_wtg, *p_wt3, *p_wtcomb, *p_bn;
    cudaGetSymbolAddress((void**)&p_h1, g_h1);
    cudaGetSymbolAddress((void**)&p_agg, g_agg);
    cudaGetSymbolAddress((void**)&p_x1, g_x1);
    cudaGetSymbolAddress((void**)&p_xin, g_xin);
    cudaGetSymbolAddress((void**)&p_hg, g_hg);
    cudaGetSymbolAddress((void**)&p_xa, g_xa);
    cudaGetSymbolAddress((void**)&p_h4, g_h4);
    cudaGetSymbolAddress((void**)&p_gc, g_gc);
    cudaGetSymbolAddress((void**)&p_wtg, g_wtg);
    cudaGetSymbolAddress((void**)&p_wt3, g_wt3);
    cudaGetSymbolAddress((void**)&p_wtcomb, g_wtcomb);
    cudaGetSymbolAddress((void**)&p_bn, g_bnpart);

    const int SMEM128 = 1024 + 128 * 132 * 4;                 // 68608
    const int SMEM80  = 1024 + 80 * 132 * 4 + 64 * DOUT * 4;  // 46336
    cudaFuncSetAttribute(mma_gemm<128, false, true, true, false>,
                         cudaFuncAttributeMaxDynamicSharedMemorySize, SMEM128);
    cudaFuncSetAttribute(mma_gemm<128, true, false, false, false>,
                         cudaFuncAttributeMaxDynamicSharedMemorySize, SMEM128);
    cudaFuncSetAttribute(mma_gemm<80, true, false, false, true>,
                         cudaFuncAttributeMaxDynamicSharedMemorySize, SMEM80);
    const int MGRID = (NN + 127) / 128;   // 782

    // graph preprocessing + weight prep
    init_kernel<<<(NN + 255) / 256, 256>>>();
    count_kernel<<<(EE + 255) / 256, 256>>>(dst, ew);
    part_kernel<<<NB, 256>>>();
    writerow_kernel<<<NB, 256>>>();
    fill_kernel<<<(EE + 255) / 256, 256>>>(src, dst, ew);
    prep_weights_kernel<<<168, 256>>>(Wg, W3, Gw1, W4);

    // layer 1
    agg24_kernel<<<NN / 4, 128>>>(x, p_xa);
    gemm_in_kernel<<<NN / 16, 128>>>(p_xa, x, W1, b1, Wi, bi, p_agg, p_xin);

    // GAT: Wg GEMM (in-kernel BN1 finalize) + side-write x1 + att reduce
    mma_gemm<128, false, true, true, false><<<MGRID, 256, SMEM128>>>(
        p_agg, nullptr, p_x1, p_wtg, nullptr, p_hg, nullptr, atts, attd,
        p_bn + 0 * 64 * 256, g1, be1, nullptr, nullptr, nullptr, nullptr, nullptr);
    gat_agg_kernel<<<NN / 8, 256>>>(p_hg, bg, p_agg);

    // layer 3: W3 GEMM (in-kernel BN2 finalize) + xin residual
    mma_gemm<128, true, false, false, false><<<MGRID, 256, SMEM128>>>(
        p_agg, p_xin, nullptr, p_wt3, nullptr, p_h1, nullptr, nullptr, nullptr,
        p_bn + 1 * 64 * 256, g2, be2, nullptr, nullptr, nullptr, nullptr, nullptr);
    gcn_agg128<<<NN / 4, 128>>>(p_h1, b3, p_agg);

    // output: combo GEMM (in-kernel BN3 finalize) + x1 residual + fused gate
    mma_gemm<80, true, false, false, true><<<MGRID, 256, SMEM80>>>(
        p_agg, p_x1, nullptr, p_wtcomb, Gb1, p_gc, p_h4, nullptr, nullptr,
        p_bn + 2 * 64 * 256, g3, be3, Gw2, Gb2, Ws, bs, x);
    out_kernel<<<NN / 4, 128>>>(p_h4, b4, p_gc, out);
}

// round 13
// speedup vs baseline: 1.0067x; 1.0067x over previous
#include <cuda_runtime.h>
#include <math.h>
#include <stdint.h>

#define NN 100000
#define EE 1600000
#define DIN 24
#define HH 128
#define DOUT 12
#define HEADS 4
#define NB 391   // ceil(NN/256)

// ----------------------------------------------------------------------------
// Scratch (device globals; no dynamic allocation allowed)
// ----------------------------------------------------------------------------
__device__ float g_h1[NN * HH];      // h3 = x2@W3
__device__ float g_agg[NN * HH];     // raw pre-BN activations per layer
__device__ float g_x1[NN * HH];      // x1 (side-written by Wg GEMM)
__device__ float g_xin[NN * HH];     // x_in_proj
__device__ float g_hg[NN * HH];      // hg
__device__ float g_xa[NN * DIN];     // 24-dim aggregated x
__device__ float g_h4[NN * DOUT];
__device__ float g_gc[NN * DOUT];    // gate contribution per node
__device__ float g_as[NN * HEADS];
__device__ float g_ad[NN * HEADS];
__device__ float g_deg[NN];
__device__ float g_dinv[NN];
__device__ int   g_cnt[NN];
__device__ int   g_cur[NN];
__device__ int   g_rowptr[NN + 1];
__device__ int2  g_epack[EE];
__device__ int   g_part[512];
__device__ float g_bnpart[3][64][256];  // per-layer bucketed BN partials
__device__ float g_wtg[HH * HH];     // Wg^T  [128,128] K-major
__device__ float g_wt3[HH * HH];     // W3^T
__device__ float g_wtcomb[80 * HH];  // [Gw1^T ; W4^T ; pad]

__device__ __forceinline__ float lrelu(float v) { return v > 0.f ? v : 0.2f * v; }
__device__ __forceinline__ uint32_t to_tf32(float f) {
    uint32_t t;
    asm("cvt.rna.tf32.f32 %0, %1;" : "=r"(t) : "f"(f));
    return t;
}

// ----------------------------------------------------------------------------
// Graph preprocessing
// ----------------------------------------------------------------------------
__global__ void __launch_bounds__(256) init_kernel() {
    int i = blockIdx.x * blockDim.x + threadIdx.x;
    if (i < NN) { g_deg[i] = 1.0f; g_cnt[i] = 0; g_cur[i] = 0; }
    if (i < 3 * 64 * 256) ((float*)g_bnpart)[i] = 0.f;
}

__global__ void __launch_bounds__(256) count_kernel(const int* __restrict__ dst,
                                                    const float* __restrict__ w) {
    int e = blockIdx.x * blockDim.x + threadIdx.x;
    if (e < EE) {
        int d = dst[e];
        atomicAdd(&g_deg[d], w[e]);
        atomicAdd(&g_cnt[d], 1);
    }
}

__global__ void __launch_bounds__(256) part_kernel() {
    __shared__ int sw[8];
    int i = blockIdx.x * 256 + threadIdx.x;
    if (i < NN) g_dinv[i] = rsqrtf(g_deg[i]);
    int v = (i < NN) ? g_cnt[i] : 0;
#pragma unroll
    for (int off = 16; off; off >>= 1) v += __shfl_down_sync(0xffffffffu, v, off);
    if ((threadIdx.x & 31) == 0) sw[threadIdx.x >> 5] = v;
    __syncthreads();
    if (threadIdx.x == 0) {
        int s = 0;
#pragma unroll
        for (int k = 0; k < 8; k++) s += sw[k];
        g_part[blockIdx.x] = s;
    }
}

__global__ void __launch_bounds__(256) writerow_kernel() {
    __shared__ int sp[256];
    __shared__ int swr[8];
    __shared__ int soff;
    const int t = threadIdx.x;
    const int i = blockIdx.x * 256 + t;
    int pre = 0;
    for (int b = t; b < blockIdx.x; b += 256) pre += g_part[b];
#pragma unroll
    for (int off = 16; off; off >>= 1) pre += __shfl_down_sync(0xffffffffu, pre, off);
    if ((t & 31) == 0) swr[t >> 5] = pre;
    __syncthreads();
    if (t == 0) {
        int s = 0;
#pragma unroll
        for (int k = 0; k < 8; k++) s += swr[k];
        soff = s;
    }
    int v = (i < NN) ? g_cnt[i] : 0;
    sp[t] = v;
    __syncthreads();
    for (int off = 1; off < 256; off <<= 1) {
        int a = (t >= off) ? sp[t - off] : 0;
        __syncthreads();
        sp[t] += a;
        __syncthreads();
    }
    if (i < NN) g_rowptr[i] = sp[t] - v + soff;
    if (i == 0) g_rowptr[NN] = EE;
}

__global__ void __launch_bounds__(256) fill_kernel(const int* __restrict__ src,
                                                   const int* __restrict__ dst,
                                                   const float* __restrict__ w) {
    int e = blockIdx.x * blockDim.x + threadIdx.x;
    if (e < EE) {
        int d = dst[e];
        int s = src[e];
        int pos = g_rowptr[d] + atomicAdd(&g_cur[d], 1);
        float coef = w[e] * __ldg(&g_dinv[s]) * __ldg(&g_dinv[d]);
        g_epack[pos] = make_int2(s, __float_as_int(coef));
    }
}

__global__ void __launch_bounds__(256) prep_weights_kernel(const float* __restrict__ Wg,
                                                           const float* __restrict__ W3,
                                                           const float* __restrict__ Gw1,
                                                           const float* __restrict__ W4) {
    int idx = blockIdx.x * 256 + threadIdx.x;
    if (idx < 16384) {
        int k = idx >> 7, c = idx & 127;
        g_wtg[c * 128 + k] = __ldg(&Wg[idx]);
    } else if (idx < 32768) {
        int j = idx - 16384;
        int k = j >> 7, c = j & 127;
        g_wt3[c * 128 + k] = __ldg(&W3[j]);
    } else if (idx < 43008) {
        int j = idx - 32768;
        int r = j >> 7, k = j & 127;
        float v = 0.f;
        if (r < 64) v = __ldg(&Gw1[k * 64 + r]);
        else if (r < 76) v = __ldg(&W4[k * DOUT + (r - 64)]);
        g_wtcomb[j] = v;
    }
}

// ----------------------------------------------------------------------------
// 24-channel GCN aggregation: unpredicated 8-wide main + predicated 8-wide tail
// ----------------------------------------------------------------------------
__global__ void __launch_bounds__(128) agg24_kernel(const float* __restrict__ x,
                                                    float* __restrict__ xa) {
    const int warp = threadIdx.x >> 5;
    const int lane = threadIdx.x & 31;
    const int n = blockIdx.x * 4 + warp;
    const float dn = g_dinv[n];
    const int s0 = g_rowptr[n], s1 = g_rowptr[n + 1];
    float acc = (lane < DIN) ? x[n * DIN + lane] * dn * dn : 0.f;
    int j = s0;
    for (; j + 8 <= s1; j += 8) {
        int2 e[8];
        float v[8];
#pragma unroll
        for (int q = 0; q < 8; q++) e[q] = __ldg(&g_epack[j + q]);
#pragma unroll
        for (int q = 0; q < 8; q++)
            v[q] = (lane < DIN) ? __ldg(&x[e[q].x * DIN + lane]) : 0.f;
#pragma unroll
        for (int q = 0; q < 8; q++) acc += __int_as_float(e[q].y) * v[q];
    }
    if (j < s1) {
        int2 e[8];
        float v[8];
#pragma unroll
        for (int q = 0; q < 8; q++)
            e[q] = (j + q < s1) ? __ldg(&g_epack[j + q]) : make_int2(n, 0);
#pragma unroll
        for (int q = 0; q < 8; q++)
            v[q] = (lane < DIN) ? __ldg(&x[e[q].x * DIN + lane]) : 0.f;
#pragma unroll
        for (int q = 0; q < 8; q++) acc += __int_as_float(e[q].y) * v[q];
    }
    if (lane < DIN) xa[n * DIN + lane] = acc;
}

// ----------------------------------------------------------------------------
// TF32 mma.sync GEMM. In-kernel BN finalize from bucketed partials.
// ----------------------------------------------------------------------------
template<int NC, bool ADD, bool WRITEX, bool ATT, bool COMBO>
__global__ void __launch_bounds__(256) mma_gemm(const float* __restrict__ Araw,
                                                const float* __restrict__ addp,
                                                float* __restrict__ xout,
                                                const float* __restrict__ Bt,
                                                const float* __restrict__ bias,
                                                float* __restrict__ out,
                                                float* __restrict__ out2,
                                                const float* __restrict__ att_s,
                                                const float* __restrict__ att_d,
                                                const float* __restrict__ bnp,
                                                const float* __restrict__ bng,
                                                const float* __restrict__ bnbe,
                                                const float* __restrict__ Gw2,
                                                const float* __restrict__ Gb2,
                                                const float* __restrict__ Ws,
                                                const float* __restrict__ bs,
                                                const float* __restrict__ xfull) {
    extern __shared__ float smf[];
    float* sSC = smf;
    float* sSH = smf + 128;
    uint32_t* sW = (uint32_t*)(smf + 256);   // [NC][132]
    float* sG = smf + 256 + NC * 132;        // [64*12] (COMBO only)
    const int tid = threadIdx.x, wid = tid >> 5, lane = tid & 31;
    const int n0 = blockIdx.x * 128;

    if (tid < 128) {
        float s = 0.f, s2 = 0.f;
#pragma unroll 8
        for (int b = 0; b < 64; b++) {
            s += __ldg(&bnp[b * 256 + tid]);
            s2 += __ldg(&bnp[b * 256 + tid + 128]);
        }
        float mean = s * (1.0f / NN);
        float var = fmaxf(s2 * (1.0f / NN) - mean * mean, 0.f);
        float sc = rsqrtf(var + 1e-5f) * __ldg(&bng[tid]);
        sSC[tid] = sc;
        sSH[tid] = __ldg(&bnbe[tid]) - mean * sc;
    }
    for (int i = tid; i < NC * 128; i += 256) {
        int c = i >> 7, k = i & 127;
        sW[c * 132 + k] = to_tf32(__ldg(&Bt[i]));
    }
    if (COMBO) {
        for (int i = tid; i < 64 * DOUT; i += 256) sG[i] = __ldg(&Gw2[i]);
    }
    __syncthreads();

    constexpr int NCH = NC / 8;
    float acc[NCH][4];
#pragma unroll
    for (int i = 0; i < NCH; i++) {
        acc[i][0] = 0.f; acc[i][1] = 0.f; acc[i][2] = 0.f; acc[i][3] = 0.f;
    }

    const int r0 = n0 + wid * 16 + (lane >> 2);
    const int r1 = r0 + 8;
    const bool v0 = r0 < NN, v1 = r1 < NN;
    const int kq = lane & 3;
    const int nq = lane >> 2;

#pragma unroll 4
    for (int k8 = 0; k8 < 128; k8 += 8) {
        int ka = k8 + kq, kb = k8 + kq + 4;
        float f0 = 0.f, f1 = 0.f, f2 = 0.f, f3 = 0.f;
        if (v0) {
            f0 = fmaxf(__ldg(&Araw[(size_t)r0 * 128 + ka]) * sSC[ka] + sSH[ka], 0.f);
            f2 = fmaxf(__ldg(&Araw[(size_t)r0 * 128 + kb]) * sSC[kb] + sSH[kb], 0.f);
            if (ADD) {
                f0 += __ldg(&addp[(size_t)r0 * 128 + ka]);
                f2 += __ldg(&addp[(size_t)r0 * 128 + kb]);
            }
            if (WRITEX) {
                xout[(size_t)r0 * 128 + ka] = f0;
                xout[(size_t)r0 * 128 + kb] = f2;
            }
        }
        if (v1) {
            f1 = fmaxf(__ldg(&Araw[(size_t)r1 * 128 + ka]) * sSC[ka] + sSH[ka], 0.f);
            f3 = fmaxf(__ldg(&Araw[(size_t)r1 * 128 + kb]) * sSC[kb] + sSH[kb], 0.f);
            if (ADD) {
                f1 += __ldg(&addp[(size_t)r1 * 128 + ka]);
                f3 += __ldg(&addp[(size_t)r1 * 128 + kb]);
            }
            if (WRITEX) {
                xout[(size_t)r1 * 128 + ka] = f1;
                xout[(size_t)r1 * 128 + kb] = f3;
            }
        }
        uint32_t a0 = to_tf32(f0), a1 = to_tf32(f1), a2 = to_tf32(f2), a3 = to_tf32(f3);
#pragma unroll
        for (int nc = 0; nc < NCH; nc++) {
            uint32_t b0 = sW[(nc * 8 + nq) * 132 + ka];
            uint32_t b1 = sW[(nc * 8 + nq) * 132 + kb];
            asm volatile(
                "mma.sync.aligned.m16n8k8.row.col.f32.tf32.tf32.f32 "
                "{%0,%1,%2,%3}, {%4,%5,%6,%7}, {%8,%9}, {%0,%1,%2,%3};"
                : "+f"(acc[nc][0]), "+f"(acc[nc][1]), "+f"(acc[nc][2]), "+f"(acc[nc][3])
                : "r"(a0), "r"(a1), "r"(a2), "r"(a3), "r"(b0), "r"(b1));
        }
    }

    const int colb = 2 * kq;
    if (COMBO) {
        float z0[DOUT], z1[DOUT];
#pragma unroll
        for (int c = 0; c < DOUT; c++) { z0[c] = 0.f; z1[c] = 0.f; }
#pragma unroll
        for (int nc = 0; nc < NCH; nc++) {
            int col = nc * 8 + colb;
            if (col < 64) {
                float bx = __ldg(&bias[col]), by = __ldg(&bias[col + 1]);
                float t0a = fmaxf(acc[nc][0] + bx, 0.f), t0b = fmaxf(acc[nc][1] + by, 0.f);
                float t1a = fmaxf(acc[nc][2] + bx, 0.f), t1b = fmaxf(acc[nc][3] + by, 0.f);
#pragma unroll
                for (int c = 0; c < DOUT; c++) {
                    float w0 = sG[col * DOUT + c], w1 = sG[(col + 1) * DOUT + c];
                    z0[c] += t0a * w0 + t0b * w1;
                    z1[c] += t1a * w0 + t1b * w1;
                }
            } else if (col < 76) {
                int c2 = col - 64;
                if (v0) *(float2*)&out2[(size_t)r0 * DOUT + c2] =
                            make_float2(acc[nc][0], acc[nc][1]);
                if (v1) *(float2*)&out2[(size_t)r1 * DOUT + c2] =
                            make_float2(acc[nc][2], acc[nc][3]);
            }
        }
#pragma unroll
        for (int c = 0; c < DOUT; c++) {
            z0[c] += __shfl_xor_sync(0xffffffffu, z0[c], 1);
            z0[c] += __shfl_xor_sync(0xffffffffu, z0[c], 2);
            z1[c] += __shfl_xor_sync(0xffffffffu, z1[c], 1);
            z1[c] += __shfl_xor_sync(0xffffffffu, z1[c], 2);
        }
        if (kq == 0) {
            if (v0) {
                float status = __ldg(&xfull[(size_t)r0 * DIN + 12]);
                float flag = status < 0.5f ? 2.5f : 0.f;
#pragma unroll
                for (int c = 0; c < DOUT; c++) {
                    float gate = 1.f / (1.f + expf(-(z0[c] + __ldg(&Gb2[c]))));
                    float sig = (1.f - status) * __ldg(&Ws[c]) + __ldg(&bs[c]);
                    out[(size_t)r0 * DOUT + c] = flag * gate * sig;
                }
            }
            if (v1) {
                float status = __ldg(&xfull[(size_t)r1 * DIN + 12]);
                float flag = status < 0.5f ? 2.5f : 0.f;
#pragma unroll
                for (int c = 0; c < DOUT; c++) {
                    float gate = 1.f / (1.f + expf(-(z1[c] + __ldg(&Gb2[c]))));
                    float sig = (1.f - status) * __ldg(&Ws[c]) + __ldg(&bs[c]);
                    out[(size_t)r1 * DOUT + c] = flag * gate * sig;
                }
            }
        }
    } else {
#pragma unroll
        for (int nc = 0; nc < NCH; nc++) {
            int col = nc * 8 + colb;
            if (v0) *(float2*)&out[(size_t)r0 * NC + col] =
                        make_float2(acc[nc][0], acc[nc][1]);
            if (v1) *(float2*)&out[(size_t)r1 * NC + col] =
                        make_float2(acc[nc][2], acc[nc][3]);
        }
    }

    if (ATT) {
        float as0[4] = {}, ad0[4] = {}, as1[4] = {}, ad1[4] = {};
#pragma unroll
        for (int nc = 0; nc < NCH; nc++) {
            int col = nc * 8 + colb;
            float sx = __ldg(&att_s[col]), sy = __ldg(&att_s[col + 1]);
            float dx = __ldg(&att_d[col]), dy = __ldg(&att_d[col + 1]);
            int h = nc >> 2;
            as0[h] += acc[nc][0] * sx + acc[nc][1] * sy;
            ad0[h] += acc[nc][0] * dx + acc[nc][1] * dy;
            as1[h] += acc[nc][2] * sx + acc[nc][3] * sy;
            ad1[h] += acc[nc][2] * dx + acc[nc][3] * dy;
        }
#pragma unroll
        for (int h = 0; h < 4; h++) {
#pragma unroll
            for (int off = 1; off <= 2; off <<= 1) {
                as0[h] += __shfl_xor_sync(0xffffffffu, as0[h], off);
                ad0[h] += __shfl_xor_sync(0xffffffffu, ad0[h], off);
                as1[h] += __shfl_xor_sync(0xffffffffu, as1[h], off);
                ad1[h] += __shfl_xor_sync(0xffffffffu, ad1[h], off);
            }
        }
        if (kq == 0) {
#pragma unroll
            for (int h = 0; h < 4; h++) {
                if (v0) { g_as[r0 * 4 + h] = as0[h]; g_ad[r0 * 4 + h] = ad0[h]; }
                if (v1) { g_as[r1 * 4 + h] = as1[h]; g_ad[r1 * 4 + h] = ad1[h]; }
            }
        }
    }
}

// ----------------------------------------------------------------------------
// Fused input GEMM: agg1 = xa@W1 + b1, xin = x@Wi + bi, + fused BN1 partials
// ----------------------------------------------------------------------------
__global__ void __launch_bounds__(128) gemm_in_kernel(
        const float* __restrict__ XA, const float* __restrict__ X,
        const float* __restrict__ W1, const float* __restrict__ b1,
        const float* __restrict__ Wi, const float* __restrict__ bi,
        float* __restrict__ h1, float* __restrict__ xin) {
    __shared__ float sS[4][128], sQ[4][128];
    const int tid = threadIdx.x;
    const int cg = tid & 31;
    const int rg = tid >> 5;
    const int n0 = blockIdx.x * 16 + rg * 4;
    float a1[4][4] = {}; float ai[4][4] = {};
    const float4* W1v = (const float4*)W1;
    const float4* Wiv = (const float4*)Wi;
#pragma unroll
    for (int k = 0; k < DIN; k++) {
        float4 w1 = __ldg(&W1v[k * 32 + cg]);
        float4 wi = __ldg(&Wiv[k * 32 + cg]);
#pragma unroll
        for (int r = 0; r < 4; r++) {
            float xav = __ldg(&XA[(n0 + r) * DIN + k]);
            float xv  = __ldg(&X[(n0 + r) * DIN + k]);
            a1[r][0] += xav * w1.x; a1[r][1] += xav * w1.y; a1[r][2] += xav * w1.z; a1[r][3] += xav * w1.w;
            ai[r][0] += xv * wi.x;  ai[r][1] += xv * wi.y;  ai[r][2] += xv * wi.z;  ai[r][3] += xv * wi.w;
        }
    }
    const int c0 = cg * 4;
    float4 b1v = __ldg(&((const float4*)b1)[cg]);
    float4 biv = __ldg(&((const float4*)bi)[cg]);
    float s4[4] = {}, q4[4] = {};
#pragma unroll
    for (int r = 0; r < 4; r++) {
        float4 v1, vi;
        v1.x = a1[r][0] + b1v.x; v1.y = a1[r][1] + b1v.y;
        v1.z = a1[r][2] + b1v.z; v1.w = a1[r][3] + b1v.w;
        vi.x = ai[r][0] + biv.x; vi.y = ai[r][1] + biv.y;
        vi.z = ai[r][2] + biv.z; vi.w = ai[r][3] + biv.w;
        s4[0] += v1.x; q4[0] += v1.x * v1.x;
        s4[1] += v1.y; q4[1] += v1.y * v1.y;
        s4[2] += v1.z; q4[2] += v1.z * v1.z;
        s4[3] += v1.w; q4[3] += v1.w * v1.w;
        *(float4*)&h1[(n0 + r) * HH + c0] = v1;
        *(float4*)&xin[(n0 + r) * HH + c0] = vi;
    }
#pragma unroll
    for (int i = 0; i < 4; i++) { sS[rg][c0 + i] = s4[i]; sQ[rg][c0 + i] = q4[i]; }
    __syncthreads();
    const int b = blockIdx.x & 63;
    float ts = sS[0][tid] + sS[1][tid] + sS[2][tid] + sS[3][tid];
    float tq = sQ[0][tid] + sQ[1][tid] + sQ[2][tid] + sQ[3][tid];
    atomicAdd(&g_bnpart[0][b][tid], ts);
    atomicAdd(&g_bnpart[0][b][tid + 128], tq);
}

// ----------------------------------------------------------------------------
// GCN aggregation (128 ch): 8-wide main + predicated 8-wide tail + BN3 partials
// ----------------------------------------------------------------------------
__global__ void __launch_bounds__(128) gcn_agg128(const float* __restrict__ in,
                                                  const float* __restrict__ bias,
                                                  float* __restrict__ out) {
    __shared__ float sS[4][128], sQ[4][128];
    const int warp = threadIdx.x >> 5;
    const int lane = threadIdx.x & 31;
    const int n = blockIdx.x * 4 + warp;
    const float dn = g_dinv[n];
    const int s0 = g_rowptr[n], s1 = g_rowptr[n + 1];
    const float4* in4 = (const float4*)in;
    float4 acc = __ldg(&in4[n * 32 + lane]);
    float dn2 = dn * dn;
    acc.x *= dn2; acc.y *= dn2; acc.z *= dn2; acc.w *= dn2;
    int j = s0;
    for (; j + 8 <= s1; j += 8) {
        int2 e[8];
        float4 v[8];
#pragma unroll
        for (int q = 0; q < 8; q++) e[q] = __ldg(&g_epack[j + q]);
#pragma unroll
        for (int q = 0; q < 8; q++) v[q] = __ldg(&in4[e[q].x * 32 + lane]);
#pragma unroll
        for (int q = 0; q < 8; q++) {
            float c = __int_as_float(e[q].y);
            acc.x += c * v[q].x; acc.y += c * v[q].y;
            acc.z += c * v[q].z; acc.w += c * v[q].w;
        }
    }
    if (j < s1) {
        int2 e[8];
        float4 v[8];
#pragma unroll
        for (int q = 0; q < 8; q++)
            e[q] = (j + q < s1) ? __ldg(&g_epack[j + q]) : make_int2(n, 0);
#pragma unroll
        for (int q = 0; q < 8; q++) v[q] = __ldg(&in4[e[q].x * 32 + lane]);
#pragma unroll
        for (int q = 0; q < 8; q++) {
            float c = __int_as_float(e[q].y);
            acc.x += c * v[q].x; acc.y += c * v[q].y;
            acc.z += c * v[q].z; acc.w += c * v[q].w;
        }
    }
    float4 bv = __ldg(&((const float4*)bias)[lane]);
    acc.x += bv.x; acc.y += bv.y; acc.z += bv.z; acc.w += bv.w;
    ((float4*)out)[n * 32 + lane] = acc;
    sS[warp][lane * 4 + 0] = acc.x; sQ[warp][lane * 4 + 0] = acc.x * acc.x;
    sS[warp][lane * 4 + 1] = acc.y; sQ[warp][lane * 4 + 1] = acc.y * acc.y;
    sS[warp][lane * 4 + 2] = acc.z; sQ[warp][lane * 4 + 2] = acc.z * acc.z;
    sS[warp][lane * 4 + 3] = acc.w; sQ[warp][lane * 4 + 3] = acc.w * acc.w;
    __syncthreads();
    const int tid = threadIdx.x;
    const int b = blockIdx.x & 63;
    float ts = sS[0][tid] + sS[1][tid] + sS[2][tid] + sS[3][tid];
    float tq = sQ[0][tid] + sQ[1][tid] + sQ[2][tid] + sQ[3][tid];
    atomicAdd(&g_bnpart[2][b][tid], ts);
    atomicAdd(&g_bnpart[2][b][tid + 128], tq);
}

// ----------------------------------------------------------------------------
// GAT aggregation: single pass, 8-wide main + predicated tail + BN2 partials
// ----------------------------------------------------------------------------
__global__ void __launch_bounds__(256) gat_agg_kernel(const float* __restrict__ hg,
                                                      const float* __restrict__ bg,
                                                      float* __restrict__ out) {
    __shared__ float sS[8][128], sQ[8][128];
    const int w = threadIdx.x >> 5;
    const int lane = threadIdx.x & 31;
    const int n = blockIdx.x * 8 + w;
    const int s0 = g_rowptr[n], s1 = g_rowptr[n + 1];
    const int h = lane >> 3;
    const int eq = lane & 7;
    const float4* ad4 = (const float4*)g_ad;
    const float4* as4 = (const float4*)g_as;

    float4 adv = __ldg(&ad4[n]);
    float4 asv = __ldg(&as4[n]);
    float adh = h < 2 ? (h == 0 ? adv.x : adv.y) : (h == 2 ? adv.z : adv.w);
    float ash = h < 2 ? (h == 0 ? asv.x : asv.y) : (h == 2 ? asv.z : asv.w);
    float xs = expf(lrelu(ash + adh));

    const float4* hg4 = (const float4*)hg;
    float4 acc = make_float4(0.f, 0.f, 0.f, 0.f);
    float tsum = 0.f;

    int j = s0;
    for (; j + 8 <= s1; j += 8) {
        int2 e[8];
#pragma unroll
        for (int q = 0; q < 8; q++) e[q] = __ldg(&g_epack[j + q]);
        float myx = expf(lrelu(__ldg(&g_as[e[eq].x * 4 + h]) + adh));
        tsum += myx;
        float4 v[8];
#pragma unroll
        for (int q = 0; q < 8; q++) v[q] = __ldg(&hg4[e[q].x * 32 + lane]);
#pragma unroll
        for (int q = 0; q < 8; q++) {
            float a = __shfl_sync(0xffffffffu, myx, h * 8 + q);
            acc.x += a * v[q].x; acc.y += a * v[q].y;
            acc.z += a * v[q].z; acc.w += a * v[q].w;
        }
    }
    if (j < s1) {
        int2 e[8];
#pragma unroll
        for (int q = 0; q < 8; q++)
            e[q] = (j + q < s1) ? __ldg(&g_epack[j + q]) : make_int2(n, 0);
        float myx = (j + eq < s1)
                        ? expf(lrelu(__ldg(&g_as[e[eq].x * 4 + h]) + adh)) : 0.f;
        tsum += myx;
        float4 v[8];
#pragma unroll
        for (int q = 0; q < 8; q++) v[q] = __ldg(&hg4[e[q].x * 32 + lane]);
#pragma unroll
        for (int q = 0; q < 8; q++) {
            float a = __shfl_sync(0xffffffffu, myx, h * 8 + q);
            acc.x += a * v[q].x; acc.y += a * v[q].y;
            acc.z += a * v[q].z; acc.w += a * v[q].w;
        }
    }
#pragma unroll
    for (int off = 1; off <= 4; off <<= 1)
        tsum += __shfl_xor_sync(0xffffffffu, tsum, off);
    float inv = 1.f / (tsum + xs);

    float4 self = __ldg(&hg4[n * 32 + lane]);
    float4 bv = __ldg(&((const float4*)bg)[lane]);
    float4 o;
    o.x = (acc.x + xs * self.x) * inv + bv.x;
    o.y = (acc.y + xs * self.y) * inv + bv.y;
    o.z = (acc.z + xs * self.z) * inv + bv.z;
    o.w = (acc.w + xs * self.w) * inv + bv.w;
    ((float4*)out)[n * 32 + lane] = o;
    sS[w][lane * 4 + 0] = o.x; sQ[w][lane * 4 + 0] = o.x * o.x;
    sS[w][lane * 4 + 1] = o.y; sQ[w][lane * 4 + 1] = o.y * o.y;
    sS[w][lane * 4 + 2] = o.z; sQ[w][lane * 4 + 2] = o.z * o.z;
    sS[w][lane * 4 + 3] = o.w; sQ[w][lane * 4 + 3] = o.w * o.w;
    __syncthreads();
    const int tid = threadIdx.x;
    if (tid < 128) {
        const int b = blockIdx.x & 63;
        float ts = 0.f, tq = 0.f;
#pragma unroll
        for (int ww = 0; ww < 8; ww++) { ts += sS[ww][tid]; tq += sQ[ww][tid]; }
        atomicAdd(&g_bnpart[1][b][tid], ts);
        atomicAdd(&g_bnpart[1][b][tid + 128], tq);
    }
}

// ----------------------------------------------------------------------------
// Output: GCN aggregation of h4 (12 ch): 8-wide main + predicated tail + gate
// ----------------------------------------------------------------------------
__global__ void __launch_bounds__(128) out_kernel(
        const float* __restrict__ h4, const float* __restrict__ b4,
        const float* __restrict__ gc, float* __restrict__ out) {
    const int warp = threadIdx.x >> 5;
    const int lane = threadIdx.x & 31;
    const int n = blockIdx.x * 4 + warp;
    const float dn = g_dinv[n];
    const int s0 = g_rowptr[n], s1 = g_rowptr[n + 1];
    float acc = (lane < DOUT) ? h4[n * DOUT + lane] * dn * dn : 0.f;
    int j = s0;
    for (; j + 8 <= s1; j += 8) {
        int2 e[8];
        float v[8];
#pragma unroll
        for (int q = 0; q < 8; q++) e[q] = __ldg(&g_epack[j + q]);
#pragma unroll
        for (int q = 0; q < 8; q++)
            v[q] = (lane < DOUT) ? __ldg(&h4[e[q].x * DOUT + lane]) : 0.f;
#pragma unroll
        for (int q = 0; q < 8; q++) acc += __int_as_float(e[q].y) * v[q];
    }
    if (j < s1) {
        int2 e[8];
        float v[8];
#pragma unroll
        for (int q = 0; q < 8; q++)
            e[q] = (j + q < s1) ? __ldg(&g_epack[j + q]) : make_int2(n, 0);
#pragma unroll
        for (int q = 0; q < 8; q++)
            v[q] = (lane < DOUT) ? __ldg(&h4[e[q].x * DOUT + lane]) : 0.f;
#pragma unroll
        for (int q = 0; q < 8; q++) acc += __int_as_float(e[q].y) * v[q];
    }
    if (lane < DOUT)
        out[n * DOUT + lane] = acc + __ldg(&b4[lane]) + __ldg(&gc[n * DOUT + lane]);
}

// ----------------------------------------------------------------------------
// Launch
// ----------------------------------------------------------------------------
extern "C" void kernel_launch(void* const* d_in, const int* in_sizes, int n_in,
                              void* d_out, int out_size) {
    const float* x   = (const float*)d_in[0];
    const int*   ei  = (const int*)d_in[1];
    const float* ew  = (const float*)d_in[2];
    const float* W1  = (const float*)d_in[3];
    const float* b1  = (const float*)d_in[4];
    const float* g1  = (const float*)d_in[5];
    const float* be1 = (const float*)d_in[6];
    const float* Wg  = (const float*)d_in[7];
    const float* atts= (const float*)d_in[8];
    const float* attd= (const float*)d_in[9];
    const float* bg  = (const float*)d_in[10];
    const float* g2  = (const float*)d_in[11];
    const float* be2 = (const float*)d_in[12];
    const float* W3  = (const float*)d_in[13];
    const float* b3  = (const float*)d_in[14];
    const float* g3  = (const float*)d_in[15];
    const float* be3 = (const float*)d_in[16];
    const float* W4  = (const float*)d_in[17];
    const float* b4  = (const float*)d_in[18];
    const float* Wi  = (const float*)d_in[19];
    const float* bi  = (const float*)d_in[20];
    const float* Gw1 = (const float*)d_in[21];
    const float* Gb1 = (const float*)d_in[22];
    const float* Gw2 = (const float*)d_in[23];
    const float* Gb2 = (const float*)d_in[24];
    const float* Ws  = (const float*)d_in[25];
    const float* bs  = (const float*)d_in[26];
    float* out = (float*)d_out;
    const int* src = ei;
    const int* dst = ei + EE;

    float *p_h1, *p_agg, *p_x1, *p_xin, *p_hg, *p_xa, *p_h4, *p_gc;
    float *p_wtg, *p_wt3, *p_wtcomb, *p_bn;
    cudaGetSymbolAddress((void**)&p_h1, g_h1);
    cudaGetSymbolAddress((void**)&p_agg, g_agg);
    cudaGetSymbolAddress((void**)&p_x1, g_x1);
    cudaGetSymbolAddress((void**)&p_xin, g_xin);
    cudaGetSymbolAddress((void**)&p_hg, g_hg);
    cudaGetSymbolAddress((void**)&p_xa, g_xa);
    cudaGetSymbolAddress((void**)&p_h4, g_h4);
    cudaGetSymbolAddress((void**)&p_gc, g_gc);
    cudaGetSymbolAddress((void**)&p_wtg, g_wtg);
    cudaGetSymbolAddress((void**)&p_wt3, g_wt3);
    cudaGetSymbolAddress((void**)&p_wtcomb, g_wtcomb);
    cudaGetSymbolAddress((void**)&p_bn, g_bnpart);

    const int SMEM128 = 1024 + 128 * 132 * 4;                 // 68608
    const int SMEM80  = 1024 + 80 * 132 * 4 + 64 * DOUT * 4;  // 46336
    cudaFuncSetAttribute(mma_gemm<128, false, true, true, false>,
                         cudaFuncAttributeMaxDynamicSharedMemorySize, SMEM128);
    cudaFuncSetAttribute(mma_gemm<128, true, false, false, false>,
                         cudaFuncAttributeMaxDynamicSharedMemorySize, SMEM128);
    cudaFuncSetAttribute(mma_gemm<80, true, false, false, true>,
                         cudaFuncAttributeMaxDynamicSharedMemorySize, SMEM80);
    const int MGRID = (NN + 127) / 128;   // 782

    // graph preprocessing + weight prep
    init_kernel<<<(NN + 255) / 256, 256>>>();
    count_kernel<<<(EE + 255) / 256, 256>>>(dst, ew);
    part_kernel<<<NB, 256>>>();
    writerow_kernel<<<NB, 256>>>();
    fill_kernel<<<(EE + 255) / 256, 256>>>(src, dst, ew);
    prep_weights_kernel<<<168, 256>>>(Wg, W3, Gw1, W4);

    // layer 1
    agg24_kernel<<<NN / 4, 128>>>(x, p_xa);
    gemm_in_kernel<<<NN / 16, 128>>>(p_xa, x, W1, b1, Wi, bi, p_agg, p_xin);

    // GAT: Wg GEMM (in-kernel BN1 finalize) + side-write x1 + att reduce
    mma_gemm<128, false, true, true, false><<<MGRID, 256, SMEM128>>>(
        p_agg, nullptr, p_x1, p_wtg, nullptr, p_hg, nullptr, atts, attd,
        p_bn + 0 * 64 * 256, g1, be1, nullptr, nullptr, nullptr, nullptr, nullptr);
    gat_agg_kernel<<<NN / 8, 256>>>(p_hg, bg, p_agg);

    // layer 3: W3 GEMM (in-kernel BN2 finalize) + xin residual
    mma_gemm<128, true, false, false, false><<<MGRID, 256, SMEM128>>>(
        p_agg, p_xin, nullptr, p_wt3, nullptr, p_h1, nullptr, nullptr, nullptr,
        p_bn + 1 * 64 * 256, g2, be2, nullptr, nullptr, nullptr, nullptr, nullptr);
    gcn_agg128<<<NN / 4, 128>>>(p_h1, b3, p_agg);

    // output: combo GEMM (in-kernel BN3 finalize) + x1 residual + fused gate
    mma_gemm<80, true, false, false, true><<<MGRID, 256, SMEM80>>>(
        p_agg, p_x1, nullptr, p_wtcomb, Gb1, p_gc, p_h4, nullptr, nullptr,
        p_bn + 2 * 64 * 256, g3, be3, Gw2, Gb2, Ws, bs, x);
    out_kernel<<<NN / 4, 128>>>(p_h4, b4, p_gc, out);
}

// round 14
// speedup vs baseline: 1.0239x; 1.0170x over previous
#include <cuda_runtime.h>
#include <math.h>
#include <stdint.h>

#define NN 100000
#define EE 1600000
#define DIN 24
#define HH 128
#define DOUT 12
#define HEADS 4
#define NB 391   // ceil(NN/256)

// ----------------------------------------------------------------------------
// Scratch (device globals; no dynamic allocation allowed)
// ----------------------------------------------------------------------------
__device__ float g_h1[NN * HH];      // h3 = x2@W3
__device__ float g_agg[NN * HH];     // raw pre-BN activations per layer
__device__ float g_x1[NN * HH];      // x1 (side-written by Wg GEMM)
__device__ float g_xin[NN * HH];     // x_in_proj
__device__ float g_hg[NN * HH];      // hg
__device__ float g_xa[NN * DIN];     // 24-dim aggregated x
__device__ float g_h4[NN * DOUT];
__device__ float g_gc[NN * DOUT];    // gate contribution per node
__device__ float g_as[NN * HEADS];
__device__ float g_ad[NN * HEADS];
__device__ float g_deg[NN];
__device__ float g_dinv[NN];
__device__ int   g_cnt[NN];
__device__ int   g_cur[NN];
__device__ int   g_rowptr[NN + 1];
__device__ int2  g_epack[EE];
__device__ int   g_part[512];
__device__ float g_bnpart[3][64][256];  // per-layer bucketed BN partials
__device__ float g_wtg[HH * HH];     // Wg^T  [128,128] K-major
__device__ float g_wt3[HH * HH];     // W3^T
__device__ float g_wtcomb[80 * HH];  // [Gw1^T ; W4^T ; pad]

__device__ __forceinline__ float lrelu(float v) { return v > 0.f ? v : 0.2f * v; }
__device__ __forceinline__ uint32_t to_tf32(float f) {
    uint32_t t;
    asm("cvt.rna.tf32.f32 %0, %1;" : "=r"(t) : "f"(f));
    return t;
}

// ----------------------------------------------------------------------------
// Graph preprocessing
// ----------------------------------------------------------------------------
__global__ void __launch_bounds__(256) init_kernel() {
    int i = blockIdx.x * blockDim.x + threadIdx.x;
    if (i < NN) { g_deg[i] = 1.0f; g_cnt[i] = 0; g_cur[i] = 0; }
    if (i < 3 * 64 * 256) ((float*)g_bnpart)[i] = 0.f;
}

__global__ void __launch_bounds__(256) count_kernel(const int* __restrict__ dst,
                                                    const float* __restrict__ w) {
    int e = blockIdx.x * blockDim.x + threadIdx.x;
    if (e < EE) {
        int d = dst[e];
        atomicAdd(&g_deg[d], w[e]);
        atomicAdd(&g_cnt[d], 1);
    }
}

__global__ void __launch_bounds__(256) part_kernel() {
    __shared__ int sw[8];
    int i = blockIdx.x * 256 + threadIdx.x;
    if (i < NN) g_dinv[i] = rsqrtf(g_deg[i]);
    int v = (i < NN) ? g_cnt[i] : 0;
#pragma unroll
    for (int off = 16; off; off >>= 1) v += __shfl_down_sync(0xffffffffu, v, off);
    if ((threadIdx.x & 31) == 0) sw[threadIdx.x >> 5] = v;
    __syncthreads();
    if (threadIdx.x == 0) {
        int s = 0;
#pragma unroll
        for (int k = 0; k < 8; k++) s += sw[k];
        g_part[blockIdx.x] = s;
    }
}

__global__ void __launch_bounds__(256) writerow_kernel() {
    __shared__ int sp[256];
    __shared__ int swr[8];
    __shared__ int soff;
    const int t = threadIdx.x;
    const int i = blockIdx.x * 256 + t;
    int pre = 0;
    for (int b = t; b < blockIdx.x; b += 256) pre += g_part[b];
#pragma unroll
    for (int off = 16; off; off >>= 1) pre += __shfl_down_sync(0xffffffffu, pre, off);
    if ((t & 31) == 0) swr[t >> 5] = pre;
    __syncthreads();
    if (t == 0) {
        int s = 0;
#pragma unroll
        for (int k = 0; k < 8; k++) s += swr[k];
        soff = s;
    }
    int v = (i < NN) ? g_cnt[i] : 0;
    sp[t] = v;
    __syncthreads();
    for (int off = 1; off < 256; off <<= 1) {
        int a = (t >= off) ? sp[t - off] : 0;
        __syncthreads();
        sp[t] += a;
        __syncthreads();
    }
    if (i < NN) g_rowptr[i] = sp[t] - v + soff;
    if (i == 0) g_rowptr[NN] = EE;
}

__global__ void __launch_bounds__(256) fill_kernel(const int* __restrict__ src,
                                                   const int* __restrict__ dst,
                                                   const float* __restrict__ w) {
    int e = blockIdx.x * blockDim.x + threadIdx.x;
    if (e < EE) {
        int d = dst[e];
        int s = src[e];
        int pos = g_rowptr[d] + atomicAdd(&g_cur[d], 1);
        float coef = w[e] * __ldg(&g_dinv[s]) * __ldg(&g_dinv[d]);
        g_epack[pos] = make_int2(s, __float_as_int(coef));
    }
}

__global__ void __launch_bounds__(256) prep_weights_kernel(const float* __restrict__ Wg,
                                                           const float* __restrict__ W3,
                                                           const float* __restrict__ Gw1,
                                                           const float* __restrict__ W4) {
    int idx = blockIdx.x * 256 + threadIdx.x;
    if (idx < 16384) {
        int k = idx >> 7, c = idx & 127;
        g_wtg[c * 128 + k] = __ldg(&Wg[idx]);
    } else if (idx < 32768) {
        int j = idx - 16384;
        int k = j >> 7, c = j & 127;
        g_wt3[c * 128 + k] = __ldg(&W3[j]);
    } else if (idx < 43008) {
        int j = idx - 32768;
        int r = j >> 7, k = j & 127;
        float v = 0.f;
        if (r < 64) v = __ldg(&Gw1[k * 64 + r]);
        else if (r < 76) v = __ldg(&W4[k * DOUT + (r - 64)]);
        g_wtcomb[j] = v;
    }
}

// ----------------------------------------------------------------------------
// 24-channel GCN aggregation (8-wide main + serial tail)
// ----------------------------------------------------------------------------
__global__ void __launch_bounds__(128) agg24_kernel(const float* __restrict__ x,
                                                    float* __restrict__ xa) {
    const int warp = threadIdx.x >> 5;
    const int lane = threadIdx.x & 31;
    const int n = blockIdx.x * 4 + warp;
    const float dn = g_dinv[n];
    const int s0 = g_rowptr[n], s1 = g_rowptr[n + 1];
    float acc = (lane < DIN) ? x[n * DIN + lane] * dn * dn : 0.f;
    int j = s0;
    for (; j + 8 <= s1; j += 8) {
        int2 e[8];
        float v[8];
#pragma unroll
        for (int q = 0; q < 8; q++) e[q] = __ldg(&g_epack[j + q]);
#pragma unroll
        for (int q = 0; q < 8; q++)
            v[q] = (lane < DIN) ? __ldg(&x[e[q].x * DIN + lane]) : 0.f;
#pragma unroll
        for (int q = 0; q < 8; q++) acc += __int_as_float(e[q].y) * v[q];
    }
    for (; j < s1; j++) {
        int2 e = __ldg(&g_epack[j]);
        if (lane < DIN) acc += __int_as_float(e.y) * __ldg(&x[e.x * DIN + lane]);
    }
    if (lane < DIN) xa[n * DIN + lane] = acc;
}

// ----------------------------------------------------------------------------
// TF32 mma.sync GEMM. In-kernel BN finalize from bucketed partials.
// ----------------------------------------------------------------------------
template<int NC, bool ADD, bool WRITEX, bool ATT, bool COMBO>
__global__ void __launch_bounds__(256) mma_gemm(const float* __restrict__ Araw,
                                                const float* __restrict__ addp,
                                                float* __restrict__ xout,
                                                const float* __restrict__ Bt,
                                                const float* __restrict__ bias,
                                                float* __restrict__ out,
                                                float* __restrict__ out2,
                                                const float* __restrict__ att_s,
                                                const float* __restrict__ att_d,
                                                const float* __restrict__ bnp,
                                                const float* __restrict__ bng,
                                                const float* __restrict__ bnbe,
                                                const float* __restrict__ Gw2,
                                                const float* __restrict__ Gb2,
                                                const float* __restrict__ Ws,
                                                const float* __restrict__ bs,
                                                const float* __restrict__ xfull) {
    extern __shared__ float smf[];
    float* sSC = smf;
    float* sSH = smf + 128;
    uint32_t* sW = (uint32_t*)(smf + 256);   // [NC][132]
    float* sG = smf + 256 + NC * 132;        // [64*12] (COMBO only)
    const int tid = threadIdx.x, wid = tid >> 5, lane = tid & 31;
    const int n0 = blockIdx.x * 128;

    if (tid < 128) {
        float s = 0.f, s2 = 0.f;
#pragma unroll 8
        for (int b = 0; b < 64; b++) {
            s += __ldg(&bnp[b * 256 + tid]);
            s2 += __ldg(&bnp[b * 256 + tid + 128]);
        }
        float mean = s * (1.0f / NN);
        float var = fmaxf(s2 * (1.0f / NN) - mean * mean, 0.f);
        float sc = rsqrtf(var + 1e-5f) * __ldg(&bng[tid]);
        sSC[tid] = sc;
        sSH[tid] = __ldg(&bnbe[tid]) - mean * sc;
    }
    for (int i = tid; i < NC * 128; i += 256) {
        int c = i >> 7, k = i & 127;
        sW[c * 132 + k] = to_tf32(__ldg(&Bt[i]));
    }
    if (COMBO) {
        for (int i = tid; i < 64 * DOUT; i += 256) sG[i] = __ldg(&Gw2[i]);
    }
    __syncthreads();

    constexpr int NCH = NC / 8;
    float acc[NCH][4];
#pragma unroll
    for (int i = 0; i < NCH; i++) {
        acc[i][0] = 0.f; acc[i][1] = 0.f; acc[i][2] = 0.f; acc[i][3] = 0.f;
    }

    const int r0 = n0 + wid * 16 + (lane >> 2);
    const int r1 = r0 + 8;
    const bool v0 = r0 < NN, v1 = r1 < NN;
    const int kq = lane & 3;
    const int nq = lane >> 2;

#pragma unroll 4
    for (int k8 = 0; k8 < 128; k8 += 8) {
        int ka = k8 + kq, kb = k8 + kq + 4;
        float f0 = 0.f, f1 = 0.f, f2 = 0.f, f3 = 0.f;
        if (v0) {
            f0 = fmaxf(__ldg(&Araw[(size_t)r0 * 128 + ka]) * sSC[ka] + sSH[ka], 0.f);
            f2 = fmaxf(__ldg(&Araw[(size_t)r0 * 128 + kb]) * sSC[kb] + sSH[kb], 0.f);
            if (ADD) {
                f0 += __ldg(&addp[(size_t)r0 * 128 + ka]);
                f2 += __ldg(&addp[(size_t)r0 * 128 + kb]);
            }
            if (WRITEX) {
                xout[(size_t)r0 * 128 + ka] = f0;
                xout[(size_t)r0 * 128 + kb] = f2;
            }
        }
        if (v1) {
            f1 = fmaxf(__ldg(&Araw[(size_t)r1 * 128 + ka]) * sSC[ka] + sSH[ka], 0.f);
            f3 = fmaxf(__ldg(&Araw[(size_t)r1 * 128 + kb]) * sSC[kb] + sSH[kb], 0.f);
            if (ADD) {
                f1 += __ldg(&addp[(size_t)r1 * 128 + ka]);
                f3 += __ldg(&addp[(size_t)r1 * 128 + kb]);
            }
            if (WRITEX) {
                xout[(size_t)r1 * 128 + ka] = f1;
                xout[(size_t)r1 * 128 + kb] = f3;
            }
        }
        uint32_t a0 = to_tf32(f0), a1 = to_tf32(f1), a2 = to_tf32(f2), a3 = to_tf32(f3);
#pragma unroll
        for (int nc = 0; nc < NCH; nc++) {
            uint32_t b0 = sW[(nc * 8 + nq) * 132 + ka];
            uint32_t b1 = sW[(nc * 8 + nq) * 132 + kb];
            asm volatile(
                "mma.sync.aligned.m16n8k8.row.col.f32.tf32.tf32.f32 "
                "{%0,%1,%2,%3}, {%4,%5,%6,%7}, {%8,%9}, {%0,%1,%2,%3};"
                : "+f"(acc[nc][0]), "+f"(acc[nc][1]), "+f"(acc[nc][2]), "+f"(acc[nc][3])
                : "r"(a0), "r"(a1), "r"(a2), "r"(a3), "r"(b0), "r"(b1));
        }
    }

    const int colb = 2 * kq;
    if (COMBO) {
        float z0[DOUT], z1[DOUT];
#pragma unroll
        for (int c = 0; c < DOUT; c++) { z0[c] = 0.f; z1[c] = 0.f; }
#pragma unroll
        for (int nc = 0; nc < NCH; nc++) {
            int col = nc * 8 + colb;
            if (col < 64) {
                float bx = __ldg(&bias[col]), by = __ldg(&bias[col + 1]);
                float t0a = fmaxf(acc[nc][0] + bx, 0.f), t0b = fmaxf(acc[nc][1] + by, 0.f);
                float t1a = fmaxf(acc[nc][2] + bx, 0.f), t1b = fmaxf(acc[nc][3] + by, 0.f);
#pragma unroll
                for (int c = 0; c < DOUT; c++) {
                    float w0 = sG[col * DOUT + c], w1 = sG[(col + 1) * DOUT + c];
                    z0[c] += t0a * w0 + t0b * w1;
                    z1[c] += t1a * w0 + t1b * w1;
                }
            } else if (col < 76) {
                int c2 = col - 64;
                if (v0) *(float2*)&out2[(size_t)r0 * DOUT + c2] =
                            make_float2(acc[nc][0], acc[nc][1]);
                if (v1) *(float2*)&out2[(size_t)r1 * DOUT + c2] =
                            make_float2(acc[nc][2], acc[nc][3]);
            }
        }
#pragma unroll
        for (int c = 0; c < DOUT; c++) {
            z0[c] += __shfl_xor_sync(0xffffffffu, z0[c], 1);
            z0[c] += __shfl_xor_sync(0xffffffffu, z0[c], 2);
            z1[c] += __shfl_xor_sync(0xffffffffu, z1[c], 1);
            z1[c] += __shfl_xor_sync(0xffffffffu, z1[c], 2);
        }
        if (kq == 0) {
            if (v0) {
                float status = __ldg(&xfull[(size_t)r0 * DIN + 12]);
                float flag = status < 0.5f ? 2.5f : 0.f;
#pragma unroll
                for (int c = 0; c < DOUT; c++) {
                    float gate = 1.f / (1.f + expf(-(z0[c] + __ldg(&Gb2[c]))));
                    float sig = (1.f - status) * __ldg(&Ws[c]) + __ldg(&bs[c]);
                    out[(size_t)r0 * DOUT + c] = flag * gate * sig;
                }
            }
            if (v1) {
                float status = __ldg(&xfull[(size_t)r1 * DIN + 12]);
                float flag = status < 0.5f ? 2.5f : 0.f;
#pragma unroll
                for (int c = 0; c < DOUT; c++) {
                    float gate = 1.f / (1.f + expf(-(z1[c] + __ldg(&Gb2[c]))));
                    float sig = (1.f - status) * __ldg(&Ws[c]) + __ldg(&bs[c]);
                    out[(size_t)r1 * DOUT + c] = flag * gate * sig;
                }
            }
        }
    } else {
#pragma unroll
        for (int nc = 0; nc < NCH; nc++) {
            int col = nc * 8 + colb;
            if (v0) *(float2*)&out[(size_t)r0 * NC + col] =
                        make_float2(acc[nc][0], acc[nc][1]);
            if (v1) *(float2*)&out[(size_t)r1 * NC + col] =
                        make_float2(acc[nc][2], acc[nc][3]);
        }
    }

    if (ATT) {
        float as0[4] = {}, ad0[4] = {}, as1[4] = {}, ad1[4] = {};
#pragma unroll
        for (int nc = 0; nc < NCH; nc++) {
            int col = nc * 8 + colb;
            float sx = __ldg(&att_s[col]), sy = __ldg(&att_s[col + 1]);
            float dx = __ldg(&att_d[col]), dy = __ldg(&att_d[col + 1]);
            int h = nc >> 2;
            as0[h] += acc[nc][0] * sx + acc[nc][1] * sy;
            ad0[h] += acc[nc][0] * dx + acc[nc][1] * dy;
            as1[h] += acc[nc][2] * sx + acc[nc][3] * sy;
            ad1[h] += acc[nc][2] * dx + acc[nc][3] * dy;
        }
#pragma unroll
        for (int h = 0; h < 4; h++) {
#pragma unroll
            for (int off = 1; off <= 2; off <<= 1) {
                as0[h] += __shfl_xor_sync(0xffffffffu, as0[h], off);
                ad0[h] += __shfl_xor_sync(0xffffffffu, ad0[h], off);
                as1[h] += __shfl_xor_sync(0xffffffffu, as1[h], off);
                ad1[h] += __shfl_xor_sync(0xffffffffu, ad1[h], off);
            }
        }
        if (kq == 0) {
#pragma unroll
            for (int h = 0; h < 4; h++) {
                if (v0) { g_as[r0 * 4 + h] = as0[h]; g_ad[r0 * 4 + h] = ad0[h]; }
                if (v1) { g_as[r1 * 4 + h] = as1[h]; g_ad[r1 * 4 + h] = ad1[h]; }
            }
        }
    }
}

// ----------------------------------------------------------------------------
// Fused input GEMM: agg1 = xa@W1 + b1, xin = x@Wi + bi, + fused BN1 partials
// ----------------------------------------------------------------------------
__global__ void __launch_bounds__(128) gemm_in_kernel(
        const float* __restrict__ XA, const float* __restrict__ X,
        const float* __restrict__ W1, const float* __restrict__ b1,
        const float* __restrict__ Wi, const float* __restrict__ bi,
        float* __restrict__ h1, float* __restrict__ xin) {
    __shared__ float sS[4][128], sQ[4][128];
    const int tid = threadIdx.x;
    const int cg = tid & 31;
    const int rg = tid >> 5;
    const int n0 = blockIdx.x * 16 + rg * 4;
    float a1[4][4] = {}; float ai[4][4] = {};
    const float4* W1v = (const float4*)W1;
    const float4* Wiv = (const float4*)Wi;
#pragma unroll
    for (int k = 0; k < DIN; k++) {
        float4 w1 = __ldg(&W1v[k * 32 + cg]);
        float4 wi = __ldg(&Wiv[k * 32 + cg]);
#pragma unroll
        for (int r = 0; r < 4; r++) {
            float xav = __ldg(&XA[(n0 + r) * DIN + k]);
            float xv  = __ldg(&X[(n0 + r) * DIN + k]);
            a1[r][0] += xav * w1.x; a1[r][1] += xav * w1.y; a1[r][2] += xav * w1.z; a1[r][3] += xav * w1.w;
            ai[r][0] += xv * wi.x;  ai[r][1] += xv * wi.y;  ai[r][2] += xv * wi.z;  ai[r][3] += xv * wi.w;
        }
    }
    const int c0 = cg * 4;
    float4 b1v = __ldg(&((const float4*)b1)[cg]);
    float4 biv = __ldg(&((const float4*)bi)[cg]);
    float s4[4] = {}, q4[4] = {};
#pragma unroll
    for (int r = 0; r < 4; r++) {
        float4 v1, vi;
        v1.x = a1[r][0] + b1v.x; v1.y = a1[r][1] + b1v.y;
        v1.z = a1[r][2] + b1v.z; v1.w = a1[r][3] + b1v.w;
        vi.x = ai[r][0] + biv.x; vi.y = ai[r][1] + biv.y;
        vi.z = ai[r][2] + biv.z; vi.w = ai[r][3] + biv.w;
        s4[0] += v1.x; q4[0] += v1.x * v1.x;
        s4[1] += v1.y; q4[1] += v1.y * v1.y;
        s4[2] += v1.z; q4[2] += v1.z * v1.z;
        s4[3] += v1.w; q4[3] += v1.w * v1.w;
        *(float4*)&h1[(n0 + r) * HH + c0] = v1;
        *(float4*)&xin[(n0 + r) * HH + c0] = vi;
    }
#pragma unroll
    for (int i = 0; i < 4; i++) { sS[rg][c0 + i] = s4[i]; sQ[rg][c0 + i] = q4[i]; }
    __syncthreads();
    const int b = blockIdx.x & 63;
    float ts = sS[0][tid] + sS[1][tid] + sS[2][tid] + sS[3][tid];
    float tq = sQ[0][tid] + sQ[1][tid] + sQ[2][tid] + sQ[3][tid];
    atomicAdd(&g_bnpart[0][b][tid], ts);
    atomicAdd(&g_bnpart[0][b][tid + 128], tq);
}

// ----------------------------------------------------------------------------
// GCN aggregation (128 ch, warp/node, 8-wide main + 2-wide tail) + BN3 partials
// ----------------------------------------------------------------------------
__global__ void __launch_bounds__(128) gcn_agg128(const float* __restrict__ in,
                                                  const float* __restrict__ bias,
                                                  float* __restrict__ out) {
    __shared__ float sS[4][128], sQ[4][128];
    const int warp = threadIdx.x >> 5;
    const int lane = threadIdx.x & 31;
    const int n = blockIdx.x * 4 + warp;
    const float dn = g_dinv[n];
    const int s0 = g_rowptr[n], s1 = g_rowptr[n + 1];
    const float4* in4 = (const float4*)in;
    float4 acc = __ldg(&in4[n * 32 + lane]);
    float dn2 = dn * dn;
    acc.x *= dn2; acc.y *= dn2; acc.z *= dn2; acc.w *= dn2;
    int j = s0;
    for (; j + 8 <= s1; j += 8) {
        int2 e[8];
        float4 v[8];
#pragma unroll
        for (int q = 0; q < 8; q++) e[q] = __ldg(&g_epack[j + q]);
#pragma unroll
        for (int q = 0; q < 8; q++) v[q] = __ldg(&in4[e[q].x * 32 + lane]);
#pragma unroll
        for (int q = 0; q < 8; q++) {
            float c = __int_as_float(e[q].y);
            acc.x += c * v[q].x; acc.y += c * v[q].y;
            acc.z += c * v[q].z; acc.w += c * v[q].w;
        }
    }
    for (; j + 2 <= s1; j += 2) {
        int2 eA = __ldg(&g_epack[j]);
        int2 eB = __ldg(&g_epack[j + 1]);
        float4 vA = __ldg(&in4[eA.x * 32 + lane]);
        float4 vB = __ldg(&in4[eB.x * 32 + lane]);
        float cA = __int_as_float(eA.y), cB = __int_as_float(eB.y);
        acc.x += cA * vA.x + cB * vB.x;
        acc.y += cA * vA.y + cB * vB.y;
        acc.z += cA * vA.z + cB * vB.z;
        acc.w += cA * vA.w + cB * vB.w;
    }
    if (j < s1) {
        int2 e = __ldg(&g_epack[j]);
        float4 v = __ldg(&in4[e.x * 32 + lane]);
        float c = __int_as_float(e.y);
        acc.x += c * v.x; acc.y += c * v.y; acc.z += c * v.z; acc.w += c * v.w;
    }
    float4 bv = __ldg(&((const float4*)bias)[lane]);
    acc.x += bv.x; acc.y += bv.y; acc.z += bv.z; acc.w += bv.w;
    ((float4*)out)[n * 32 + lane] = acc;
    sS[warp][lane * 4 + 0] = acc.x; sQ[warp][lane * 4 + 0] = acc.x * acc.x;
    sS[warp][lane * 4 + 1] = acc.y; sQ[warp][lane * 4 + 1] = acc.y * acc.y;
    sS[warp][lane * 4 + 2] = acc.z; sQ[warp][lane * 4 + 2] = acc.z * acc.z;
    sS[warp][lane * 4 + 3] = acc.w; sQ[warp][lane * 4 + 3] = acc.w * acc.w;
    __syncthreads();
    const int tid = threadIdx.x;
    const int b = blockIdx.x & 63;
    float ts = sS[0][tid] + sS[1][tid] + sS[2][tid] + sS[3][tid];
    float tq = sQ[0][tid] + sQ[1][tid] + sQ[2][tid] + sQ[3][tid];
    atomicAdd(&g_bnpart[2][b][tid], ts);
    atomicAdd(&g_bnpart[2][b][tid + 128], tq);
}

// ----------------------------------------------------------------------------
// GAT aggregation: single pass, 8-wide main + 2-wide tail + BN2 partials
// ----------------------------------------------------------------------------
__global__ void __launch_bounds__(256) gat_agg_kernel(const float* __restrict__ hg,
                                                      const float* __restrict__ bg,
                                                      float* __restrict__ out) {
    __shared__ float sS[8][128], sQ[8][128];
    const int w = threadIdx.x >> 5;
    const int lane = threadIdx.x & 31;
    const int n = blockIdx.x * 8 + w;
    const int s0 = g_rowptr[n], s1 = g_rowptr[n + 1];
    const int h = lane >> 3;
    const int eq = lane & 7;
    const float4* ad4 = (const float4*)g_ad;
    const float4* as4 = (const float4*)g_as;

    float4 adv = __ldg(&ad4[n]);
    float4 asv = __ldg(&as4[n]);
    float adh = h < 2 ? (h == 0 ? adv.x : adv.y) : (h == 2 ? adv.z : adv.w);
    float ash = h < 2 ? (h == 0 ? asv.x : asv.y) : (h == 2 ? asv.z : asv.w);
    float xs = expf(lrelu(ash + adh));

    const float4* hg4 = (const float4*)hg;
    float4 acc = make_float4(0.f, 0.f, 0.f, 0.f);
    float tsum = 0.f;

    int j = s0;
    for (; j + 8 <= s1; j += 8) {
        int2 e[8];
#pragma unroll
        for (int q = 0; q < 8; q++) e[q] = __ldg(&g_epack[j + q]);
        float myx = expf(lrelu(__ldg(&g_as[e[eq].x * 4 + h]) + adh));
        tsum += myx;
        float4 v[8];
#pragma unroll
        for (int q = 0; q < 8; q++) v[q] = __ldg(&hg4[e[q].x * 32 + lane]);
#pragma unroll
        for (int q = 0; q < 8; q++) {
            float a = __shfl_sync(0xffffffffu, myx, h * 8 + q);
            acc.x += a * v[q].x; acc.y += a * v[q].y;
            acc.z += a * v[q].z; acc.w += a * v[q].w;
        }
    }
    for (; j + 2 <= s1; j += 2) {
        int2 eA = __ldg(&g_epack[j]);
        int2 eB = __ldg(&g_epack[j + 1]);
        float aA = expf(lrelu(__ldg(&g_as[eA.x * 4 + h]) + adh));
        float aB = expf(lrelu(__ldg(&g_as[eB.x * 4 + h]) + adh));
        if (eq == 0) tsum += aA + aB;
        float4 vA = __ldg(&hg4[eA.x * 32 + lane]);
        float4 vB = __ldg(&hg4[eB.x * 32 + lane]);
        acc.x += aA * vA.x + aB * vB.x;
        acc.y += aA * vA.y + aB * vB.y;
        acc.z += aA * vA.z + aB * vB.z;
        acc.w += aA * vA.w + aB * vB.w;
    }
    if (j < s1) {
        int2 e = __ldg(&g_epack[j]);
        float a = expf(lrelu(__ldg(&g_as[e.x * 4 + h]) + adh));
        if (eq == 0) tsum += a;
        float4 v = __ldg(&hg4[e.x * 32 + lane]);
        acc.x += a * v.x; acc.y += a * v.y; acc.z += a * v.z; acc.w += a * v.w;
    }
#pragma unroll
    for (int off = 1; off <= 4; off <<= 1)
        tsum += __shfl_xor_sync(0xffffffffu, tsum, off);
    float inv = 1.f / (tsum + xs);

    float4 self = __ldg(&hg4[n * 32 + lane]);
    float4 bv = __ldg(&((const float4*)bg)[lane]);
    float4 o;
    o.x = (acc.x + xs * self.x) * inv + bv.x;
    o.y = (acc.y + xs * self.y) * inv + bv.y;
    o.z = (acc.z + xs * self.z) * inv + bv.z;
    o.w = (acc.w + xs * self.w) * inv + bv.w;
    ((float4*)out)[n * 32 + lane] = o;
    sS[w][lane * 4 + 0] = o.x; sQ[w][lane * 4 + 0] = o.x * o.x;
    sS[w][lane * 4 + 1] = o.y; sQ[w][lane * 4 + 1] = o.y * o.y;
    sS[w][lane * 4 + 2] = o.z; sQ[w][lane * 4 + 2] = o.z * o.z;
    sS[w][lane * 4 + 3] = o.w; sQ[w][lane * 4 + 3] = o.w * o.w;
    __syncthreads();
    const int tid = threadIdx.x;
    if (tid < 128) {
        const int b = blockIdx.x & 63;
        float ts = 0.f, tq = 0.f;
#pragma unroll
        for (int ww = 0; ww < 8; ww++) { ts += sS[ww][tid]; tq += sQ[ww][tid]; }
        atomicAdd(&g_bnpart[1][b][tid], ts);
        atomicAdd(&g_bnpart[1][b][tid + 128], tq);
    }
}

// ----------------------------------------------------------------------------
// Output: GCN aggregation of h4 (12 ch, 8-wide main + serial tail) + gate add
// ----------------------------------------------------------------------------
__global__ void __launch_bounds__(128) out_kernel(
        const float* __restrict__ h4, const float* __restrict__ b4,
        const float* __restrict__ gc, float* __restrict__ out) {
    const int warp = threadIdx.x >> 5;
    const int lane = threadIdx.x & 31;
    const int n = blockIdx.x * 4 + warp;
    const float dn = g_dinv[n];
    const int s0 = g_rowptr[n], s1 = g_rowptr[n + 1];
    float acc = (lane < DOUT) ? h4[n * DOUT + lane] * dn * dn : 0.f;
    int j = s0;
    for (; j + 8 <= s1; j += 8) {
        int2 e[8];
        float v[8];
#pragma unroll
        for (int q = 0; q < 8; q++) e[q] = __ldg(&g_epack[j + q]);
#pragma unroll
        for (int q = 0; q < 8; q++)
            v[q] = (lane < DOUT) ? __ldg(&h4[e[q].x * DOUT + lane]) : 0.f;
#pragma unroll
        for (int q = 0; q < 8; q++) acc += __int_as_float(e[q].y) * v[q];
    }
    for (; j < s1; j++) {
        int2 e = __ldg(&g_epack[j]);
        if (lane < DOUT) acc += __int_as_float(e.y) * __ldg(&h4[e.x * DOUT + lane]);
    }
    if (lane < DOUT)
        out[n * DOUT + lane] = acc + __ldg(&b4[lane]) + __ldg(&gc[n * DOUT + lane]);
}

// ----------------------------------------------------------------------------
// Launch
// ----------------------------------------------------------------------------
extern "C" void kernel_launch(void* const* d_in, const int* in_sizes, int n_in,
                              void* d_out, int out_size) {
    const float* x   = (const float*)d_in[0];
    const int*   ei  = (const int*)d_in[1];
    const float* ew  = (const float*)d_in[2];
    const float* W1  = (const float*)d_in[3];
    const float* b1  = (const float*)d_in[4];
    const float* g1  = (const float*)d_in[5];
    const float* be1 = (const float*)d_in[6];
    const float* Wg  = (const float*)d_in[7];
    const float* atts= (const float*)d_in[8];
    const float* attd= (const float*)d_in[9];
    const float* bg  = (const float*)d_in[10];
    const float* g2  = (const float*)d_in[11];
    const float* be2 = (const float*)d_in[12];
    const float* W3  = (const float*)d_in[13];
    const float* b3  = (const float*)d_in[14];
    const float* g3  = (const float*)d_in[15];
    const float* be3 = (const float*)d_in[16];
    const float* W4  = (const float*)d_in[17];
    const float* b4  = (const float*)d_in[18];
    const float* Wi  = (const float*)d_in[19];
    const float* bi  = (const float*)d_in[20];
    const float* Gw1 = (const float*)d_in[21];
    const float* Gb1 = (const float*)d_in[22];
    const float* Gw2 = (const float*)d_in[23];
    const float* Gb2 = (const float*)d_in[24];
    const float* Ws  = (const float*)d_in[25];
    const float* bs  = (const float*)d_in[26];
    float* out = (float*)d_out;
    const int* src = ei;
    const int* dst = ei + EE;

    float *p_h1, *p_agg, *p_x1, *p_xin, *p_hg, *p_xa, *p_h4, *p_gc;
    float *p_wtg, *p_wt3, *p_wtcomb, *p_bn;
    cudaGetSymbolAddress((void**)&p_h1, g_h1);
    cudaGetSymbolAddress((void**)&p_agg, g_agg);
    cudaGetSymbolAddress((void**)&p_x1, g_x1);
    cudaGetSymbolAddress((void**)&p_xin, g_xin);
    cudaGetSymbolAddress((void**)&p_hg, g_hg);
    cudaGetSymbolAddress((void**)&p_xa, g_xa);
    cudaGetSymbolAddress((void**)&p_h4, g_h4);
    cudaGetSymbolAddress((void**)&p_gc, g_gc);
    cudaGetSymbolAddress((void**)&p_wtg, g_wtg);
    cudaGetSymbolAddress((void**)&p_wt3, g_wt3);
    cudaGetSymbolAddress((void**)&p_wtcomb, g_wtcomb);
    cudaGetSymbolAddress((void**)&p_bn, g_bnpart);

    const int SMEM128 = 1024 + 128 * 132 * 4;                 // 68608
    const int SMEM80  = 1024 + 80 * 132 * 4 + 64 * DOUT * 4;  // 46336
    cudaFuncSetAttribute(mma_gemm<128, false, true, true, false>,
                         cudaFuncAttributeMaxDynamicSharedMemorySize, SMEM128);
    cudaFuncSetAttribute(mma_gemm<128, true, false, false, false>,
                         cudaFuncAttributeMaxDynamicSharedMemorySize, SMEM128);
    cudaFuncSetAttribute(mma_gemm<80, true, false, false, true>,
                         cudaFuncAttributeMaxDynamicSharedMemorySize, SMEM80);
    const int MGRID = (NN + 127) / 128;   // 782

    // graph preprocessing + weight prep
    init_kernel<<<(NN + 255) / 256, 256>>>();
    count_kernel<<<(EE + 255) / 256, 256>>>(dst, ew);
    part_kernel<<<NB, 256>>>();
    writerow_kernel<<<NB, 256>>>();
    fill_kernel<<<(EE + 255) / 256, 256>>>(src, dst, ew);
    prep_weights_kernel<<<168, 256>>>(Wg, W3, Gw1, W4);

    // layer 1
    agg24_kernel<<<NN / 4, 128>>>(x, p_xa);
    gemm_in_kernel<<<NN / 16, 128>>>(p_xa, x, W1, b1, Wi, bi, p_agg, p_xin);

    // GAT: Wg GEMM (in-kernel BN1 finalize) + side-write x1 + att reduce
    mma_gemm<128, false, true, true, false><<<MGRID, 256, SMEM128>>>(
        p_agg, nullptr, p_x1, p_wtg, nullptr, p_hg, nullptr, atts, attd,
        p_bn + 0 * 64 * 256, g1, be1, nullptr, nullptr, nullptr, nullptr, nullptr);
    gat_agg_kernel<<<NN / 8, 256>>>(p_hg, bg, p_agg);

    // layer 3: W3 GEMM (in-kernel BN2 finalize) + xin residual
    mma_gemm<128, true, false, false, false><<<MGRID, 256, SMEM128>>>(
        p_agg, p_xin, nullptr, p_wt3, nullptr, p_h1, nullptr, nullptr, nullptr,
        p_bn + 1 * 64 * 256, g2, be2, nullptr, nullptr, nullptr, nullptr, nullptr);
    gcn_agg128<<<NN / 4, 128>>>(p_h1, b3, p_agg);

    // output: combo GEMM (in-kernel BN3 finalize) + x1 residual + fused gate
    mma_gemm<80, true, false, false, true><<<MGRID, 256, SMEM80>>>(
        p_agg, p_x1, nullptr, p_wtcomb, Gb1, p_gc, p_h4, nullptr, nullptr,
        p_bn + 2 * 64 * 256, g3, be3, Gw2, Gb2, Ws, bs, x);
    out_kernel<<<NN / 4, 128>>>(p_h4, b4, p_gc, out);
}

// round 15
// speedup vs baseline: 1.0458x; 1.0214x over previous
#include <cuda_runtime.h>
#include <math.h>
#include <stdint.h>

#define NN 100000
#define EE 1600000
#define DIN 24
#define HH 128
#define DOUT 12
#define HEADS 4
#define NB 391   // ceil(NN/256)
#define NBUK 32  // BN partial buckets

// ----------------------------------------------------------------------------
// Scratch (device globals; no dynamic allocation allowed)
// ----------------------------------------------------------------------------
__device__ float g_h1[NN * HH];      // h3 = x2@W3
__device__ float g_agg[NN * HH];     // raw pre-BN activations per layer
__device__ float g_x1[NN * HH];      // x1 (side-written by Wg GEMM)
__device__ float g_xin[NN * HH];     // x_in_proj
__device__ float g_hg[NN * HH];      // hg
__device__ float g_xa[NN * DIN];     // 24-dim aggregated x
__device__ float g_h4[NN * DOUT];
__device__ float g_gc[NN * DOUT];    // gate contribution per node
__device__ float g_as[NN * HEADS];
__device__ float g_ad[NN * HEADS];
__device__ float g_deg[NN];
__device__ float g_dinv[NN];
__device__ int   g_cnt[NN];
__device__ int   g_cur[NN];
__device__ int   g_rowptr[NN + 1];
__device__ int2  g_epack[EE];
__device__ int   g_part[512];
__device__ float g_bnpart[3][NBUK][256];  // per-layer bucketed BN partials
__device__ float g_wtg[HH * HH];     // Wg^T  [128,128] K-major
__device__ float g_wt3[HH * HH];     // W3^T
__device__ float g_wtcomb[80 * HH];  // [Gw1^T ; W4^T ; pad]

__device__ __forceinline__ float lrelu(float v) { return v > 0.f ? v : 0.2f * v; }
__device__ __forceinline__ uint32_t to_tf32(float f) {
    uint32_t t;
    asm("cvt.rna.tf32.f32 %0, %1;" : "=r"(t) : "f"(f));
    return t;
}

// ----------------------------------------------------------------------------
// Graph preprocessing
// ----------------------------------------------------------------------------
__global__ void __launch_bounds__(256) init_kernel() {
    int i = blockIdx.x * blockDim.x + threadIdx.x;
    if (i < NN) { g_deg[i] = 1.0f; g_cnt[i] = 0; g_cur[i] = 0; }
    if (i < 3 * NBUK * 256) ((float*)g_bnpart)[i] = 0.f;
}

__global__ void __launch_bounds__(256) count_kernel(const int* __restrict__ dst,
                                                    const float* __restrict__ w) {
    int e = blockIdx.x * blockDim.x + threadIdx.x;
    if (e < EE) {
        int d = dst[e];
        atomicAdd(&g_deg[d], w[e]);
        atomicAdd(&g_cnt[d], 1);
    }
}

__global__ void __launch_bounds__(256) part_kernel() {
    __shared__ int sw[8];
    int i = blockIdx.x * 256 + threadIdx.x;
    if (i < NN) g_dinv[i] = rsqrtf(g_deg[i]);
    int v = (i < NN) ? g_cnt[i] : 0;
#pragma unroll
    for (int off = 16; off; off >>= 1) v += __shfl_down_sync(0xffffffffu, v, off);
    if ((threadIdx.x & 31) == 0) sw[threadIdx.x >> 5] = v;
    __syncthreads();
    if (threadIdx.x == 0) {
        int s = 0;
#pragma unroll
        for (int k = 0; k < 8; k++) s += sw[k];
        g_part[blockIdx.x] = s;
    }
}

__global__ void __launch_bounds__(256) writerow_kernel() {
    __shared__ int sp[256];
    __shared__ int swr[8];
    __shared__ int soff;
    const int t = threadIdx.x;
    const int i = blockIdx.x * 256 + t;
    int pre = 0;
    for (int b = t; b < blockIdx.x; b += 256) pre += g_part[b];
#pragma unroll
    for (int off = 16; off; off >>= 1) pre += __shfl_down_sync(0xffffffffu, pre, off);
    if ((t & 31) == 0) swr[t >> 5] = pre;
    __syncthreads();
    if (t == 0) {
        int s = 0;
#pragma unroll
        for (int k = 0; k < 8; k++) s += swr[k];
        soff = s;
    }
    int v = (i < NN) ? g_cnt[i] : 0;
    sp[t] = v;
    __syncthreads();
    for (int off = 1; off < 256; off <<= 1) {
        int a = (t >= off) ? sp[t - off] : 0;
        __syncthreads();
        sp[t] += a;
        __syncthreads();
    }
    if (i < NN) g_rowptr[i] = sp[t] - v + soff;
    if (i == 0) g_rowptr[NN] = EE;
}

__global__ void __launch_bounds__(256) fill_kernel(const int* __restrict__ src,
                                                   const int* __restrict__ dst,
                                                   const float* __restrict__ w) {
    int e = blockIdx.x * blockDim.x + threadIdx.x;
    if (e < EE) {
        int d = dst[e];
        int s = src[e];
        int pos = g_rowptr[d] + atomicAdd(&g_cur[d], 1);
        float coef = w[e] * __ldg(&g_dinv[s]) * __ldg(&g_dinv[d]);
        g_epack[pos] = make_int2(s, __float_as_int(coef));
    }
}

__global__ void __launch_bounds__(256) prep_weights_kernel(const float* __restrict__ Wg,
                                                           const float* __restrict__ W3,
                                                           const float* __restrict__ Gw1,
                                                           const float* __restrict__ W4) {
    int idx = blockIdx.x * 256 + threadIdx.x;
    if (idx < 16384) {
        int k = idx >> 7, c = idx & 127;
        g_wtg[c * 128 + k] = __ldg(&Wg[idx]);
    } else if (idx < 32768) {
        int j = idx - 16384;
        int k = j >> 7, c = j & 127;
        g_wt3[c * 128 + k] = __ldg(&W3[j]);
    } else if (idx < 43008) {
        int j = idx - 32768;
        int r = j >> 7, k = j & 127;
        float v = 0.f;
        if (r < 64) v = __ldg(&Gw1[k * 64 + r]);
        else if (r < 76) v = __ldg(&W4[k * DOUT + (r - 64)]);
        g_wtcomb[j] = v;
    }
}

// ----------------------------------------------------------------------------
// 24-channel GCN aggregation (8-wide main + serial tail)
// ----------------------------------------------------------------------------
__global__ void __launch_bounds__(128) agg24_kernel(const float* __restrict__ x,
                                                    float* __restrict__ xa) {
    const int warp = threadIdx.x >> 5;
    const int lane = threadIdx.x & 31;
    const int n = blockIdx.x * 4 + warp;
    const float dn = g_dinv[n];
    const int s0 = g_rowptr[n], s1 = g_rowptr[n + 1];
    float acc = (lane < DIN) ? x[n * DIN + lane] * dn * dn : 0.f;
    int j = s0;
    for (; j + 8 <= s1; j += 8) {
        int2 e[8];
        float v[8];
#pragma unroll
        for (int q = 0; q < 8; q++) e[q] = __ldg(&g_epack[j + q]);
#pragma unroll
        for (int q = 0; q < 8; q++)
            v[q] = (lane < DIN) ? __ldg(&x[e[q].x * DIN + lane]) : 0.f;
#pragma unroll
        for (int q = 0; q < 8; q++) acc += __int_as_float(e[q].y) * v[q];
    }
    for (; j < s1; j++) {
        int2 e = __ldg(&g_epack[j]);
        if (lane < DIN) acc += __int_as_float(e.y) * __ldg(&x[e.x * DIN + lane]);
    }
    if (lane < DIN) xa[n * DIN + lane] = acc;
}

// ----------------------------------------------------------------------------
// TF32 mma.sync GEMM. In-kernel BN finalize from bucketed partials.
// ----------------------------------------------------------------------------
template<int NC, bool ADD, bool WRITEX, bool ATT, bool COMBO>
__global__ void __launch_bounds__(256) mma_gemm(const float* __restrict__ Araw,
                                                const float* __restrict__ addp,
                                                float* __restrict__ xout,
                                                const float* __restrict__ Bt,
                                                const float* __restrict__ bias,
                                                float* __restrict__ out,
                                                float* __restrict__ out2,
                                                const float* __restrict__ att_s,
                                                const float* __restrict__ att_d,
                                                const float* __restrict__ bnp,
                                                const float* __restrict__ bng,
                                                const float* __restrict__ bnbe,
                                                const float* __restrict__ Gw2,
                                                const float* __restrict__ Gb2,
                                                const float* __restrict__ Ws,
                                                const float* __restrict__ bs,
                                                const float* __restrict__ xfull) {
    extern __shared__ float smf[];
    float* sSC = smf;
    float* sSH = smf + 128;
    uint32_t* sW = (uint32_t*)(smf + 256);   // [NC][132]
    float* sG = smf + 256 + NC * 132;        // [64*12] (COMBO only)
    const int tid = threadIdx.x, wid = tid >> 5, lane = tid & 31;
    const int n0 = blockIdx.x * 128;

    if (tid < 128) {
        float s = 0.f, s2 = 0.f;
#pragma unroll 8
        for (int b = 0; b < NBUK; b++) {
            s += __ldg(&bnp[b * 256 + tid]);
            s2 += __ldg(&bnp[b * 256 + tid + 128]);
        }
        float mean = s * (1.0f / NN);
        float var = fmaxf(s2 * (1.0f / NN) - mean * mean, 0.f);
        float sc = rsqrtf(var + 1e-5f) * __ldg(&bng[tid]);
        sSC[tid] = sc;
        sSH[tid] = __ldg(&bnbe[tid]) - mean * sc;
    }
    for (int i = tid; i < NC * 128; i += 256) {
        int c = i >> 7, k = i & 127;
        sW[c * 132 + k] = to_tf32(__ldg(&Bt[i]));
    }
    if (COMBO) {
        for (int i = tid; i < 64 * DOUT; i += 256) sG[i] = __ldg(&Gw2[i]);
    }
    __syncthreads();

    constexpr int NCH = NC / 8;
    float acc[NCH][4];
#pragma unroll
    for (int i = 0; i < NCH; i++) {
        acc[i][0] = 0.f; acc[i][1] = 0.f; acc[i][2] = 0.f; acc[i][3] = 0.f;
    }

    const int r0 = n0 + wid * 16 + (lane >> 2);
    const int r1 = r0 + 8;
    const bool v0 = r0 < NN, v1 = r1 < NN;
    const int kq = lane & 3;
    const int nq = lane >> 2;

#pragma unroll 4
    for (int k8 = 0; k8 < 128; k8 += 8) {
        int ka = k8 + kq, kb = k8 + kq + 4;
        float f0 = 0.f, f1 = 0.f, f2 = 0.f, f3 = 0.f;
        if (v0) {
            f0 = fmaxf(__ldg(&Araw[(size_t)r0 * 128 + ka]) * sSC[ka] + sSH[ka], 0.f);
            f2 = fmaxf(__ldg(&Araw[(size_t)r0 * 128 + kb]) * sSC[kb] + sSH[kb], 0.f);
            if (ADD) {
                f0 += __ldg(&addp[(size_t)r0 * 128 + ka]);
                f2 += __ldg(&addp[(size_t)r0 * 128 + kb]);
            }
            if (WRITEX) {
                xout[(size_t)r0 * 128 + ka] = f0;
                xout[(size_t)r0 * 128 + kb] = f2;
            }
        }
        if (v1) {
            f1 = fmaxf(__ldg(&Araw[(size_t)r1 * 128 + ka]) * sSC[ka] + sSH[ka], 0.f);
            f3 = fmaxf(__ldg(&Araw[(size_t)r1 * 128 + kb]) * sSC[kb] + sSH[kb], 0.f);
            if (ADD) {
                f1 += __ldg(&addp[(size_t)r1 * 128 + ka]);
                f3 += __ldg(&addp[(size_t)r1 * 128 + kb]);
            }
            if (WRITEX) {
                xout[(size_t)r1 * 128 + ka] = f1;
                xout[(size_t)r1 * 128 + kb] = f3;
            }
        }
        uint32_t a0 = to_tf32(f0), a1 = to_tf32(f1), a2 = to_tf32(f2), a3 = to_tf32(f3);
#pragma unroll
        for (int nc = 0; nc < NCH; nc++) {
            uint32_t b0 = sW[(nc * 8 + nq) * 132 + ka];
            uint32_t b1 = sW[(nc * 8 + nq) * 132 + kb];
            asm volatile(
                "mma.sync.aligned.m16n8k8.row.col.f32.tf32.tf32.f32 "
                "{%0,%1,%2,%3}, {%4,%5,%6,%7}, {%8,%9}, {%0,%1,%2,%3};"
                : "+f"(acc[nc][0]), "+f"(acc[nc][1]), "+f"(acc[nc][2]), "+f"(acc[nc][3])
                : "r"(a0), "r"(a1), "r"(a2), "r"(a3), "r"(b0), "r"(b1));
        }
    }

    const int colb = 2 * kq;
    if (COMBO) {
        float z0[DOUT], z1[DOUT];
#pragma unroll
        for (int c = 0; c < DOUT; c++) { z0[c] = 0.f; z1[c] = 0.f; }
#pragma unroll
        for (int nc = 0; nc < NCH; nc++) {
            int col = nc * 8 + colb;
            if (col < 64) {
                float bx = __ldg(&bias[col]), by = __ldg(&bias[col + 1]);
                float t0a = fmaxf(acc[nc][0] + bx, 0.f), t0b = fmaxf(acc[nc][1] + by, 0.f);
                float t1a = fmaxf(acc[nc][2] + bx, 0.f), t1b = fmaxf(acc[nc][3] + by, 0.f);
#pragma unroll
                for (int c = 0; c < DOUT; c++) {
                    float w0 = sG[col * DOUT + c], w1 = sG[(col + 1) * DOUT + c];
                    z0[c] += t0a * w0 + t0b * w1;
                    z1[c] += t1a * w0 + t1b * w1;
                }
            } else if (col < 76) {
                int c2 = col - 64;
                if (v0) *(float2*)&out2[(size_t)r0 * DOUT + c2] =
                            make_float2(acc[nc][0], acc[nc][1]);
                if (v1) *(float2*)&out2[(size_t)r1 * DOUT + c2] =
                            make_float2(acc[nc][2], acc[nc][3]);
            }
        }
#pragma unroll
        for (int c = 0; c < DOUT; c++) {
            z0[c] += __shfl_xor_sync(0xffffffffu, z0[c], 1);
            z0[c] += __shfl_xor_sync(0xffffffffu, z0[c], 2);
            z1[c] += __shfl_xor_sync(0xffffffffu, z1[c], 1);
            z1[c] += __shfl_xor_sync(0xffffffffu, z1[c], 2);
        }
        if (kq == 0) {
            if (v0) {
                float status = __ldg(&xfull[(size_t)r0 * DIN + 12]);
                float flag = status < 0.5f ? 2.5f : 0.f;
#pragma unroll
                for (int c = 0; c < DOUT; c++) {
                    float gate = 1.f / (1.f + expf(-(z0[c] + __ldg(&Gb2[c]))));
                    float sig = (1.f - status) * __ldg(&Ws[c]) + __ldg(&bs[c]);
                    out[(size_t)r0 * DOUT + c] = flag * gate * sig;
                }
            }
            if (v1) {
                float status = __ldg(&xfull[(size_t)r1 * DIN + 12]);
                float flag = status < 0.5f ? 2.5f : 0.f;
#pragma unroll
                for (int c = 0; c < DOUT; c++) {
                    float gate = 1.f / (1.f + expf(-(z1[c] + __ldg(&Gb2[c]))));
                    float sig = (1.f - status) * __ldg(&Ws[c]) + __ldg(&bs[c]);
                    out[(size_t)r1 * DOUT + c] = flag * gate * sig;
                }
            }
        }
    } else {
#pragma unroll
        for (int nc = 0; nc < NCH; nc++) {
            int col = nc * 8 + colb;
            if (v0) *(float2*)&out[(size_t)r0 * NC + col] =
                        make_float2(acc[nc][0], acc[nc][1]);
            if (v1) *(float2*)&out[(size_t)r1 * NC + col] =
                        make_float2(acc[nc][2], acc[nc][3]);
        }
    }

    if (ATT) {
        float as0[4] = {}, ad0[4] = {}, as1[4] = {}, ad1[4] = {};
#pragma unroll
        for (int nc = 0; nc < NCH; nc++) {
            int col = nc * 8 + colb;
            float sx = __ldg(&att_s[col]), sy = __ldg(&att_s[col + 1]);
            float dx = __ldg(&att_d[col]), dy = __ldg(&att_d[col + 1]);
            int h = nc >> 2;
            as0[h] += acc[nc][0] * sx + acc[nc][1] * sy;
            ad0[h] += acc[nc][0] * dx + acc[nc][1] * dy;
            as1[h] += acc[nc][2] * sx + acc[nc][3] * sy;
            ad1[h] += acc[nc][2] * dx + acc[nc][3] * dy;
        }
#pragma unroll
        for (int h = 0; h < 4; h++) {
#pragma unroll
            for (int off = 1; off <= 2; off <<= 1) {
                as0[h] += __shfl_xor_sync(0xffffffffu, as0[h], off);
                ad0[h] += __shfl_xor_sync(0xffffffffu, ad0[h], off);
                as1[h] += __shfl_xor_sync(0xffffffffu, as1[h], off);
                ad1[h] += __shfl_xor_sync(0xffffffffu, ad1[h], off);
            }
        }
        if (kq == 0) {
#pragma unroll
            for (int h = 0; h < 4; h++) {
                if (v0) { g_as[r0 * 4 + h] = as0[h]; g_ad[r0 * 4 + h] = ad0[h]; }
                if (v1) { g_as[r1 * 4 + h] = as1[h]; g_ad[r1 * 4 + h] = ad1[h]; }
            }
        }
    }
}

// ----------------------------------------------------------------------------
// Fused input GEMM: agg1 = xa@W1 + b1, xin = x@Wi + bi, + fused BN1 partials
// ----------------------------------------------------------------------------
__global__ void __launch_bounds__(128) gemm_in_kernel(
        const float* __restrict__ XA, const float* __restrict__ X,
        const float* __restrict__ W1, const float* __restrict__ b1,
        const float* __restrict__ Wi, const float* __restrict__ bi,
        float* __restrict__ h1, float* __restrict__ xin) {
    __shared__ float sS[4][128], sQ[4][128];
    const int tid = threadIdx.x;
    const int cg = tid & 31;
    const int rg = tid >> 5;
    const int n0 = blockIdx.x * 16 + rg * 4;
    float a1[4][4] = {}; float ai[4][4] = {};
    const float4* W1v = (const float4*)W1;
    const float4* Wiv = (const float4*)Wi;
#pragma unroll
    for (int k = 0; k < DIN; k++) {
        float4 w1 = __ldg(&W1v[k * 32 + cg]);
        float4 wi = __ldg(&Wiv[k * 32 + cg]);
#pragma unroll
        for (int r = 0; r < 4; r++) {
            float xav = __ldg(&XA[(n0 + r) * DIN + k]);
            float xv  = __ldg(&X[(n0 + r) * DIN + k]);
            a1[r][0] += xav * w1.x; a1[r][1] += xav * w1.y; a1[r][2] += xav * w1.z; a1[r][3] += xav * w1.w;
            ai[r][0] += xv * wi.x;  ai[r][1] += xv * wi.y;  ai[r][2] += xv * wi.z;  ai[r][3] += xv * wi.w;
        }
    }
    const int c0 = cg * 4;
    float4 b1v = __ldg(&((const float4*)b1)[cg]);
    float4 biv = __ldg(&((const float4*)bi)[cg]);
    float s4[4] = {}, q4[4] = {};
#pragma unroll
    for (int r = 0; r < 4; r++) {
        float4 v1, vi;
        v1.x = a1[r][0] + b1v.x; v1.y = a1[r][1] + b1v.y;
        v1.z = a1[r][2] + b1v.z; v1.w = a1[r][3] + b1v.w;
        vi.x = ai[r][0] + biv.x; vi.y = ai[r][1] + biv.y;
        vi.z = ai[r][2] + biv.z; vi.w = ai[r][3] + biv.w;
        s4[0] += v1.x; q4[0] += v1.x * v1.x;
        s4[1] += v1.y; q4[1] += v1.y * v1.y;
        s4[2] += v1.z; q4[2] += v1.z * v1.z;
        s4[3] += v1.w; q4[3] += v1.w * v1.w;
        *(float4*)&h1[(n0 + r) * HH + c0] = v1;
        *(float4*)&xin[(n0 + r) * HH + c0] = vi;
    }
#pragma unroll
    for (int i = 0; i < 4; i++) { sS[rg][c0 + i] = s4[i]; sQ[rg][c0 + i] = q4[i]; }
    __syncthreads();
    const int b = blockIdx.x & (NBUK - 1);
    float ts = sS[0][tid] + sS[1][tid] + sS[2][tid] + sS[3][tid];
    float tq = sQ[0][tid] + sQ[1][tid] + sQ[2][tid] + sQ[3][tid];
    atomicAdd(&g_bnpart[0][b][tid], ts);
    atomicAdd(&g_bnpart[0][b][tid + 128], tq);
}

// ----------------------------------------------------------------------------
// GCN aggregation (128 ch, warp/node, 8-wide main + serial tail) + BN3 partials
// ----------------------------------------------------------------------------
__global__ void __launch_bounds__(128) gcn_agg128(const float* __restrict__ in,
                                                  const float* __restrict__ bias,
                                                  float* __restrict__ out) {
    __shared__ float sS[4][128], sQ[4][128];
    const int warp = threadIdx.x >> 5;
    const int lane = threadIdx.x & 31;
    const int n = blockIdx.x * 4 + warp;
    const float dn = g_dinv[n];
    const int s0 = g_rowptr[n], s1 = g_rowptr[n + 1];
    const float4* in4 = (const float4*)in;
    float4 acc = __ldg(&in4[n * 32 + lane]);
    float dn2 = dn * dn;
    acc.x *= dn2; acc.y *= dn2; acc.z *= dn2; acc.w *= dn2;
    int j = s0;
    for (; j + 8 <= s1; j += 8) {
        int2 e[8];
        float4 v[8];
#pragma unroll
        for (int q = 0; q < 8; q++) e[q] = __ldg(&g_epack[j + q]);
#pragma unroll
        for (int q = 0; q < 8; q++) v[q] = __ldg(&in4[e[q].x * 32 + lane]);
#pragma unroll
        for (int q = 0; q < 8; q++) {
            float c = __int_as_float(e[q].y);
            acc.x += c * v[q].x; acc.y += c * v[q].y;
            acc.z += c * v[q].z; acc.w += c * v[q].w;
        }
    }
    for (; j < s1; j++) {
        int2 e = __ldg(&g_epack[j]);
        float4 v = __ldg(&in4[e.x * 32 + lane]);
        float c = __int_as_float(e.y);
        acc.x += c * v.x; acc.y += c * v.y; acc.z += c * v.z; acc.w += c * v.w;
    }
    float4 bv = __ldg(&((const float4*)bias)[lane]);
    acc.x += bv.x; acc.y += bv.y; acc.z += bv.z; acc.w += bv.w;
    ((float4*)out)[n * 32 + lane] = acc;
    sS[warp][lane * 4 + 0] = acc.x; sQ[warp][lane * 4 + 0] = acc.x * acc.x;
    sS[warp][lane * 4 + 1] = acc.y; sQ[warp][lane * 4 + 1] = acc.y * acc.y;
    sS[warp][lane * 4 + 2] = acc.z; sQ[warp][lane * 4 + 2] = acc.z * acc.z;
    sS[warp][lane * 4 + 3] = acc.w; sQ[warp][lane * 4 + 3] = acc.w * acc.w;
    __syncthreads();
    const int tid = threadIdx.x;
    const int b = blockIdx.x & (NBUK - 1);
    float ts = sS[0][tid] + sS[1][tid] + sS[2][tid] + sS[3][tid];
    float tq = sQ[0][tid] + sQ[1][tid] + sQ[2][tid] + sQ[3][tid];
    atomicAdd(&g_bnpart[2][b][tid], ts);
    atomicAdd(&g_bnpart[2][b][tid + 128], tq);
}

// ----------------------------------------------------------------------------
// GAT aggregation: single pass, 8-wide main + serial tail + BN2 partials
// ----------------------------------------------------------------------------
__global__ void __launch_bounds__(256) gat_agg_kernel(const float* __restrict__ hg,
                                                      const float* __restrict__ bg,
                                                      float* __restrict__ out) {
    __shared__ float sS[8][128], sQ[8][128];
    const int w = threadIdx.x >> 5;
    const int lane = threadIdx.x & 31;
    const int n = blockIdx.x * 8 + w;
    const int s0 = g_rowptr[n], s1 = g_rowptr[n + 1];
    const int h = lane >> 3;
    const int eq = lane & 7;
    const float4* ad4 = (const float4*)g_ad;
    const float4* as4 = (const float4*)g_as;

    float4 adv = __ldg(&ad4[n]);
    float4 asv = __ldg(&as4[n]);
    float adh = h < 2 ? (h == 0 ? adv.x : adv.y) : (h == 2 ? adv.z : adv.w);
    float ash = h < 2 ? (h == 0 ? asv.x : asv.y) : (h == 2 ? asv.z : asv.w);
    float xs = expf(lrelu(ash + adh));

    const float4* hg4 = (const float4*)hg;
    float4 acc = make_float4(0.f, 0.f, 0.f, 0.f);
    float tsum = 0.f;

    int j = s0;
    for (; j + 8 <= s1; j += 8) {
        int2 e[8];
#pragma unroll
        for (int q = 0; q < 8; q++) e[q] = __ldg(&g_epack[j + q]);
        float myx = expf(lrelu(__ldg(&g_as[e[eq].x * 4 + h]) + adh));
        tsum += myx;
        float4 v[8];
#pragma unroll
        for (int q = 0; q < 8; q++) v[q] = __ldg(&hg4[e[q].x * 32 + lane]);
#pragma unroll
        for (int q = 0; q < 8; q++) {
            float a = __shfl_sync(0xffffffffu, myx, h * 8 + q);
            acc.x += a * v[q].x; acc.y += a * v[q].y;
            acc.z += a * v[q].z; acc.w += a * v[q].w;
        }
    }
    for (; j < s1; j++) {
        int2 e = __ldg(&g_epack[j]);
        float a = expf(lrelu(__ldg(&g_as[e.x * 4 + h]) + adh));
        if (eq == 0) tsum += a;
        float4 v = __ldg(&hg4[e.x * 32 + lane]);
        acc.x += a * v.x; acc.y += a * v.y; acc.z += a * v.z; acc.w += a * v.w;
    }
#pragma unroll
    for (int off = 1; off <= 4; off <<= 1)
        tsum += __shfl_xor_sync(0xffffffffu, tsum, off);
    float inv = 1.f / (tsum + xs);

    float4 self = __ldg(&hg4[n * 32 + lane]);
    float4 bv = __ldg(&((const float4*)bg)[lane]);
    float4 o;
    o.x = (acc.x + xs * self.x) * inv + bv.x;
    o.y = (acc.y + xs * self.y) * inv + bv.y;
    o.z = (acc.z + xs * self.z) * inv + bv.z;
    o.w = (acc.w + xs * self.w) * inv + bv.w;
    ((float4*)out)[n * 32 + lane] = o;
    sS[w][lane * 4 + 0] = o.x; sQ[w][lane * 4 + 0] = o.x * o.x;
    sS[w][lane * 4 + 1] = o.y; sQ[w][lane * 4 + 1] = o.y * o.y;
    sS[w][lane * 4 + 2] = o.z; sQ[w][lane * 4 + 2] = o.z * o.z;
    sS[w][lane * 4 + 3] = o.w; sQ[w][lane * 4 + 3] = o.w * o.w;
    __syncthreads();
    const int tid = threadIdx.x;
    if (tid < 128) {
        const int b = blockIdx.x & (NBUK - 1);
        float ts = 0.f, tq = 0.f;
#pragma unroll
        for (int ww = 0; ww < 8; ww++) { ts += sS[ww][tid]; tq += sQ[ww][tid]; }
        atomicAdd(&g_bnpart[1][b][tid], ts);
        atomicAdd(&g_bnpart[1][b][tid + 128], tq);
    }
}

// ----------------------------------------------------------------------------
// Output: GCN aggregation of h4 (12 ch, 8-wide main + serial tail) + gate add
// ----------------------------------------------------------------------------
__global__ void __launch_bounds__(128) out_kernel(
        const float* __restrict__ h4, const float* __restrict__ b4,
        const float* __restrict__ gc, float* __restrict__ out) {
    const int warp = threadIdx.x >> 5;
    const int lane = threadIdx.x & 31;
    const int n = blockIdx.x * 4 + warp;
    const float dn = g_dinv[n];
    const int s0 = g_rowptr[n], s1 = g_rowptr[n + 1];
    float acc = (lane < DOUT) ? h4[n * DOUT + lane] * dn * dn : 0.f;
    int j = s0;
    for (; j + 8 <= s1; j += 8) {
        int2 e[8];
        float v[8];
#pragma unroll
        for (int q = 0; q < 8; q++) e[q] = __ldg(&g_epack[j + q]);
#pragma unroll
        for (int q = 0; q < 8; q++)
            v[q] = (lane < DOUT) ? __ldg(&h4[e[q].x * DOUT + lane]) : 0.f;
#pragma unroll
        for (int q = 0; q < 8; q++) acc += __int_as_float(e[q].y) * v[q];
    }
    for (; j < s1; j++) {
        int2 e = __ldg(&g_epack[j]);
        if (lane < DOUT) acc += __int_as_float(e.y) * __ldg(&h4[e.x * DOUT + lane]);
    }
    if (lane < DOUT)
        out[n * DOUT + lane] = acc + __ldg(&b4[lane]) + __ldg(&gc[n * DOUT + lane]);
}

// ----------------------------------------------------------------------------
// Launch
// ----------------------------------------------------------------------------
extern "C" void kernel_launch(void* const* d_in, const int* in_sizes, int n_in,
                              void* d_out, int out_size) {
    const float* x   = (const float*)d_in[0];
    const int*   ei  = (const int*)d_in[1];
    const float* ew  = (const float*)d_in[2];
    const float* W1  = (const float*)d_in[3];
    const float* b1  = (const float*)d_in[4];
    const float* g1  = (const float*)d_in[5];
    const float* be1 = (const float*)d_in[6];
    const float* Wg  = (const float*)d_in[7];
    const float* atts= (const float*)d_in[8];
    const float* attd= (const float*)d_in[9];
    const float* bg  = (const float*)d_in[10];
    const float* g2  = (const float*)d_in[11];
    const float* be2 = (const float*)d_in[12];
    const float* W3  = (const float*)d_in[13];
    const float* b3  = (const float*)d_in[14];
    const float* g3  = (const float*)d_in[15];
    const float* be3 = (const float*)d_in[16];
    const float* W4  = (const float*)d_in[17];
    const float* b4  = (const float*)d_in[18];
    const float* Wi  = (const float*)d_in[19];
    const float* bi  = (const float*)d_in[20];
    const float* Gw1 = (const float*)d_in[21];
    const float* Gb1 = (const float*)d_in[22];
    const float* Gw2 = (const float*)d_in[23];
    const float* Gb2 = (const float*)d_in[24];
    const float* Ws  = (const float*)d_in[25];
    const float* bs  = (const float*)d_in[26];
    float* out = (float*)d_out;
    const int* src = ei;
    const int* dst = ei + EE;

    float *p_h1, *p_agg, *p_x1, *p_xin, *p_hg, *p_xa, *p_h4, *p_gc;
    float *p_wtg, *p_wt3, *p_wtcomb, *p_bn;
    cudaGetSymbolAddress((void**)&p_h1, g_h1);
    cudaGetSymbolAddress((void**)&p_agg, g_agg);
    cudaGetSymbolAddress((void**)&p_x1, g_x1);
    cudaGetSymbolAddress((void**)&p_xin, g_xin);
    cudaGetSymbolAddress((void**)&p_hg, g_hg);
    cudaGetSymbolAddress((void**)&p_xa, g_xa);
    cudaGetSymbolAddress((void**)&p_h4, g_h4);
    cudaGetSymbolAddress((void**)&p_gc, g_gc);
    cudaGetSymbolAddress((void**)&p_wtg, g_wtg);
    cudaGetSymbolAddress((void**)&p_wt3, g_wt3);
    cudaGetSymbolAddress((void**)&p_wtcomb, g_wtcomb);
    cudaGetSymbolAddress((void**)&p_bn, g_bnpart);

    const int SMEM128 = 1024 + 128 * 132 * 4;                 // 68608
    const int SMEM80  = 1024 + 80 * 132 * 4 + 64 * DOUT * 4;  // 46336
    cudaFuncSetAttribute(mma_gemm<128, false, true, true, false>,
                         cudaFuncAttributeMaxDynamicSharedMemorySize, SMEM128);
    cudaFuncSetAttribute(mma_gemm<128, true, false, false, false>,
                         cudaFuncAttributeMaxDynamicSharedMemorySize, SMEM128);
    cudaFuncSetAttribute(mma_gemm<80, true, false, false, true>,
                         cudaFuncAttributeMaxDynamicSharedMemorySize, SMEM80);
    const int MGRID = (NN + 127) / 128;   // 782

    // graph preprocessing + weight prep
    init_kernel<<<(NN + 255) / 256, 256>>>();
    count_kernel<<<(EE + 255) / 256, 256>>>(dst, ew);
    part_kernel<<<NB, 256>>>();
    writerow_kernel<<<NB, 256>>>();
    fill_kernel<<<(EE + 255) / 256, 256>>>(src, dst, ew);
    prep_weights_kernel<<<168, 256>>>(Wg, W3, Gw1, W4);

    // layer 1
    agg24_kernel<<<NN / 4, 128>>>(x, p_xa);
    gemm_in_kernel<<<NN / 16, 128>>>(p_xa, x, W1, b1, Wi, bi, p_agg, p_xin);

    // GAT: Wg GEMM (in-kernel BN1 finalize) + side-write x1 + att reduce
    mma_gemm<128, false, true, true, false><<<MGRID, 256, SMEM128>>>(
        p_agg, nullptr, p_x1, p_wtg, nullptr, p_hg, nullptr, atts, attd,
        p_bn + 0 * NBUK * 256, g1, be1, nullptr, nullptr, nullptr, nullptr, nullptr);
    gat_agg_kernel<<<NN / 8, 256>>>(p_hg, bg, p_agg);

    // layer 3: W3 GEMM (in-kernel BN2 finalize) + xin residual
    mma_gemm<128, true, false, false, false><<<MGRID, 256, SMEM128>>>(
        p_agg, p_xin, nullptr, p_wt3, nullptr, p_h1, nullptr, nullptr, nullptr,
        p_bn + 1 * NBUK * 256, g2, be2, nullptr, nullptr, nullptr, nullptr, nullptr);
    gcn_agg128<<<NN / 4, 128>>>(p_h1, b3, p_agg);

    // output: combo GEMM (in-kernel BN3 finalize) + x1 residual + fused gate
    mma_gemm<80, true, false, false, true><<<MGRID, 256, SMEM80>>>(
        p_agg, p_x1, nullptr, p_wtcomb, Gb1, p_gc, p_h4, nullptr, nullptr,
        p_bn + 2 * NBUK * 256, g3, be3, Gw2, Gb2, Ws, bs, x);
    out_kernel<<<NN / 4, 128>>>(p_h4, b4, p_gc, out);
}

// round 16
// speedup vs baseline: 1.0531x; 1.0070x over previous
#include <cuda_runtime.h>
#include <math.h>
#include <stdint.h>

#define NN 100000
#define EE 1600000
#define DIN 24
#define HH 128
#define DOUT 12
#define HEADS 4
#define NB 391   // ceil(NN/256)
#define NBUK 32  // BN partial buckets
#define WSCALE 33554432.0f   // 2^25 fixed-point scale for packed degree

// ----------------------------------------------------------------------------
// Scratch (device globals; no dynamic allocation allowed)
// ----------------------------------------------------------------------------
__device__ float g_h1[NN * HH];      // h3 = x2@W3
__device__ float g_agg[NN * HH];     // raw pre-BN activations per layer
__device__ float g_x1[NN * HH];      // x1 (side-written by Wg GEMM)
__device__ float g_xin[NN * HH];     // x_in_proj
__device__ float g_hg[NN * HH];      // hg
__device__ float g_xa[NN * DIN];     // 24-dim aggregated x
__device__ float g_h4[NN * DOUT];
__device__ float g_gc[NN * DOUT];    // gate contribution per node
__device__ float g_as[NN * HEADS];
__device__ float g_ad[NN * HEADS];
__device__ unsigned long long g_packed[NN];  // (cnt<<40) | round(sum_w * 2^25)
__device__ float g_dinv[NN];
__device__ int   g_cnt[NN];
__device__ int   g_cur[NN];
__device__ int   g_rowptr[NN + 1];
__device__ int2  g_epack[EE];
__device__ int   g_part[512];
__device__ float g_bnpart[3][NBUK][256];  // per-layer bucketed BN partials
__device__ float g_wtg[HH * HH];     // Wg^T  [128,128] K-major
__device__ float g_wt3[HH * HH];     // W3^T
__device__ float g_wtcomb[80 * HH];  // [Gw1^T ; W4^T ; pad]

__device__ __forceinline__ float lrelu(float v) { return v > 0.f ? v : 0.2f * v; }
__device__ __forceinline__ uint32_t to_tf32(float f) {
    uint32_t t;
    asm("cvt.rna.tf32.f32 %0, %1;" : "=r"(t) : "f"(f));
    return t;
}

// ----------------------------------------------------------------------------
// Graph preprocessing
// ----------------------------------------------------------------------------
__global__ void __launch_bounds__(256) init_kernel() {
    int i = blockIdx.x * blockDim.x + threadIdx.x;
    if (i < NN) {
        g_packed[i] = (unsigned long long)(1u << 25);   // deg=1.0 (self loop), cnt=0
        g_cur[i] = 0;
    }
    if (i < 3 * NBUK * 256) ((float*)g_bnpart)[i] = 0.f;
}

// single 64-bit atomic per edge: cnt in bits[40:], fixed-point w-sum in bits[:40]
__global__ void __launch_bounds__(256) count_kernel(const int* __restrict__ dst,
                                                    const float* __restrict__ w) {
    int e = blockIdx.x * blockDim.x + threadIdx.x;
    if (e < EE) {
        int d = dst[e];
        unsigned long long inc =
            (1ull << 40) + (unsigned long long)(w[e] * WSCALE + 0.5f);
        atomicAdd(&g_packed[d], inc);
    }
}

__global__ void __launch_bounds__(256) part_kernel() {
    __shared__ int sw[8];
    int i = blockIdx.x * 256 + threadIdx.x;
    int v = 0;
    if (i < NN) {
        unsigned long long p = g_packed[i];
        v = (int)(p >> 40);
        float deg = (float)(p & ((1ull << 40) - 1ull)) * (1.0f / WSCALE);
        g_dinv[i] = rsqrtf(deg);
        g_cnt[i] = v;
    }
    int s = v;
#pragma unroll
    for (int off = 16; off; off >>= 1) s += __shfl_down_sync(0xffffffffu, s, off);
    if ((threadIdx.x & 31) == 0) sw[threadIdx.x >> 5] = s;
    __syncthreads();
    if (threadIdx.x == 0) {
        int t = 0;
#pragma unroll
        for (int k = 0; k < 8; k++) t += sw[k];
        g_part[blockIdx.x] = t;
    }
}

__global__ void __launch_bounds__(256) writerow_kernel() {
    __shared__ int sp[256];
    __shared__ int swr[8];
    __shared__ int soff;
    const int t = threadIdx.x;
    const int i = blockIdx.x * 256 + t;
    int pre = 0;
    for (int b = t; b < blockIdx.x; b += 256) pre += g_part[b];
#pragma unroll
    for (int off = 16; off; off >>= 1) pre += __shfl_down_sync(0xffffffffu, pre, off);
    if ((t & 31) == 0) swr[t >> 5] = pre;
    __syncthreads();
    if (t == 0) {
        int s = 0;
#pragma unroll
        for (int k = 0; k < 8; k++) s += swr[k];
        soff = s;
    }
    int v = (i < NN) ? g_cnt[i] : 0;
    sp[t] = v;
    __syncthreads();
    for (int off = 1; off < 256; off <<= 1) {
        int a = (t >= off) ? sp[t - off] : 0;
        __syncthreads();
        sp[t] += a;
        __syncthreads();
    }
    if (i < NN) g_rowptr[i] = sp[t] - v + soff;
    if (i == 0) g_rowptr[NN] = EE;
}

__global__ void __launch_bounds__(256) fill_kernel(const int* __restrict__ src,
                                                   const int* __restrict__ dst,
                                                   const float* __restrict__ w) {
    int e = blockIdx.x * blockDim.x + threadIdx.x;
    if (e < EE) {
        int d = dst[e];
        int s = src[e];
        int pos = g_rowptr[d] + atomicAdd(&g_cur[d], 1);
        float coef = w[e] * __ldg(&g_dinv[s]) * __ldg(&g_dinv[d]);
        g_epack[pos] = make_int2(s, __float_as_int(coef));
    }
}

__global__ void __launch_bounds__(256) prep_weights_kernel(const float* __restrict__ Wg,
                                                           const float* __restrict__ W3,
                                                           const float* __restrict__ Gw1,
                                                           const float* __restrict__ W4) {
    int idx = blockIdx.x * 256 + threadIdx.x;
    if (idx < 16384) {
        int k = idx >> 7, c = idx & 127;
        g_wtg[c * 128 + k] = __ldg(&Wg[idx]);
    } else if (idx < 32768) {
        int j = idx - 16384;
        int k = j >> 7, c = j & 127;
        g_wt3[c * 128 + k] = __ldg(&W3[j]);
    } else if (idx < 43008) {
        int j = idx - 32768;
        int r = j >> 7, k = j & 127;
        float v = 0.f;
        if (r < 64) v = __ldg(&Gw1[k * 64 + r]);
        else if (r < 76) v = __ldg(&W4[k * DOUT + (r - 64)]);
        g_wtcomb[j] = v;
    }
}

// ----------------------------------------------------------------------------
// 24-channel GCN aggregation (8-wide main + serial tail)
// ----------------------------------------------------------------------------
__global__ void __launch_bounds__(128) agg24_kernel(const float* __restrict__ x,
                                                    float* __restrict__ xa) {
    const int warp = threadIdx.x >> 5;
    const int lane = threadIdx.x & 31;
    const int n = blockIdx.x * 4 + warp;
    const float dn = g_dinv[n];
    const int s0 = g_rowptr[n], s1 = g_rowptr[n + 1];
    float acc = (lane < DIN) ? x[n * DIN + lane] * dn * dn : 0.f;
    int j = s0;
    for (; j + 8 <= s1; j += 8) {
        int2 e[8];
        float v[8];
#pragma unroll
        for (int q = 0; q < 8; q++) e[q] = __ldg(&g_epack[j + q]);
#pragma unroll
        for (int q = 0; q < 8; q++)
            v[q] = (lane < DIN) ? __ldg(&x[e[q].x * DIN + lane]) : 0.f;
#pragma unroll
        for (int q = 0; q < 8; q++) acc += __int_as_float(e[q].y) * v[q];
    }
    for (; j < s1; j++) {
        int2 e = __ldg(&g_epack[j]);
        if (lane < DIN) acc += __int_as_float(e.y) * __ldg(&x[e.x * DIN + lane]);
    }
    if (lane < DIN) xa[n * DIN + lane] = acc;
}

// ----------------------------------------------------------------------------
// TF32 mma.sync GEMM. In-kernel BN finalize from bucketed partials.
// ----------------------------------------------------------------------------
template<int NC, bool ADD, bool WRITEX, bool ATT, bool COMBO>
__global__ void __launch_bounds__(256) mma_gemm(const float* __restrict__ Araw,
                                                const float* __restrict__ addp,
                                                float* __restrict__ xout,
                                                const float* __restrict__ Bt,
                                                const float* __restrict__ bias,
                                                float* __restrict__ out,
                                                float* __restrict__ out2,
                                                const float* __restrict__ att_s,
                                                const float* __restrict__ att_d,
                                                const float* __restrict__ bnp,
                                                const float* __restrict__ bng,
                                                const float* __restrict__ bnbe,
                                                const float* __restrict__ Gw2,
                                                const float* __restrict__ Gb2,
                                                const float* __restrict__ Ws,
                                                const float* __restrict__ bs,
                                                const float* __restrict__ xfull) {
    extern __shared__ float smf[];
    float* sSC = smf;
    float* sSH = smf + 128;
    uint32_t* sW = (uint32_t*)(smf + 256);   // [NC][132]
    float* sG = smf + 256 + NC * 132;        // [64*12] (COMBO only)
    const int tid = threadIdx.x, wid = tid >> 5, lane = tid & 31;
    const int n0 = blockIdx.x * 128;

    if (tid < 128) {
        float s = 0.f, s2 = 0.f;
#pragma unroll 8
        for (int b = 0; b < NBUK; b++) {
            s += __ldg(&bnp[b * 256 + tid]);
            s2 += __ldg(&bnp[b * 256 + tid + 128]);
        }
        float mean = s * (1.0f / NN);
        float var = fmaxf(s2 * (1.0f / NN) - mean * mean, 0.f);
        float sc = rsqrtf(var + 1e-5f) * __ldg(&bng[tid]);
        sSC[tid] = sc;
        sSH[tid] = __ldg(&bnbe[tid]) - mean * sc;
    }
    for (int i = tid; i < NC * 128; i += 256) {
        int c = i >> 7, k = i & 127;
        sW[c * 132 + k] = to_tf32(__ldg(&Bt[i]));
    }
    if (COMBO) {
        for (int i = tid; i < 64 * DOUT; i += 256) sG[i] = __ldg(&Gw2[i]);
    }
    __syncthreads();

    constexpr int NCH = NC / 8;
    float acc[NCH][4];
#pragma unroll
    for (int i = 0; i < NCH; i++) {
        acc[i][0] = 0.f; acc[i][1] = 0.f; acc[i][2] = 0.f; acc[i][3] = 0.f;
    }

    const int r0 = n0 + wid * 16 + (lane >> 2);
    const int r1 = r0 + 8;
    const bool v0 = r0 < NN, v1 = r1 < NN;
    const int kq = lane & 3;
    const int nq = lane >> 2;

#pragma unroll 4
    for (int k8 = 0; k8 < 128; k8 += 8) {
        int ka = k8 + kq, kb = k8 + kq + 4;
        float f0 = 0.f, f1 = 0.f, f2 = 0.f, f3 = 0.f;
        if (v0) {
            f0 = fmaxf(__ldg(&Araw[(size_t)r0 * 128 + ka]) * sSC[ka] + sSH[ka], 0.f);
            f2 = fmaxf(__ldg(&Araw[(size_t)r0 * 128 + kb]) * sSC[kb] + sSH[kb], 0.f);
            if (ADD) {
                f0 += __ldg(&addp[(size_t)r0 * 128 + ka]);
                f2 += __ldg(&addp[(size_t)r0 * 128 + kb]);
            }
            if (WRITEX) {
                xout[(size_t)r0 * 128 + ka] = f0;
                xout[(size_t)r0 * 128 + kb] = f2;
            }
        }
        if (v1) {
            f1 = fmaxf(__ldg(&Araw[(size_t)r1 * 128 + ka]) * sSC[ka] + sSH[ka], 0.f);
            f3 = fmaxf(__ldg(&Araw[(size_t)r1 * 128 + kb]) * sSC[kb] + sSH[kb], 0.f);
            if (ADD) {
                f1 += __ldg(&addp[(size_t)r1 * 128 + ka]);
                f3 += __ldg(&addp[(size_t)r1 * 128 + kb]);
            }
            if (WRITEX) {
                xout[(size_t)r1 * 128 + ka] = f1;
                xout[(size_t)r1 * 128 + kb] = f3;
            }
        }
        uint32_t a0 = to_tf32(f0), a1 = to_tf32(f1), a2 = to_tf32(f2), a3 = to_tf32(f3);
#pragma unroll
        for (int nc = 0; nc < NCH; nc++) {
            uint32_t b0 = sW[(nc * 8 + nq) * 132 + ka];
            uint32_t b1 = sW[(nc * 8 + nq) * 132 + kb];
            asm volatile(
                "mma.sync.aligned.m16n8k8.row.col.f32.tf32.tf32.f32 "
                "{%0,%1,%2,%3}, {%4,%5,%6,%7}, {%8,%9}, {%0,%1,%2,%3};"
                : "+f"(acc[nc][0]), "+f"(acc[nc][1]), "+f"(acc[nc][2]), "+f"(acc[nc][3])
                : "r"(a0), "r"(a1), "r"(a2), "r"(a3), "r"(b0), "r"(b1));
        }
    }

    const int colb = 2 * kq;
    if (COMBO) {
        float z0[DOUT], z1[DOUT];
#pragma unroll
        for (int c = 0; c < DOUT; c++) { z0[c] = 0.f; z1[c] = 0.f; }
#pragma unroll
        for (int nc = 0; nc < NCH; nc++) {
            int col = nc * 8 + colb;
            if (col < 64) {
                float bx = __ldg(&bias[col]), by = __ldg(&bias[col + 1]);
                float t0a = fmaxf(acc[nc][0] + bx, 0.f), t0b = fmaxf(acc[nc][1] + by, 0.f);
                float t1a = fmaxf(acc[nc][2] + bx, 0.f), t1b = fmaxf(acc[nc][3] + by, 0.f);
#pragma unroll
                for (int c = 0; c < DOUT; c++) {
                    float w0 = sG[col * DOUT + c], w1 = sG[(col + 1) * DOUT + c];
                    z0[c] += t0a * w0 + t0b * w1;
                    z1[c] += t1a * w0 + t1b * w1;
                }
            } else if (col < 76) {
                int c2 = col - 64;
                if (v0) *(float2*)&out2[(size_t)r0 * DOUT + c2] =
                            make_float2(acc[nc][0], acc[nc][1]);
                if (v1) *(float2*)&out2[(size_t)r1 * DOUT + c2] =
                            make_float2(acc[nc][2], acc[nc][3]);
            }
        }
#pragma unroll
        for (int c = 0; c < DOUT; c++) {
            z0[c] += __shfl_xor_sync(0xffffffffu, z0[c], 1);
            z0[c] += __shfl_xor_sync(0xffffffffu, z0[c], 2);
            z1[c] += __shfl_xor_sync(0xffffffffu, z1[c], 1);
            z1[c] += __shfl_xor_sync(0xffffffffu, z1[c], 2);
        }
        if (kq == 0) {
            if (v0) {
                float status = __ldg(&xfull[(size_t)r0 * DIN + 12]);
                float flag = status < 0.5f ? 2.5f : 0.f;
#pragma unroll
                for (int c = 0; c < DOUT; c++) {
                    float gate = 1.f / (1.f + expf(-(z0[c] + __ldg(&Gb2[c]))));
                    float sig = (1.f - status) * __ldg(&Ws[c]) + __ldg(&bs[c]);
                    out[(size_t)r0 * DOUT + c] = flag * gate * sig;
                }
            }
            if (v1) {
                float status = __ldg(&xfull[(size_t)r1 * DIN + 12]);
                float flag = status < 0.5f ? 2.5f : 0.f;
#pragma unroll
                for (int c = 0; c < DOUT; c++) {
                    float gate = 1.f / (1.f + expf(-(z1[c] + __ldg(&Gb2[c]))));
                    float sig = (1.f - status) * __ldg(&Ws[c]) + __ldg(&bs[c]);
                    out[(size_t)r1 * DOUT + c] = flag * gate * sig;
                }
            }
        }
    } else {
#pragma unroll
        for (int nc = 0; nc < NCH; nc++) {
            int col = nc * 8 + colb;
            if (v0) *(float2*)&out[(size_t)r0 * NC + col] =
                        make_float2(acc[nc][0], acc[nc][1]);
            if (v1) *(float2*)&out[(size_t)r1 * NC + col] =
                        make_float2(acc[nc][2], acc[nc][3]);
        }
    }

    if (ATT) {
        float as0[4] = {}, ad0[4] = {}, as1[4] = {}, ad1[4] = {};
#pragma unroll
        for (int nc = 0; nc < NCH; nc++) {
            int col = nc * 8 + colb;
            float sx = __ldg(&att_s[col]), sy = __ldg(&att_s[col + 1]);
            float dx = __ldg(&att_d[col]), dy = __ldg(&att_d[col + 1]);
            int h = nc >> 2;
            as0[h] += acc[nc][0] * sx + acc[nc][1] * sy;
            ad0[h] += acc[nc][0] * dx + acc[nc][1] * dy;
            as1[h] += acc[nc][2] * sx + acc[nc][3] * sy;
            ad1[h] += acc[nc][2] * dx + acc[nc][3] * dy;
        }
#pragma unroll
        for (int h = 0; h < 4; h++) {
#pragma unroll
            for (int off = 1; off <= 2; off <<= 1) {
                as0[h] += __shfl_xor_sync(0xffffffffu, as0[h], off);
                ad0[h] += __shfl_xor_sync(0xffffffffu, ad0[h], off);
                as1[h] += __shfl_xor_sync(0xffffffffu, as1[h], off);
                ad1[h] += __shfl_xor_sync(0xffffffffu, ad1[h], off);
            }
        }
        if (kq == 0) {
#pragma unroll
            for (int h = 0; h < 4; h++) {
                if (v0) { g_as[r0 * 4 + h] = as0[h]; g_ad[r0 * 4 + h] = ad0[h]; }
                if (v1) { g_as[r1 * 4 + h] = as1[h]; g_ad[r1 * 4 + h] = ad1[h]; }
            }
        }
    }
}

// ----------------------------------------------------------------------------
// Fused input GEMM: agg1 = xa@W1 + b1, xin = x@Wi + bi, + fused BN1 partials
// ----------------------------------------------------------------------------
__global__ void __launch_bounds__(128) gemm_in_kernel(
        const float* __restrict__ XA, const float* __restrict__ X,
        const float* __restrict__ W1, const float* __restrict__ b1,
        const float* __restrict__ Wi, const float* __restrict__ bi,
        float* __restrict__ h1, float* __restrict__ xin) {
    __shared__ float sS[4][128], sQ[4][128];
    const int tid = threadIdx.x;
    const int cg = tid & 31;
    const int rg = tid >> 5;
    const int n0 = blockIdx.x * 16 + rg * 4;
    float a1[4][4] = {}; float ai[4][4] = {};
    const float4* W1v = (const float4*)W1;
    const float4* Wiv = (const float4*)Wi;
#pragma unroll
    for (int k = 0; k < DIN; k++) {
        float4 w1 = __ldg(&W1v[k * 32 + cg]);
        float4 wi = __ldg(&Wiv[k * 32 + cg]);
#pragma unroll
        for (int r = 0; r < 4; r++) {
            float xav = __ldg(&XA[(n0 + r) * DIN + k]);
            float xv  = __ldg(&X[(n0 + r) * DIN + k]);
            a1[r][0] += xav * w1.x; a1[r][1] += xav * w1.y; a1[r][2] += xav * w1.z; a1[r][3] += xav * w1.w;
            ai[r][0] += xv * wi.x;  ai[r][1] += xv * wi.y;  ai[r][2] += xv * wi.z;  ai[r][3] += xv * wi.w;
        }
    }
    const int c0 = cg * 4;
    float4 b1v = __ldg(&((const float4*)b1)[cg]);
    float4 biv = __ldg(&((const float4*)bi)[cg]);
    float s4[4] = {}, q4[4] = {};
#pragma unroll
    for (int r = 0; r < 4; r++) {
        float4 v1, vi;
        v1.x = a1[r][0] + b1v.x; v1.y = a1[r][1] + b1v.y;
        v1.z = a1[r][2] + b1v.z; v1.w = a1[r][3] + b1v.w;
        vi.x = ai[r][0] + biv.x; vi.y = ai[r][1] + biv.y;
        vi.z = ai[r][2] + biv.z; vi.w = ai[r][3] + biv.w;
        s4[0] += v1.x; q4[0] += v1.x * v1.x;
        s4[1] += v1.y; q4[1] += v1.y * v1.y;
        s4[2] += v1.z; q4[2] += v1.z * v1.z;
        s4[3] += v1.w; q4[3] += v1.w * v1.w;
        *(float4*)&h1[(n0 + r) * HH + c0] = v1;
        *(float4*)&xin[(n0 + r) * HH + c0] = vi;
    }
#pragma unroll
    for (int i = 0; i < 4; i++) { sS[rg][c0 + i] = s4[i]; sQ[rg][c0 + i] = q4[i]; }
    __syncthreads();
    const int b = blockIdx.x & (NBUK - 1);
    float ts = sS[0][tid] + sS[1][tid] + sS[2][tid] + sS[3][tid];
    float tq = sQ[0][tid] + sQ[1][tid] + sQ[2][tid] + sQ[3][tid];
    atomicAdd(&g_bnpart[0][b][tid], ts);
    atomicAdd(&g_bnpart[0][b][tid + 128], tq);
}

// ----------------------------------------------------------------------------
// GCN aggregation (128 ch, warp/node, 8-wide main + serial tail) + BN3 partials
// ----------------------------------------------------------------------------
__global__ void __launch_bounds__(128) gcn_agg128(const float* __restrict__ in,
                                                  const float* __restrict__ bias,
                                                  float* __restrict__ out) {
    __shared__ float sS[4][128], sQ[4][128];
    const int warp = threadIdx.x >> 5;
    const int lane = threadIdx.x & 31;
    const int n = blockIdx.x * 4 + warp;
    const float dn = g_dinv[n];
    const int s0 = g_rowptr[n], s1 = g_rowptr[n + 1];
    const float4* in4 = (const float4*)in;
    float4 acc = __ldg(&in4[n * 32 + lane]);
    float dn2 = dn * dn;
    acc.x *= dn2; acc.y *= dn2; acc.z *= dn2; acc.w *= dn2;
    int j = s0;
    for (; j + 8 <= s1; j += 8) {
        int2 e[8];
        float4 v[8];
#pragma unroll
        for (int q = 0; q < 8; q++) e[q] = __ldg(&g_epack[j + q]);
#pragma unroll
        for (int q = 0; q < 8; q++) v[q] = __ldg(&in4[e[q].x * 32 + lane]);
#pragma unroll
        for (int q = 0; q < 8; q++) {
            float c = __int_as_float(e[q].y);
            acc.x += c * v[q].x; acc.y += c * v[q].y;
            acc.z += c * v[q].z; acc.w += c * v[q].w;
        }
    }
    for (; j < s1; j++) {
        int2 e = __ldg(&g_epack[j]);
        float4 v = __ldg(&in4[e.x * 32 + lane]);
        float c = __int_as_float(e.y);
        acc.x += c * v.x; acc.y += c * v.y; acc.z += c * v.z; acc.w += c * v.w;
    }
    float4 bv = __ldg(&((const float4*)bias)[lane]);
    acc.x += bv.x; acc.y += bv.y; acc.z += bv.z; acc.w += bv.w;
    ((float4*)out)[n * 32 + lane] = acc;
    sS[warp][lane * 4 + 0] = acc.x; sQ[warp][lane * 4 + 0] = acc.x * acc.x;
    sS[warp][lane * 4 + 1] = acc.y; sQ[warp][lane * 4 + 1] = acc.y * acc.y;
    sS[warp][lane * 4 + 2] = acc.z; sQ[warp][lane * 4 + 2] = acc.z * acc.z;
    sS[warp][lane * 4 + 3] = acc.w; sQ[warp][lane * 4 + 3] = acc.w * acc.w;
    __syncthreads();
    const int tid = threadIdx.x;
    const int b = blockIdx.x & (NBUK - 1);
    float ts = sS[0][tid] + sS[1][tid] + sS[2][tid] + sS[3][tid];
    float tq = sQ[0][tid] + sQ[1][tid] + sQ[2][tid] + sQ[3][tid];
    atomicAdd(&g_bnpart[2][b][tid], ts);
    atomicAdd(&g_bnpart[2][b][tid + 128], tq);
}

// ----------------------------------------------------------------------------
// GAT aggregation: single pass, 8-wide main + serial tail + BN2 partials
// ----------------------------------------------------------------------------
__global__ void __launch_bounds__(256) gat_agg_kernel(const float* __restrict__ hg,
                                                      const float* __restrict__ bg,
                                                      float* __restrict__ out) {
    __shared__ float sS[8][128], sQ[8][128];
    const int w = threadIdx.x >> 5;
    const int lane = threadIdx.x & 31;
    const int n = blockIdx.x * 8 + w;
    const int s0 = g_rowptr[n], s1 = g_rowptr[n + 1];
    const int h = lane >> 3;
    const int eq = lane & 7;
    const float4* ad4 = (const float4*)g_ad;
    const float4* as4 = (const float4*)g_as;

    float4 adv = __ldg(&ad4[n]);
    float4 asv = __ldg(&as4[n]);
    float adh = h < 2 ? (h == 0 ? adv.x : adv.y) : (h == 2 ? adv.z : adv.w);
    float ash = h < 2 ? (h == 0 ? asv.x : asv.y) : (h == 2 ? asv.z : asv.w);
    float xs = expf(lrelu(ash + adh));

    const float4* hg4 = (const float4*)hg;
    float4 acc = make_float4(0.f, 0.f, 0.f, 0.f);
    float tsum = 0.f;

    int j = s0;
    for (; j + 8 <= s1; j += 8) {
        int2 e[8];
#pragma unroll
        for (int q = 0; q < 8; q++) e[q] = __ldg(&g_epack[j + q]);
        float myx = expf(lrelu(__ldg(&g_as[e[eq].x * 4 + h]) + adh));
        tsum += myx;
        float4 v[8];
#pragma unroll
        for (int q = 0; q < 8; q++) v[q] = __ldg(&hg4[e[q].x * 32 + lane]);
#pragma unroll
        for (int q = 0; q < 8; q++) {
            float a = __shfl_sync(0xffffffffu, myx, h * 8 + q);
            acc.x += a * v[q].x; acc.y += a * v[q].y;
            acc.z += a * v[q].z; acc.w += a * v[q].w;
        }
    }
    for (; j < s1; j++) {
        int2 e = __ldg(&g_epack[j]);
        float a = expf(lrelu(__ldg(&g_as[e.x * 4 + h]) + adh));
        if (eq == 0) tsum += a;
        float4 v = __ldg(&hg4[e.x * 32 + lane]);
        acc.x += a * v.x; acc.y += a * v.y; acc.z += a * v.z; acc.w += a * v.w;
    }
#pragma unroll
    for (int off = 1; off <= 4; off <<= 1)
        tsum += __shfl_xor_sync(0xffffffffu, tsum, off);
    float inv = 1.f / (tsum + xs);

    float4 self = __ldg(&hg4[n * 32 + lane]);
    float4 bv = __ldg(&((const float4*)bg)[lane]);
    float4 o;
    o.x = (acc.x + xs * self.x) * inv + bv.x;
    o.y = (acc.y + xs * self.y) * inv + bv.y;
    o.z = (acc.z + xs * self.z) * inv + bv.z;
    o.w = (acc.w + xs * self.w) * inv + bv.w;
    ((float4*)out)[n * 32 + lane] = o;
    sS[w][lane * 4 + 0] = o.x; sQ[w][lane * 4 + 0] = o.x * o.x;
    sS[w][lane * 4 + 1] = o.y; sQ[w][lane * 4 + 1] = o.y * o.y;
    sS[w][lane * 4 + 2] = o.z; sQ[w][lane * 4 + 2] = o.z * o.z;
    sS[w][lane * 4 + 3] = o.w; sQ[w][lane * 4 + 3] = o.w * o.w;
    __syncthreads();
    const int tid = threadIdx.x;
    if (tid < 128) {
        const int b = blockIdx.x & (NBUK - 1);
        float ts = 0.f, tq = 0.f;
#pragma unroll
        for (int ww = 0; ww < 8; ww++) { ts += sS[ww][tid]; tq += sQ[ww][tid]; }
        atomicAdd(&g_bnpart[1][b][tid], ts);
        atomicAdd(&g_bnpart[1][b][tid + 128], tq);
    }
}

// ----------------------------------------------------------------------------
// Output: GCN aggregation of h4 (12 ch, 8-wide main + serial tail) + gate add
// ----------------------------------------------------------------------------
__global__ void __launch_bounds__(128) out_kernel(
        const float* __restrict__ h4, const float* __restrict__ b4,
        const float* __restrict__ gc, float* __restrict__ out) {
    const int warp = threadIdx.x >> 5;
    const int lane = threadIdx.x & 31;
    const int n = blockIdx.x * 4 + warp;
    const float dn = g_dinv[n];
    const int s0 = g_rowptr[n], s1 = g_rowptr[n + 1];
    float acc = (lane < DOUT) ? h4[n * DOUT + lane] * dn * dn : 0.f;
    int j = s0;
    for (; j + 8 <= s1; j += 8) {
        int2 e[8];
        float v[8];
#pragma unroll
        for (int q = 0; q < 8; q++) e[q] = __ldg(&g_epack[j + q]);
#pragma unroll
        for (int q = 0; q < 8; q++)
            v[q] = (lane < DOUT) ? __ldg(&h4[e[q].x * DOUT + lane]) : 0.f;
#pragma unroll
        for (int q = 0; q < 8; q++) acc += __int_as_float(e[q].y) * v[q];
    }
    for (; j < s1; j++) {
        int2 e = __ldg(&g_epack[j]);
        if (lane < DOUT) acc += __int_as_float(e.y) * __ldg(&h4[e.x * DOUT + lane]);
    }
    if (lane < DOUT)
        out[n * DOUT + lane] = acc + __ldg(&b4[lane]) + __ldg(&gc[n * DOUT + lane]);
}

// ----------------------------------------------------------------------------
// Launch
// ----------------------------------------------------------------------------
extern "C" void kernel_launch(void* const* d_in, const int* in_sizes, int n_in,
                              void* d_out, int out_size) {
    const float* x   = (const float*)d_in[0];
    const int*   ei  = (const int*)d_in[1];
    const float* ew  = (const float*)d_in[2];
    const float* W1  = (const float*)d_in[3];
    const float* b1  = (const float*)d_in[4];
    const float* g1  = (const float*)d_in[5];
    const float* be1 = (const float*)d_in[6];
    const float* Wg  = (const float*)d_in[7];
    const float* atts= (const float*)d_in[8];
    const float* attd= (const float*)d_in[9];
    const float* bg  = (const float*)d_in[10];
    const float* g2  = (const float*)d_in[11];
    const float* be2 = (const float*)d_in[12];
    const float* W3  = (const float*)d_in[13];
    const float* b3  = (const float*)d_in[14];
    const float* g3  = (const float*)d_in[15];
    const float* be3 = (const float*)d_in[16];
    const float* W4  = (const float*)d_in[17];
    const float* b4  = (const float*)d_in[18];
    const float* Wi  = (const float*)d_in[19];
    const float* bi  = (const float*)d_in[20];
    const float* Gw1 = (const float*)d_in[21];
    const float* Gb1 = (const float*)d_in[22];
    const float* Gw2 = (const float*)d_in[23];
    const float* Gb2 = (const float*)d_in[24];
    const float* Ws  = (const float*)d_in[25];
    const float* bs  = (const float*)d_in[26];
    float* out = (float*)d_out;
    const int* src = ei;
    const int* dst = ei + EE;

    float *p_h1, *p_agg, *p_x1, *p_xin, *p_hg, *p_xa, *p_h4, *p_gc;
    float *p_wtg, *p_wt3, *p_wtcomb, *p_bn;
    cudaGetSymbolAddress((void**)&p_h1, g_h1);
    cudaGetSymbolAddress((void**)&p_agg, g_agg);
    cudaGetSymbolAddress((void**)&p_x1, g_x1);
    cudaGetSymbolAddress((void**)&p_xin, g_xin);
    cudaGetSymbolAddress((void**)&p_hg, g_hg);
    cudaGetSymbolAddress((void**)&p_xa, g_xa);
    cudaGetSymbolAddress((void**)&p_h4, g_h4);
    cudaGetSymbolAddress((void**)&p_gc, g_gc);
    cudaGetSymbolAddress((void**)&p_wtg, g_wtg);
    cudaGetSymbolAddress((void**)&p_wt3, g_wt3);
    cudaGetSymbolAddress((void**)&p_wtcomb, g_wtcomb);
    cudaGetSymbolAddress((void**)&p_bn, g_bnpart);

    const int SMEM128 = 1024 + 128 * 132 * 4;                 // 68608
    const int SMEM80  = 1024 + 80 * 132 * 4 + 64 * DOUT * 4;  // 46336
    cudaFuncSetAttribute(mma_gemm<128, false, true, true, false>,
                         cudaFuncAttributeMaxDynamicSharedMemorySize, SMEM128);
    cudaFuncSetAttribute(mma_gemm<128, true, false, false, false>,
                         cudaFuncAttributeMaxDynamicSharedMemorySize, SMEM128);
    cudaFuncSetAttribute(mma_gemm<80, true, false, false, true>,
                         cudaFuncAttributeMaxDynamicSharedMemorySize, SMEM80);
    const int MGRID = (NN + 127) / 128;   // 782

    // graph preprocessing + weight prep
    init_kernel<<<(NN + 255) / 256, 256>>>();
    count_kernel<<<(EE + 255) / 256, 256>>>(dst, ew);
    part_kernel<<<NB, 256>>>();
    writerow_kernel<<<NB, 256>>>();
    fill_kernel<<<(EE + 255) / 256, 256>>>(src, dst, ew);
    prep_weights_kernel<<<168, 256>>>(Wg, W3, Gw1, W4);

    // layer 1
    agg24_kernel<<<NN / 4, 128>>>(x, p_xa);
    gemm_in_kernel<<<NN / 16, 128>>>(p_xa, x, W1, b1, Wi, bi, p_agg, p_xin);

    // GAT: Wg GEMM (in-kernel BN1 finalize) + side-write x1 + att reduce
    mma_gemm<128, false, true, true, false><<<MGRID, 256, SMEM128>>>(
        p_agg, nullptr, p_x1, p_wtg, nullptr, p_hg, nullptr, atts, attd,
        p_bn + 0 * NBUK * 256, g1, be1, nullptr, nullptr, nullptr, nullptr, nullptr);
    gat_agg_kernel<<<NN / 8, 256>>>(p_hg, bg, p_agg);

    // layer 3: W3 GEMM (in-kernel BN2 finalize) + xin residual
    mma_gemm<128, true, false, false, false><<<MGRID, 256, SMEM128>>>(
        p_agg, p_xin, nullptr, p_wt3, nullptr, p_h1, nullptr, nullptr, nullptr,
        p_bn + 1 * NBUK * 256, g2, be2, nullptr, nullptr, nullptr, nullptr, nullptr);
    gcn_agg128<<<NN / 4, 128>>>(p_h1, b3, p_agg);

    // output: combo GEMM (in-kernel BN3 finalize) + x1 residual + fused gate
    mma_gemm<80, true, false, false, true><<<MGRID, 256, SMEM80>>>(
        p_agg, p_x1, nullptr, p_wtcomb, Gb1, p_gc, p_h4, nullptr, nullptr,
        p_bn + 2 * NBUK * 256, g3, be3, Gw2, Gb2, Ws, bs, x);
    out_kernel<<<NN / 4, 128>>>(p_h4, b4, p_gc, out);
}

// round 17
// speedup vs baseline: 1.0607x; 1.0072x over previous
#include <cuda_runtime.h>
#include <math.h>
#include <stdint.h>

#define NN 100000
#define EE 1600000
#define DIN 24
#define HH 128
#define DOUT 12
#define HEADS 4
#define NB 391   // ceil(NN/256)
#define NBUK 32  // BN partial buckets
#define WSCALE 33554432.0f   // 2^25 fixed-point scale for packed degree

// ----------------------------------------------------------------------------
// Scratch (device globals; no dynamic allocation allowed)
// ----------------------------------------------------------------------------
__device__ float g_h1[NN * HH];      // h3 = x2@W3
__device__ float g_agg[NN * HH];     // raw pre-BN activations per layer
__device__ float g_x1[NN * HH];      // x1 (side-written by Wg GEMM)
__device__ float g_xin[NN * HH];     // x_in_proj
__device__ float g_hg[NN * HH];      // hg
__device__ float g_xa[NN * DIN];     // 24-dim aggregated x
__device__ float g_h4[NN * DOUT];
__device__ float g_gc[NN * DOUT];    // gate contribution per node
__device__ float g_as[NN * HEADS];
__device__ float g_ad[NN * HEADS];
__device__ unsigned long long g_packed[NN];  // (cnt<<40) | round(sum_w * 2^25)
__device__ float g_dinv[NN];
__device__ int   g_cur[NN];
__device__ int   g_rowptr[NN + 1];
__device__ int2  g_epack[EE];
__device__ int   g_part[512];
__device__ float g_bnpart[3][NBUK][256];  // per-layer bucketed BN partials
__device__ float g_wtg[HH * HH];     // Wg^T  [128,128] K-major
__device__ float g_wt3[HH * HH];     // W3^T
__device__ float g_wtcomb[80 * HH];  // [Gw1^T ; W4^T ; pad]

__device__ __forceinline__ float lrelu(float v) { return v > 0.f ? v : 0.2f * v; }
__device__ __forceinline__ uint32_t to_tf32(float f) {
    uint32_t t;
    asm("cvt.rna.tf32.f32 %0, %1;" : "=r"(t) : "f"(f));
    return t;
}

// ----------------------------------------------------------------------------
// Graph preprocessing
// ----------------------------------------------------------------------------
__global__ void __launch_bounds__(256) init_kernel() {
    int i = blockIdx.x * blockDim.x + threadIdx.x;
    if (i < NN) {
        g_packed[i] = (unsigned long long)(1u << 25);   // deg=1.0 (self loop), cnt=0
        g_cur[i] = 0;
    }
    if (i < 3 * NBUK * 256) ((float*)g_bnpart)[i] = 0.f;
}

// single 64-bit atomic per edge: cnt in bits[40:], fixed-point w-sum in bits[:40]
__global__ void __launch_bounds__(256) count_kernel(const int* __restrict__ dst,
                                                    const float* __restrict__ w) {
    int e = blockIdx.x * blockDim.x + threadIdx.x;
    if (e < EE) {
        int d = dst[e];
        unsigned long long inc =
            (1ull << 40) + (unsigned long long)(w[e] * WSCALE + 0.5f);
        atomicAdd(&g_packed[d], inc);
    }
}

__global__ void __launch_bounds__(256) part_kernel() {
    __shared__ int sw[8];
    int i = blockIdx.x * 256 + threadIdx.x;
    int v = 0;
    if (i < NN) {
        unsigned long long p = g_packed[i];
        v = (int)(p >> 40);
        float deg = (float)(p & ((1ull << 40) - 1ull)) * (1.0f / WSCALE);
        g_dinv[i] = rsqrtf(deg);
    }
    int s = v;
#pragma unroll
    for (int off = 16; off; off >>= 1) s += __shfl_down_sync(0xffffffffu, s, off);
    if ((threadIdx.x & 31) == 0) sw[threadIdx.x >> 5] = s;
    __syncthreads();
    if (threadIdx.x == 0) {
        int t = 0;
#pragma unroll
        for (int k = 0; k < 8; k++) t += sw[k];
        g_part[blockIdx.x] = t;
    }
}

__global__ void __launch_bounds__(256) writerow_kernel() {
    __shared__ int sp[256];
    __shared__ int swr[8];
    __shared__ int soff;
    const int t = threadIdx.x;
    const int i = blockIdx.x * 256 + t;
    int pre = 0;
    for (int b = t; b < blockIdx.x; b += 256) pre += g_part[b];
#pragma unroll
    for (int off = 16; off; off >>= 1) pre += __shfl_down_sync(0xffffffffu, pre, off);
    if ((t & 31) == 0) swr[t >> 5] = pre;
    __syncthreads();
    if (t == 0) {
        int s = 0;
#pragma unroll
        for (int k = 0; k < 8; k++) s += swr[k];
        soff = s;
    }
    int v = (i < NN) ? (int)(g_packed[i] >> 40) : 0;
    sp[t] = v;
    __syncthreads();
    for (int off = 1; off < 256; off <<= 1) {
        int a = (t >= off) ? sp[t - off] : 0;
        __syncthreads();
        sp[t] += a;
        __syncthreads();
    }
    if (i < NN) g_rowptr[i] = sp[t] - v + soff;
    if (i == 0) g_rowptr[NN] = EE;
}

__global__ void __launch_bounds__(256) fill_kernel(const int* __restrict__ src,
                                                   const int* __restrict__ dst,
                                                   const float* __restrict__ w) {
    int e = blockIdx.x * blockDim.x + threadIdx.x;
    if (e < EE) {
        int d = dst[e];
        int s = src[e];
        int pos = g_rowptr[d] + atomicAdd(&g_cur[d], 1);
        float coef = w[e] * __ldg(&g_dinv[s]) * __ldg(&g_dinv[d]);
        g_epack[pos] = make_int2(s, __float_as_int(coef));
    }
}

__global__ void __launch_bounds__(256) prep_weights_kernel(const float* __restrict__ Wg,
                                                           const float* __restrict__ W3,
                                                           const float* __restrict__ Gw1,
                                                           const float* __restrict__ W4) {
    int idx = blockIdx.x * 256 + threadIdx.x;
    if (idx < 16384) {
        int k = idx >> 7, c = idx & 127;
        g_wtg[c * 128 + k] = __ldg(&Wg[idx]);
    } else if (idx < 32768) {
        int j = idx - 16384;
        int k = j >> 7, c = j & 127;
        g_wt3[c * 128 + k] = __ldg(&W3[j]);
    } else if (idx < 43008) {
        int j = idx - 32768;
        int r = j >> 7, k = j & 127;
        float v = 0.f;
        if (r < 64) v = __ldg(&Gw1[k * 64 + r]);
        else if (r < 76) v = __ldg(&W4[k * DOUT + (r - 64)]);
        g_wtcomb[j] = v;
    }
}

// ----------------------------------------------------------------------------
// 24-channel GCN aggregation (8-wide main + serial tail)
// ----------------------------------------------------------------------------
__global__ void __launch_bounds__(128) agg24_kernel(const float* __restrict__ x,
                                                    float* __restrict__ xa) {
    const int warp = threadIdx.x >> 5;
    const int lane = threadIdx.x & 31;
    const int n = blockIdx.x * 4 + warp;
    const float dn = g_dinv[n];
    const int s0 = g_rowptr[n], s1 = g_rowptr[n + 1];
    float acc = (lane < DIN) ? x[n * DIN + lane] * dn * dn : 0.f;
    int j = s0;
    for (; j + 8 <= s1; j += 8) {
        int2 e[8];
        float v[8];
#pragma unroll
        for (int q = 0; q < 8; q++) e[q] = __ldg(&g_epack[j + q]);
#pragma unroll
        for (int q = 0; q < 8; q++)
            v[q] = (lane < DIN) ? __ldg(&x[e[q].x * DIN + lane]) : 0.f;
#pragma unroll
        for (int q = 0; q < 8; q++) acc += __int_as_float(e[q].y) * v[q];
    }
    for (; j < s1; j++) {
        int2 e = __ldg(&g_epack[j]);
        if (lane < DIN) acc += __int_as_float(e.y) * __ldg(&x[e.x * DIN + lane]);
    }
    if (lane < DIN) xa[n * DIN + lane] = acc;
}

// ----------------------------------------------------------------------------
// TF32 mma.sync GEMM. In-kernel BN finalize from bucketed partials.
// ----------------------------------------------------------------------------
template<int NC, bool ADD, bool WRITEX, bool ATT, bool COMBO>
__global__ void __launch_bounds__(256) mma_gemm(const float* __restrict__ Araw,
                                                const float* __restrict__ addp,
                                                float* __restrict__ xout,
                                                const float* __restrict__ Bt,
                                                const float* __restrict__ bias,
                                                float* __restrict__ out,
                                                float* __restrict__ out2,
                                                const float* __restrict__ att_s,
                                                const float* __restrict__ att_d,
                                                const float* __restrict__ bnp,
                                                const float* __restrict__ bng,
                                                const float* __restrict__ bnbe,
                                                const float* __restrict__ Gw2,
                                                const float* __restrict__ Gb2,
                                                const float* __restrict__ Ws,
                                                const float* __restrict__ bs,
                                                const float* __restrict__ xfull) {
    extern __shared__ float smf[];
    float* sSC = smf;
    float* sSH = smf + 128;
    uint32_t* sW = (uint32_t*)(smf + 256);   // [NC][132]
    float* sG = smf + 256 + NC * 132;        // [64*12] (COMBO only)
    const int tid = threadIdx.x, wid = tid >> 5, lane = tid & 31;
    const int n0 = blockIdx.x * 128;

    if (tid < 128) {
        float s = 0.f, s2 = 0.f;
#pragma unroll 8
        for (int b = 0; b < NBUK; b++) {
            s += __ldg(&bnp[b * 256 + tid]);
            s2 += __ldg(&bnp[b * 256 + tid + 128]);
        }
        float mean = s * (1.0f / NN);
        float var = fmaxf(s2 * (1.0f / NN) - mean * mean, 0.f);
        float sc = rsqrtf(var + 1e-5f) * __ldg(&bng[tid]);
        sSC[tid] = sc;
        sSH[tid] = __ldg(&bnbe[tid]) - mean * sc;
    }
    for (int i = tid; i < NC * 128; i += 256) {
        int c = i >> 7, k = i & 127;
        sW[c * 132 + k] = to_tf32(__ldg(&Bt[i]));
    }
    if (COMBO) {
        for (int i = tid; i < 64 * DOUT; i += 256) sG[i] = __ldg(&Gw2[i]);
    }
    __syncthreads();

    constexpr int NCH = NC / 8;
    float acc[NCH][4];
#pragma unroll
    for (int i = 0; i < NCH; i++) {
        acc[i][0] = 0.f; acc[i][1] = 0.f; acc[i][2] = 0.f; acc[i][3] = 0.f;
    }

    const int r0 = n0 + wid * 16 + (lane >> 2);
    const int r1 = r0 + 8;
    const bool v0 = r0 < NN, v1 = r1 < NN;
    const int kq = lane & 3;
    const int nq = lane >> 2;

#pragma unroll 4
    for (int k8 = 0; k8 < 128; k8 += 8) {
        int ka = k8 + kq, kb = k8 + kq + 4;
        float f0 = 0.f, f1 = 0.f, f2 = 0.f, f3 = 0.f;
        if (v0) {
            f0 = fmaxf(__ldg(&Araw[(size_t)r0 * 128 + ka]) * sSC[ka] + sSH[ka], 0.f);
            f2 = fmaxf(__ldg(&Araw[(size_t)r0 * 128 + kb]) * sSC[kb] + sSH[kb], 0.f);
            if (ADD) {
                f0 += __ldg(&addp[(size_t)r0 * 128 + ka]);
                f2 += __ldg(&addp[(size_t)r0 * 128 + kb]);
            }
            if (WRITEX) {
                xout[(size_t)r0 * 128 + ka] = f0;
                xout[(size_t)r0 * 128 + kb] = f2;
            }
        }
        if (v1) {
            f1 = fmaxf(__ldg(&Araw[(size_t)r1 * 128 + ka]) * sSC[ka] + sSH[ka], 0.f);
            f3 = fmaxf(__ldg(&Araw[(size_t)r1 * 128 + kb]) * sSC[kb] + sSH[kb], 0.f);
            if (ADD) {
                f1 += __ldg(&addp[(size_t)r1 * 128 + ka]);
                f3 += __ldg(&addp[(size_t)r1 * 128 + kb]);
            }
            if (WRITEX) {
                xout[(size_t)r1 * 128 + ka] = f1;
                xout[(size_t)r1 * 128 + kb] = f3;
            }
        }
        uint32_t a0 = to_tf32(f0), a1 = to_tf32(f1), a2 = to_tf32(f2), a3 = to_tf32(f3);
#pragma unroll
        for (int nc = 0; nc < NCH; nc++) {
            uint32_t b0 = sW[(nc * 8 + nq) * 132 + ka];
            uint32_t b1 = sW[(nc * 8 + nq) * 132 + kb];
            asm volatile(
                "mma.sync.aligned.m16n8k8.row.col.f32.tf32.tf32.f32 "
                "{%0,%1,%2,%3}, {%4,%5,%6,%7}, {%8,%9}, {%0,%1,%2,%3};"
                : "+f"(acc[nc][0]), "+f"(acc[nc][1]), "+f"(acc[nc][2]), "+f"(acc[nc][3])
                : "r"(a0), "r"(a1), "r"(a2), "r"(a3), "r"(b0), "r"(b1));
        }
    }

    const int colb = 2 * kq;
    if (COMBO) {
        float z0[DOUT], z1[DOUT];
#pragma unroll
        for (int c = 0; c < DOUT; c++) { z0[c] = 0.f; z1[c] = 0.f; }
#pragma unroll
        for (int nc = 0; nc < NCH; nc++) {
            int col = nc * 8 + colb;
            if (col < 64) {
                float bx = __ldg(&bias[col]), by = __ldg(&bias[col + 1]);
                float t0a = fmaxf(acc[nc][0] + bx, 0.f), t0b = fmaxf(acc[nc][1] + by, 0.f);
                float t1a = fmaxf(acc[nc][2] + bx, 0.f), t1b = fmaxf(acc[nc][3] + by, 0.f);
#pragma unroll
                for (int c = 0; c < DOUT; c++) {
                    float w0 = sG[col * DOUT + c], w1 = sG[(col + 1) * DOUT + c];
                    z0[c] += t0a * w0 + t0b * w1;
                    z1[c] += t1a * w0 + t1b * w1;
                }
            } else if (col < 76) {
                int c2 = col - 64;
                if (v0) *(float2*)&out2[(size_t)r0 * DOUT + c2] =
                            make_float2(acc[nc][0], acc[nc][1]);
                if (v1) *(float2*)&out2[(size_t)r1 * DOUT + c2] =
                            make_float2(acc[nc][2], acc[nc][3]);
            }
        }
#pragma unroll
        for (int c = 0; c < DOUT; c++) {
            z0[c] += __shfl_xor_sync(0xffffffffu, z0[c], 1);
            z0[c] += __shfl_xor_sync(0xffffffffu, z0[c], 2);
            z1[c] += __shfl_xor_sync(0xffffffffu, z1[c], 1);
            z1[c] += __shfl_xor_sync(0xffffffffu, z1[c], 2);
        }
        if (kq == 0) {
            if (v0) {
                float status = __ldg(&xfull[(size_t)r0 * DIN + 12]);
                float flag = status < 0.5f ? 2.5f : 0.f;
#pragma unroll
                for (int c = 0; c < DOUT; c++) {
                    float gate = 1.f / (1.f + expf(-(z0[c] + __ldg(&Gb2[c]))));
                    float sig = (1.f - status) * __ldg(&Ws[c]) + __ldg(&bs[c]);
                    out[(size_t)r0 * DOUT + c] = flag * gate * sig;
                }
            }
            if (v1) {
                float status = __ldg(&xfull[(size_t)r1 * DIN + 12]);
                float flag = status < 0.5f ? 2.5f : 0.f;
#pragma unroll
                for (int c = 0; c < DOUT; c++) {
                    float gate = 1.f / (1.f + expf(-(z1[c] + __ldg(&Gb2[c]))));
                    float sig = (1.f - status) * __ldg(&Ws[c]) + __ldg(&bs[c]);
                    out[(size_t)r1 * DOUT + c] = flag * gate * sig;
                }
            }
        }
    } else {
#pragma unroll
        for (int nc = 0; nc < NCH; nc++) {
            int col = nc * 8 + colb;
            if (v0) *(float2*)&out[(size_t)r0 * NC + col] =
                        make_float2(acc[nc][0], acc[nc][1]);
            if (v1) *(float2*)&out[(size_t)r1 * NC + col] =
                        make_float2(acc[nc][2], acc[nc][3]);
        }
    }

    if (ATT) {
        float as0[4] = {}, ad0[4] = {}, as1[4] = {}, ad1[4] = {};
#pragma unroll
        for (int nc = 0; nc < NCH; nc++) {
            int col = nc * 8 + colb;
            float sx = __ldg(&att_s[col]), sy = __ldg(&att_s[col + 1]);
            float dx = __ldg(&att_d[col]), dy = __ldg(&att_d[col + 1]);
            int h = nc >> 2;
            as0[h] += acc[nc][0] * sx + acc[nc][1] * sy;
            ad0[h] += acc[nc][0] * dx + acc[nc][1] * dy;
            as1[h] += acc[nc][2] * sx + acc[nc][3] * sy;
            ad1[h] += acc[nc][2] * dx + acc[nc][3] * dy;
        }
#pragma unroll
        for (int h = 0; h < 4; h++) {
#pragma unroll
            for (int off = 1; off <= 2; off <<= 1) {
                as0[h] += __shfl_xor_sync(0xffffffffu, as0[h], off);
                ad0[h] += __shfl_xor_sync(0xffffffffu, ad0[h], off);
                as1[h] += __shfl_xor_sync(0xffffffffu, as1[h], off);
                ad1[h] += __shfl_xor_sync(0xffffffffu, ad1[h], off);
            }
        }
        if (kq == 0) {
#pragma unroll
            for (int h = 0; h < 4; h++) {
                if (v0) { g_as[r0 * 4 + h] = as0[h]; g_ad[r0 * 4 + h] = ad0[h]; }
                if (v1) { g_as[r1 * 4 + h] = as1[h]; g_ad[r1 * 4 + h] = ad1[h]; }
            }
        }
    }
}

// ----------------------------------------------------------------------------
// Fused input GEMM: agg1 = xa@W1 + b1, xin = x@Wi + bi, + fused BN1 partials
// ----------------------------------------------------------------------------
__global__ void __launch_bounds__(128) gemm_in_kernel(
        const float* __restrict__ XA, const float* __restrict__ X,
        const float* __restrict__ W1, const float* __restrict__ b1,
        const float* __restrict__ Wi, const float* __restrict__ bi,
        float* __restrict__ h1, float* __restrict__ xin) {
    __shared__ float sS[4][128], sQ[4][128];
    const int tid = threadIdx.x;
    const int cg = tid & 31;
    const int rg = tid >> 5;
    const int n0 = blockIdx.x * 16 + rg * 4;
    float a1[4][4] = {}; float ai[4][4] = {};
    const float4* W1v = (const float4*)W1;
    const float4* Wiv = (const float4*)Wi;
#pragma unroll
    for (int k = 0; k < DIN; k++) {
        float4 w1 = __ldg(&W1v[k * 32 + cg]);
        float4 wi = __ldg(&Wiv[k * 32 + cg]);
#pragma unroll
        for (int r = 0; r < 4; r++) {
            float xav = __ldg(&XA[(n0 + r) * DIN + k]);
            float xv  = __ldg(&X[(n0 + r) * DIN + k]);
            a1[r][0] += xav * w1.x; a1[r][1] += xav * w1.y; a1[r][2] += xav * w1.z; a1[r][3] += xav * w1.w;
            ai[r][0] += xv * wi.x;  ai[r][1] += xv * wi.y;  ai[r][2] += xv * wi.z;  ai[r][3] += xv * wi.w;
        }
    }
    const int c0 = cg * 4;
    float4 b1v = __ldg(&((const float4*)b1)[cg]);
    float4 biv = __ldg(&((const float4*)bi)[cg]);
    float s4[4] = {}, q4[4] = {};
#pragma unroll
    for (int r = 0; r < 4; r++) {
        float4 v1, vi;
        v1.x = a1[r][0] + b1v.x; v1.y = a1[r][1] + b1v.y;
        v1.z = a1[r][2] + b1v.z; v1.w = a1[r][3] + b1v.w;
        vi.x = ai[r][0] + biv.x; vi.y = ai[r][1] + biv.y;
        vi.z = ai[r][2] + biv.z; vi.w = ai[r][3] + biv.w;
        s4[0] += v1.x; q4[0] += v1.x * v1.x;
        s4[1] += v1.y; q4[1] += v1.y * v1.y;
        s4[2] += v1.z; q4[2] += v1.z * v1.z;
        s4[3] += v1.w; q4[3] += v1.w * v1.w;
        *(float4*)&h1[(n0 + r) * HH + c0] = v1;
        *(float4*)&xin[(n0 + r) * HH + c0] = vi;
    }
#pragma unroll
    for (int i = 0; i < 4; i++) { sS[rg][c0 + i] = s4[i]; sQ[rg][c0 + i] = q4[i]; }
    __syncthreads();
    const int b = blockIdx.x & (NBUK - 1);
    float ts = sS[0][tid] + sS[1][tid] + sS[2][tid] + sS[3][tid];
    float tq = sQ[0][tid] + sQ[1][tid] + sQ[2][tid] + sQ[3][tid];
    atomicAdd(&g_bnpart[0][b][tid], ts);
    atomicAdd(&g_bnpart[0][b][tid + 128], tq);
}

// ----------------------------------------------------------------------------
// GCN aggregation (128 ch, warp/node, 8-wide main + serial tail) + BN3 partials
// ----------------------------------------------------------------------------
__global__ void __launch_bounds__(128) gcn_agg128(const float* __restrict__ in,
                                                  const float* __restrict__ bias,
                                                  float* __restrict__ out) {
    __shared__ float sS[4][128], sQ[4][128];
    const int warp = threadIdx.x >> 5;
    const int lane = threadIdx.x & 31;
    const int n = blockIdx.x * 4 + warp;
    const float dn = g_dinv[n];
    const int s0 = g_rowptr[n], s1 = g_rowptr[n + 1];
    const float4* in4 = (const float4*)in;
    float4 acc = __ldg(&in4[n * 32 + lane]);
    float dn2 = dn * dn;
    acc.x *= dn2; acc.y *= dn2; acc.z *= dn2; acc.w *= dn2;
    int j = s0;
    for (; j + 8 <= s1; j += 8) {
        int2 e[8];
        float4 v[8];
#pragma unroll
        for (int q = 0; q < 8; q++) e[q] = __ldg(&g_epack[j + q]);
#pragma unroll
        for (int q = 0; q < 8; q++) v[q] = __ldg(&in4[e[q].x * 32 + lane]);
#pragma unroll
        for (int q = 0; q < 8; q++) {
            float c = __int_as_float(e[q].y);
            acc.x += c * v[q].x; acc.y += c * v[q].y;
            acc.z += c * v[q].z; acc.w += c * v[q].w;
        }
    }
    for (; j < s1; j++) {
        int2 e = __ldg(&g_epack[j]);
        float4 v = __ldg(&in4[e.x * 32 + lane]);
        float c = __int_as_float(e.y);
        acc.x += c * v.x; acc.y += c * v.y; acc.z += c * v.z; acc.w += c * v.w;
    }
    float4 bv = __ldg(&((const float4*)bias)[lane]);
    acc.x += bv.x; acc.y += bv.y; acc.z += bv.z; acc.w += bv.w;
    ((float4*)out)[n * 32 + lane] = acc;
    sS[warp][lane * 4 + 0] = acc.x; sQ[warp][lane * 4 + 0] = acc.x * acc.x;
    sS[warp][lane * 4 + 1] = acc.y; sQ[warp][lane * 4 + 1] = acc.y * acc.y;
    sS[warp][lane * 4 + 2] = acc.z; sQ[warp][lane * 4 + 2] = acc.z * acc.z;
    sS[warp][lane * 4 + 3] = acc.w; sQ[warp][lane * 4 + 3] = acc.w * acc.w;
    __syncthreads();
    const int tid = threadIdx.x;
    const int b = blockIdx.x & (NBUK - 1);
    float ts = sS[0][tid] + sS[1][tid] + sS[2][tid] + sS[3][tid];
    float tq = sQ[0][tid] + sQ[1][tid] + sQ[2][tid] + sQ[3][tid];
    atomicAdd(&g_bnpart[2][b][tid], ts);
    atomicAdd(&g_bnpart[2][b][tid + 128], tq);
}

// ----------------------------------------------------------------------------
// GAT aggregation: single pass, 8-wide main + serial tail + BN2 partials
// ----------------------------------------------------------------------------
__global__ void __launch_bounds__(256) gat_agg_kernel(const float* __restrict__ hg,
                                                      const float* __restrict__ bg,
                                                      float* __restrict__ out) {
    __shared__ float sS[8][128], sQ[8][128];
    const int w = threadIdx.x >> 5;
    const int lane = threadIdx.x & 31;
    const int n = blockIdx.x * 8 + w;
    const int s0 = g_rowptr[n], s1 = g_rowptr[n + 1];
    const int h = lane >> 3;
    const int eq = lane & 7;
    const float4* ad4 = (const float4*)g_ad;
    const float4* as4 = (const float4*)g_as;

    float4 adv = __ldg(&ad4[n]);
    float4 asv = __ldg(&as4[n]);
    float adh = h < 2 ? (h == 0 ? adv.x : adv.y) : (h == 2 ? adv.z : adv.w);
    float ash = h < 2 ? (h == 0 ? asv.x : asv.y) : (h == 2 ? asv.z : asv.w);
    float xs = expf(lrelu(ash + adh));

    const float4* hg4 = (const float4*)hg;
    float4 acc = make_float4(0.f, 0.f, 0.f, 0.f);
    float tsum = 0.f;

    int j = s0;
    for (; j + 8 <= s1; j += 8) {
        int2 e[8];
#pragma unroll
        for (int q = 0; q < 8; q++) e[q] = __ldg(&g_epack[j + q]);
        float myx = expf(lrelu(__ldg(&g_as[e[eq].x * 4 + h]) + adh));
        tsum += myx;
        float4 v[8];
#pragma unroll
        for (int q = 0; q < 8; q++) v[q] = __ldg(&hg4[e[q].x * 32 + lane]);
#pragma unroll
        for (int q = 0; q < 8; q++) {
            float a = __shfl_sync(0xffffffffu, myx, h * 8 + q);
            acc.x += a * v[q].x; acc.y += a * v[q].y;
            acc.z += a * v[q].z; acc.w += a * v[q].w;
        }
    }
    for (; j < s1; j++) {
        int2 e = __ldg(&g_epack[j]);
        float a = expf(lrelu(__ldg(&g_as[e.x * 4 + h]) + adh));
        if (eq == 0) tsum += a;
        float4 v = __ldg(&hg4[e.x * 32 + lane]);
        acc.x += a * v.x; acc.y += a * v.y; acc.z += a * v.z; acc.w += a * v.w;
    }
#pragma unroll
    for (int off = 1; off <= 4; off <<= 1)
        tsum += __shfl_xor_sync(0xffffffffu, tsum, off);
    float inv = 1.f / (tsum + xs);

    float4 self = __ldg(&hg4[n * 32 + lane]);
    float4 bv = __ldg(&((const float4*)bg)[lane]);
    float4 o;
    o.x = (acc.x + xs * self.x) * inv + bv.x;
    o.y = (acc.y + xs * self.y) * inv + bv.y;
    o.z = (acc.z + xs * self.z) * inv + bv.z;
    o.w = (acc.w + xs * self.w) * inv + bv.w;
    ((float4*)out)[n * 32 + lane] = o;
    sS[w][lane * 4 + 0] = o.x; sQ[w][lane * 4 + 0] = o.x * o.x;
    sS[w][lane * 4 + 1] = o.y; sQ[w][lane * 4 + 1] = o.y * o.y;
    sS[w][lane * 4 + 2] = o.z; sQ[w][lane * 4 + 2] = o.z * o.z;
    sS[w][lane * 4 + 3] = o.w; sQ[w][lane * 4 + 3] = o.w * o.w;
    __syncthreads();
    const int tid = threadIdx.x;
    if (tid < 128) {
        const int b = blockIdx.x & (NBUK - 1);
        float ts = 0.f, tq = 0.f;
#pragma unroll
        for (int ww = 0; ww < 8; ww++) { ts += sS[ww][tid]; tq += sQ[ww][tid]; }
        atomicAdd(&g_bnpart[1][b][tid], ts);
        atomicAdd(&g_bnpart[1][b][tid + 128], tq);
    }
}

// ----------------------------------------------------------------------------
// Output: GCN aggregation of h4 (12 ch, 8-wide main + serial tail) + gate add
// ----------------------------------------------------------------------------
__global__ void __launch_bounds__(128) out_kernel(
        const float* __restrict__ h4, const float* __restrict__ b4,
        const float* __restrict__ gc, float* __restrict__ out) {
    const int warp = threadIdx.x >> 5;
    const int lane = threadIdx.x & 31;
    const int n = blockIdx.x * 4 + warp;
    const float dn = g_dinv[n];
    const int s0 = g_rowptr[n], s1 = g_rowptr[n + 1];
    float acc = (lane < DOUT) ? h4[n * DOUT + lane] * dn * dn : 0.f;
    int j = s0;
    for (; j + 8 <= s1; j += 8) {
        int2 e[8];
        float v[8];
#pragma unroll
        for (int q = 0; q < 8; q++) e[q] = __ldg(&g_epack[j + q]);
#pragma unroll
        for (int q = 0; q < 8; q++)
            v[q] = (lane < DOUT) ? __ldg(&h4[e[q].x * DOUT + lane]) : 0.f;
#pragma unroll
        for (int q = 0; q < 8; q++) acc += __int_as_float(e[q].y) * v[q];
    }
    for (; j < s1; j++) {
        int2 e = __ldg(&g_epack[j]);
        if (lane < DOUT) acc += __int_as_float(e.y) * __ldg(&h4[e.x * DOUT + lane]);
    }
    if (lane < DOUT)
        out[n * DOUT + lane] = acc + __ldg(&b4[lane]) + __ldg(&gc[n * DOUT + lane]);
}

// ----------------------------------------------------------------------------
// Launch
// ----------------------------------------------------------------------------
extern "C" void kernel_launch(void* const* d_in, const int* in_sizes, int n_in,
                              void* d_out, int out_size) {
    const float* x   = (const float*)d_in[0];
    const int*   ei  = (const int*)d_in[1];
    const float* ew  = (const float*)d_in[2];
    const float* W1  = (const float*)d_in[3];
    const float* b1  = (const float*)d_in[4];
    const float* g1  = (const float*)d_in[5];
    const float* be1 = (const float*)d_in[6];
    const float* Wg  = (const float*)d_in[7];
    const float* atts= (const float*)d_in[8];
    const float* attd= (const float*)d_in[9];
    const float* bg  = (const float*)d_in[10];
    const float* g2  = (const float*)d_in[11];
    const float* be2 = (const float*)d_in[12];
    const float* W3  = (const float*)d_in[13];
    const float* b3  = (const float*)d_in[14];
    const float* g3  = (const float*)d_in[15];
    const float* be3 = (const float*)d_in[16];
    const float* W4  = (const float*)d_in[17];
    const float* b4  = (const float*)d_in[18];
    const float* Wi  = (const float*)d_in[19];
    const float* bi  = (const float*)d_in[20];
    const float* Gw1 = (const float*)d_in[21];
    const float* Gb1 = (const float*)d_in[22];
    const float* Gw2 = (const float*)d_in[23];
    const float* Gb2 = (const float*)d_in[24];
    const float* Ws  = (const float*)d_in[25];
    const float* bs  = (const float*)d_in[26];
    float* out = (float*)d_out;
    const int* src = ei;
    const int* dst = ei + EE;

    float *p_h1, *p_agg, *p_x1, *p_xin, *p_hg, *p_xa, *p_h4, *p_gc;
    float *p_wtg, *p_wt3, *p_wtcomb, *p_bn;
    cudaGetSymbolAddress((void**)&p_h1, g_h1);
    cudaGetSymbolAddress((void**)&p_agg, g_agg);
    cudaGetSymbolAddress((void**)&p_x1, g_x1);
    cudaGetSymbolAddress((void**)&p_xin, g_xin);
    cudaGetSymbolAddress((void**)&p_hg, g_hg);
    cudaGetSymbolAddress((void**)&p_xa, g_xa);
    cudaGetSymbolAddress((void**)&p_h4, g_h4);
    cudaGetSymbolAddress((void**)&p_gc, g_gc);
    cudaGetSymbolAddress((void**)&p_wtg, g_wtg);
    cudaGetSymbolAddress((void**)&p_wt3, g_wt3);
    cudaGetSymbolAddress((void**)&p_wtcomb, g_wtcomb);
    cudaGetSymbolAddress((void**)&p_bn, g_bnpart);

    const int SMEM128 = 1024 + 128 * 132 * 4;                 // 68608
    const int SMEM80  = 1024 + 80 * 132 * 4 + 64 * DOUT * 4;  // 46336
    cudaFuncSetAttribute(mma_gemm<128, false, true, true, false>,
                         cudaFuncAttributeMaxDynamicSharedMemorySize, SMEM128);
    cudaFuncSetAttribute(mma_gemm<128, true, false, false, false>,
                         cudaFuncAttributeMaxDynamicSharedMemorySize, SMEM128);
    cudaFuncSetAttribute(mma_gemm<80, true, false, false, true>,
                         cudaFuncAttributeMaxDynamicSharedMemorySize, SMEM80);
    const int MGRID = (NN + 127) / 128;   // 782

    // graph preprocessing + weight prep
    init_kernel<<<(NN + 255) / 256, 256>>>();
    count_kernel<<<(EE + 255) / 256, 256>>>(dst, ew);
    part_kernel<<<NB, 256>>>();
    writerow_kernel<<<NB, 256>>>();
    fill_kernel<<<(EE + 255) / 256, 256>>>(src, dst, ew);
    prep_weights_kernel<<<168, 256>>>(Wg, W3, Gw1, W4);

    // layer 1
    agg24_kernel<<<NN / 4, 128>>>(x, p_xa);
    gemm_in_kernel<<<NN / 16, 128>>>(p_xa, x, W1, b1, Wi, bi, p_agg, p_xin);

    // GAT: Wg GEMM (in-kernel BN1 finalize) + side-write x1 + att reduce
    mma_gemm<128, false, true, true, false><<<MGRID, 256, SMEM128>>>(
        p_agg, nullptr, p_x1, p_wtg, nullptr, p_hg, nullptr, atts, attd,
        p_bn + 0 * NBUK * 256, g1, be1, nullptr, nullptr, nullptr, nullptr, nullptr);
    gat_agg_kernel<<<NN / 8, 256>>>(p_hg, bg, p_agg);

    // layer 3: W3 GEMM (in-kernel BN2 finalize) + xin residual
    mma_gemm<128, true, false, false, false><<<MGRID, 256, SMEM128>>>(
        p_agg, p_xin, nullptr, p_wt3, nullptr, p_h1, nullptr, nullptr, nullptr,
        p_bn + 1 * NBUK * 256, g2, be2, nullptr, nullptr, nullptr, nullptr, nullptr);
    gcn_agg128<<<NN / 4, 128>>>(p_h1, b3, p_agg);

    // output: combo GEMM (in-kernel BN3 finalize) + x1 residual + fused gate
    mma_gemm<80, true, false, false, true><<<MGRID, 256, SMEM80>>>(
        p_agg, p_x1, nullptr, p_wtcomb, Gb1, p_gc, p_h4, nullptr, nullptr,
        p_bn + 2 * NBUK * 256, g3, be3, Gw2, Gb2, Ws, bs, x);
    out_kernel<<<NN / 4, 128>>>(p_h4, b4, p_gc, out);
}